// round 4
// baseline (speedup 1.0000x reference)
#include <cuda_runtime.h>
#include <cuda_bf16.h>
#include <cstdint>

#define N_NODES 65536
#define N_EDGES 1048576
#define HDIM    128
#define IN_F    5
#define N_GRAPH 16
#define ELEC    32
#define BSZ     128
#define LCONV   63   // (128-3)/2+1

// ---------------- device scratch (no allocations allowed) ----------------
__device__ float g_h  [N_NODES * HDIM];     // 32 MB
__device__ float g_m  [N_NODES * HDIM];     // 32 MB
__device__ float g_agg[N_NODES * HDIM];     // 32 MB
__device__ float g_gi [N_NODES * 3 * HDIM]; // 96 MB
__device__ float g_gh [N_NODES * 3 * HDIM]; // 96 MB
__device__ float g_wT [2 * HDIM * HDIM];    // transposed gconv weights [2][n][k]
// CSR scratch
__device__ int   g_deg [N_NODES];
__device__ int   g_off [N_NODES + 1];
__device__ int   g_cur [N_NODES];
__device__ int   g_csrc[N_EDGES];
__device__ float g_cw  [N_EDGES];

// ---------------- helpers ----------------
__device__ __forceinline__ unsigned int f2tf(float f) {
    unsigned int u; asm("cvt.rna.tf32.f32 %0, %1;" : "=r"(u) : "f"(f)); return u;
}

__device__ __forceinline__ void mma_tf32(float* c, const unsigned int* a, const unsigned int* b) {
    asm("mma.sync.aligned.m16n8k8.row.col.f32.tf32.tf32.f32 "
        "{%0,%1,%2,%3},{%4,%5,%6,%7},{%8,%9},{%0,%1,%2,%3};"
        : "+f"(c[0]), "+f"(c[1]), "+f"(c[2]), "+f"(c[3])
        : "r"(a[0]), "r"(a[1]), "r"(a[2]), "r"(a[3]), "r"(b[0]), "r"(b[1]));
}

__global__ void zero_kernel(float4* p, int n4) {
    int i = blockIdx.x * blockDim.x + threadIdx.x;
    if (i < n4) p[i] = make_float4(0.f, 0.f, 0.f, 0.f);
}

// h[:, 0:5] = x, rest 0
__global__ void pad_kernel(const float* __restrict__ x, float* __restrict__ h) {
    int i = blockIdx.x * blockDim.x + threadIdx.x;   // over N*32 float4s
    if (i >= N_NODES * 32) return;
    int n = i >> 5, c4 = i & 31;
    float4 v = make_float4(0.f, 0.f, 0.f, 0.f);
    if (c4 == 0) {
        const float* xr = x + n * IN_F;
        v.x = xr[0]; v.y = xr[1]; v.z = xr[2]; v.w = xr[3];
    } else if (c4 == 1) {
        v.x = x[n * IN_F + 4];
    }
    reinterpret_cast<float4*>(h)[i] = v;
}

// wT[l][n][k] = gconv_w[l][k][n]
__global__ void prep_gconv(const float* __restrict__ w, float* __restrict__ wT) {
    int idx = blockIdx.x * blockDim.x + threadIdx.x;
    if (idx >= 2 * HDIM * HDIM) return;
    int l = idx >> 14, rem = idx & 16383, n = rem >> 7, k = rem & 127;
    wT[l * 16384 + n * 128 + k] = w[l * 16384 + k * 128 + n];
}

// ---------------- CSR build ----------------
__global__ void count_kernel(const int* __restrict__ ei, int* __restrict__ deg) {
    int e = blockIdx.x * blockDim.x + threadIdx.x;
    if (e < N_EDGES) atomicAdd(&deg[ei[N_EDGES + e]], 1);
}

// single-block exclusive scan over 65536 degrees -> off, cursor
__global__ void scan_kernel(const int* __restrict__ deg, int* __restrict__ off,
                            int* __restrict__ cur) {
    __shared__ int ssum[1024];
    int t = threadIdx.x;
    int base = t * 64;
    int s = 0;
    #pragma unroll 8
    for (int i = 0; i < 64; i++) s += deg[base + i];
    int my = s;
    ssum[t] = s;
    __syncthreads();
    // inclusive Hillis-Steele
    for (int o = 1; o < 1024; o <<= 1) {
        int v = (t >= o) ? ssum[t - o] : 0;
        __syncthreads();
        ssum[t] += v;
        __syncthreads();
    }
    int run = ssum[t] - my;   // exclusive prefix of this thread's chunk
    for (int i = 0; i < 64; i++) {
        off[base + i] = run;
        cur[base + i] = run;
        run += deg[base + i];
    }
    if (t == 1023) off[N_NODES] = run;
}

__global__ void fill_kernel(const int* __restrict__ ei, const float* __restrict__ ea,
                            int* __restrict__ cur, int* __restrict__ csrc,
                            float* __restrict__ cw) {
    int e = blockIdx.x * blockDim.x + threadIdx.x;
    if (e >= N_EDGES) return;
    int d = ei[N_EDGES + e];
    int pos = atomicAdd(&cur[d], 1);
    csrc[pos] = ei[e];
    cw[pos]   = ea[e];
}

// ---------------- gather aggregation: agg[n] = sum_e w_e * m[src_e] ----------------
__global__ void agg_kernel(const int* __restrict__ off, const int* __restrict__ csrc,
                           const float* __restrict__ cw, const float4* __restrict__ m4,
                           float4* __restrict__ agg4) {
    int gid  = blockIdx.x * blockDim.x + threadIdx.x;
    int node = gid >> 5;
    int lane = gid & 31;
    if (node >= N_NODES) return;
    int e0 = __ldg(off + node), e1 = __ldg(off + node + 1);
    float4 acc0 = make_float4(0.f, 0.f, 0.f, 0.f);
    float4 acc1 = make_float4(0.f, 0.f, 0.f, 0.f);
    int e = e0;
    for (; e + 1 < e1; e += 2) {
        int   sA = __ldg(csrc + e),     sB = __ldg(csrc + e + 1);
        float wA = __ldg(cw + e),       wB = __ldg(cw + e + 1);
        float4 vA = __ldg(m4 + (size_t)sA * 32 + lane);
        float4 vB = __ldg(m4 + (size_t)sB * 32 + lane);
        acc0.x += wA * vA.x; acc0.y += wA * vA.y; acc0.z += wA * vA.z; acc0.w += wA * vA.w;
        acc1.x += wB * vB.x; acc1.y += wB * vB.y; acc1.z += wB * vB.z; acc1.w += wB * vB.w;
    }
    if (e < e1) {
        int   sA = __ldg(csrc + e);
        float wA = __ldg(cw + e);
        float4 vA = __ldg(m4 + (size_t)sA * 32 + lane);
        acc0.x += wA * vA.x; acc0.y += wA * vA.y; acc0.z += wA * vA.z; acc0.w += wA * vA.w;
    }
    acc0.x += acc1.x; acc0.y += acc1.y; acc0.z += acc1.z; acc0.w += acc1.w;
    agg4[(size_t)node * 32 + lane] = acc0;
}

// ---------------- tf32 tensor-core GEMM ----------------
// C[M,Nc] = A[M,128] @ Bsrc^T  where Bsrc is [Nc,128] row-major (K-major).
// Block tile 128x128, full K=128 in smem, 8 warps (2x4), warp tile 64x32.
// blockIdx.z selects operand set (for merged gi/gh launch).
#define AS_STR 132
#define BS_STR 136
#define GEMM_SMEM ((128 * AS_STR + 128 * BS_STR) * 4)

__global__ void gemm_tf32(const float* __restrict__ A0, const float* __restrict__ B0,
                          const float* __restrict__ bias0, float* __restrict__ C0,
                          const float* __restrict__ A1, const float* __restrict__ B1,
                          const float* __restrict__ bias1, float* __restrict__ C1,
                          int Nc) {
    extern __shared__ unsigned int sm[];
    unsigned int* As = sm;                    // [128][AS_STR]
    unsigned int* Bs = sm + 128 * AS_STR;     // [128][BS_STR]

    const float* A    = blockIdx.z ? A1    : A0;
    const float* Bsrc = blockIdx.z ? B1    : B0;
    const float* bias = blockIdx.z ? bias1 : bias0;
    float*       C    = blockIdx.z ? C1    : C0;

    int t  = threadIdx.x;
    int rb = blockIdx.x * 128;
    int cb = blockIdx.y * 128;

    {
        const float4* A4 = reinterpret_cast<const float4*>(A) + (size_t)rb * 32;
        #pragma unroll
        for (int i = t; i < 128 * 32; i += 256) {
            int r = i >> 5, k4 = i & 31;
            float4 v = A4[r * 32 + k4];
            uint4 u = make_uint4(f2tf(v.x), f2tf(v.y), f2tf(v.z), f2tf(v.w));
            *reinterpret_cast<uint4*>(&As[r * AS_STR + k4 * 4]) = u;
        }
    }
    {
        const float4* B4 = reinterpret_cast<const float4*>(Bsrc) + (size_t)cb * 32;
        #pragma unroll
        for (int i = t; i < 128 * 32; i += 256) {
            int n = i >> 5, k4 = i & 31;
            float4 v = B4[n * 32 + k4];
            uint4 u = make_uint4(f2tf(v.x), f2tf(v.y), f2tf(v.z), f2tf(v.w));
            *reinterpret_cast<uint4*>(&Bs[n * BS_STR + k4 * 4]) = u;
        }
    }
    __syncthreads();

    int warp = t >> 5, lane = t & 31;
    int wm = (warp >> 2) * 64;
    int wn = (warp & 3) * 32;
    int lr = lane >> 2, lc = lane & 3;

    float acc[4][4][4];
    #pragma unroll
    for (int mt = 0; mt < 4; mt++)
        #pragma unroll
        for (int nt = 0; nt < 4; nt++)
            #pragma unroll
            for (int q = 0; q < 4; q++) acc[mt][nt][q] = 0.f;

    #pragma unroll
    for (int kk = 0; kk < 16; kk++) {
        int k0 = kk * 8 + lc;
        unsigned int a[4][4], b[4][2];
        #pragma unroll
        for (int mt = 0; mt < 4; mt++) {
            int r = wm + mt * 16 + lr;
            a[mt][0] = As[r * AS_STR + k0];
            a[mt][1] = As[(r + 8) * AS_STR + k0];
            a[mt][2] = As[r * AS_STR + k0 + 4];
            a[mt][3] = As[(r + 8) * AS_STR + k0 + 4];
        }
        #pragma unroll
        for (int nt = 0; nt < 4; nt++) {
            int n = wn + nt * 8 + lr;
            b[nt][0] = Bs[n * BS_STR + k0];
            b[nt][1] = Bs[n * BS_STR + k0 + 4];
        }
        #pragma unroll
        for (int mt = 0; mt < 4; mt++)
            #pragma unroll
            for (int nt = 0; nt < 4; nt++)
                mma_tf32(acc[mt][nt], a[mt], b[nt]);
    }

    #pragma unroll
    for (int nt = 0; nt < 4; nt++) {
        int c = cb + wn + nt * 8 + lc * 2;
        float b0 = bias ? __ldg(bias + c) : 0.f;
        float b1 = bias ? __ldg(bias + c + 1) : 0.f;
        #pragma unroll
        for (int mt = 0; mt < 4; mt++) {
            int r = rb + wm + mt * 16 + lr;
            float2 v0 = make_float2(acc[mt][nt][0] + b0, acc[mt][nt][1] + b1);
            float2 v1 = make_float2(acc[mt][nt][2] + b0, acc[mt][nt][3] + b1);
            *reinterpret_cast<float2*>(&C[(size_t)r * Nc + c])       = v0;
            *reinterpret_cast<float2*>(&C[(size_t)(r + 8) * Nc + c]) = v1;
        }
    }
}

// ---------------- GRU elementwise update (h in place, vectorized) ----------------
__global__ void gru_kernel(const float4* __restrict__ gi, const float4* __restrict__ gh,
                           float4* __restrict__ h) {
    int idx = blockIdx.x * blockDim.x + threadIdx.x;   // N*32 float4s
    if (idx >= N_NODES * 32) return;
    int n = idx >> 5, q = idx & 31;
    const float4* gin = gi + (size_t)n * 96;
    const float4* ghn = gh + (size_t)n * 96;
    float4 ir = gin[q], iz = gin[q + 32], in_ = gin[q + 64];
    float4 hr = ghn[q], hz = ghn[q + 32], hn  = ghn[q + 64];
    float4 ho = h[idx];
    float4 o;
    {
        float r  = 1.f / (1.f + __expf(-(ir.x + hr.x)));
        float z  = 1.f / (1.f + __expf(-(iz.x + hz.x)));
        float nn = tanhf(in_.x + r * hn.x);
        o.x = (1.f - z) * nn + z * ho.x;
    }
    {
        float r  = 1.f / (1.f + __expf(-(ir.y + hr.y)));
        float z  = 1.f / (1.f + __expf(-(iz.y + hz.y)));
        float nn = tanhf(in_.y + r * hn.y);
        o.y = (1.f - z) * nn + z * ho.y;
    }
    {
        float r  = 1.f / (1.f + __expf(-(ir.z + hr.z)));
        float z  = 1.f / (1.f + __expf(-(iz.z + hz.z)));
        float nn = tanhf(in_.z + r * hn.z);
        o.z = (1.f - z) * nn + z * ho.z;
    }
    {
        float r  = 1.f / (1.f + __expf(-(ir.w + hr.w)));
        float z  = 1.f / (1.f + __expf(-(iz.w + hz.w)));
        float nn = tanhf(in_.w + r * hn.w);
        o.w = (1.f - z) * nn + z * ho.w;
    }
    h[idx] = o;
}

// ---------------- post ----------------
__global__ void post_kernel(const float* __restrict__ h,
                            const float* __restrict__ conv_w, const float* __restrict__ conv_b,
                            const float* __restrict__ lin1_w, const float* __restrict__ lin1_b,
                            const float* __restrict__ lin2_w, const float* __restrict__ lin2_b,
                            float* __restrict__ out) {
    int b = blockIdx.x;
    int t = threadIdx.x;
    __shared__ float cw[48];
    __shared__ float v[ELEC * LCONV];
    __shared__ float u[HDIM];

    if (t < 48) cw[t] = conv_w[t];
    __syncthreads();
    float cb0 = conv_b[0];

    for (int idx = t; idx < ELEC * LCONV; idx += 256) {
        int e = idx / LCONV, l = idx % LCONV;
        float s = cb0;
        #pragma unroll
        for (int g = 0; g < N_GRAPH; g++) {
            const float* hr = h + ((size_t)((b * N_GRAPH + g) * ELEC + e)) * HDIM + 2 * l;
            s += cw[g * 3 + 0] * fmaxf(hr[0], 0.f)
               + cw[g * 3 + 1] * fmaxf(hr[1], 0.f)
               + cw[g * 3 + 2] * fmaxf(hr[2], 0.f);
        }
        v[idx] = fmaxf(s, 0.f);
    }
    __syncthreads();

    int w = t >> 5, lane = t & 31;
    for (int j = w; j < HDIM; j += 8) {
        float s = 0.f;
        for (int f = lane * 4; f < ELEC * LCONV; f += 128) {
            float4 wv = *reinterpret_cast<const float4*>(&lin1_w[(size_t)j * 2016 + f]);
            float4 vv = *reinterpret_cast<const float4*>(&v[f]);
            s += wv.x * vv.x + wv.y * vv.y + wv.z * vv.z + wv.w * vv.w;
        }
        #pragma unroll
        for (int o = 16; o; o >>= 1) s += __shfl_xor_sync(0xffffffffu, s, o);
        if (lane == 0) u[j] = fmaxf(s + lin1_b[j], 0.f);
    }
    __syncthreads();

    if (t < 32) {
        float s3[3];
        #pragma unroll
        for (int j = 0; j < 3; j++) {
            float acc = 0.f;
            for (int f = t; f < HDIM; f += 32) acc += lin2_w[j * HDIM + f] * u[f];
            #pragma unroll
            for (int o = 16; o; o >>= 1) acc += __shfl_xor_sync(0xffffffffu, acc, o);
            s3[j] = acc + lin2_b[j];
        }
        if (t == 0) {
            float mx = fmaxf(s3[0], fmaxf(s3[1], s3[2]));
            float e0 = expf(s3[0] - mx), e1 = expf(s3[1] - mx), e2 = expf(s3[2] - mx);
            float inv = 1.f / (e0 + e1 + e2);
            out[b * 3 + 0] = e0 * inv;
            out[b * 3 + 1] = e1 * inv;
            out[b * 3 + 2] = e2 * inv;
        }
    }
}

// ---------------- launch ----------------
extern "C" void kernel_launch(void* const* d_in, const int* in_sizes, int n_in,
                              void* d_out, int out_size) {
    const float* x       = (const float*)d_in[0];
    const int*   ei      = (const int*)  d_in[1];
    const float* ea      = (const float*)d_in[2];
    const float* gconv_w = (const float*)d_in[4];
    const float* w_ih    = (const float*)d_in[5];
    const float* w_hh    = (const float*)d_in[6];
    const float* b_ih    = (const float*)d_in[7];
    const float* b_hh    = (const float*)d_in[8];
    const float* conv_w  = (const float*)d_in[9];
    const float* conv_b  = (const float*)d_in[10];
    const float* lin1_w  = (const float*)d_in[11];
    const float* lin1_b  = (const float*)d_in[12];
    const float* lin2_w  = (const float*)d_in[13];
    const float* lin2_b  = (const float*)d_in[14];
    float* out = (float*)d_out;

    float *ph, *pm, *pagg, *pgi, *pgh, *pwT, *pcw;
    int *pdeg, *poff, *pcur, *pcsrc;
    cudaGetSymbolAddress((void**)&ph,    g_h);
    cudaGetSymbolAddress((void**)&pm,    g_m);
    cudaGetSymbolAddress((void**)&pagg,  g_agg);
    cudaGetSymbolAddress((void**)&pgi,   g_gi);
    cudaGetSymbolAddress((void**)&pgh,   g_gh);
    cudaGetSymbolAddress((void**)&pwT,   g_wT);
    cudaGetSymbolAddress((void**)&pdeg,  g_deg);
    cudaGetSymbolAddress((void**)&poff,  g_off);
    cudaGetSymbolAddress((void**)&pcur,  g_cur);
    cudaGetSymbolAddress((void**)&pcsrc, g_csrc);
    cudaGetSymbolAddress((void**)&pcw,   g_cw);

    cudaFuncSetAttribute(gemm_tf32, cudaFuncAttributeMaxDynamicSharedMemorySize, GEMM_SMEM);

    // preprocessing
    prep_gconv<<<(2 * HDIM * HDIM + 255) / 256, 256>>>(gconv_w, pwT);
    pad_kernel<<<(N_NODES * 32 + 255) / 256, 256>>>(x, ph);
    // CSR build
    zero_kernel<<<(N_NODES / 4 + 255) / 256, 256>>>((float4*)pdeg, N_NODES / 4);
    count_kernel<<<N_EDGES / 256, 256>>>(ei, pdeg);
    scan_kernel<<<1, 1024>>>(pdeg, poff, pcur);
    fill_kernel<<<N_EDGES / 256, 256>>>(ei, ea, pcur, pcsrc, pcw);

    for (int layer = 0; layer < 2; layer++) {
        // m = h @ gconv_w[layer]
        gemm_tf32<<<dim3(N_NODES / 128, 1, 1), 256, GEMM_SMEM>>>(
            ph, pwT + (size_t)layer * HDIM * HDIM, nullptr, pm,
            nullptr, nullptr, nullptr, nullptr, HDIM);
        // agg[n] = sum_{e->n} w_e * m[src_e]   (CSR gather, no atomics)
        agg_kernel<<<N_NODES * 32 / 256, 256>>>(poff, pcsrc, pcw,
                                                (const float4*)pm, (float4*)pagg);
        // gi = agg @ w_ih^T + b_ih ; gh = h @ w_hh^T + b_hh  (merged launch)
        gemm_tf32<<<dim3(N_NODES / 128, 3, 2), 256, GEMM_SMEM>>>(
            pagg, w_ih, b_ih, pgi,
            ph,   w_hh, b_hh, pgh, 384);
        // GRU update
        gru_kernel<<<(N_NODES * 32 + 255) / 256, 256>>>(
            (const float4*)pgi, (const float4*)pgh, (float4*)ph);
    }

    post_kernel<<<BSZ, 256>>>(ph, conv_w, conv_b, lin1_w, lin1_b, lin2_w, lin2_b, out);
}

// round 5
// speedup vs baseline: 1.2266x; 1.2266x over previous
#include <cuda_runtime.h>
#include <cuda_bf16.h>
#include <cstdint>

#define N_NODES 65536
#define N_EDGES 1048576
#define HDIM    128
#define IN_F    5
#define N_GRAPH 16
#define ELEC    32
#define BSZ     128
#define LCONV   63   // (128-3)/2+1

// ---------------- device scratch (no allocations allowed) ----------------
__device__ float g_h  [N_NODES * HDIM];     // 32 MB
__device__ float g_m  [N_NODES * HDIM];     // 32 MB
__device__ float g_agg[N_NODES * HDIM];     // 32 MB
__device__ float g_wT [2 * HDIM * HDIM];    // transposed gconv weights [2][n][k]
// CSR scratch
__device__ int   g_deg [N_NODES];
__device__ int   g_off [N_NODES + 1];
__device__ int   g_cur [N_NODES];
__device__ int   g_csrc[N_EDGES];
__device__ float g_cw  [N_EDGES];

// ---------------- helpers ----------------
__device__ __forceinline__ unsigned int f2tf(float f) {
    unsigned int u; asm("cvt.rna.tf32.f32 %0, %1;" : "=r"(u) : "f"(f)); return u;
}

__device__ __forceinline__ void mma_tf32(float* c, const unsigned int* a, const unsigned int* b) {
    asm("mma.sync.aligned.m16n8k8.row.col.f32.tf32.tf32.f32 "
        "{%0,%1,%2,%3},{%4,%5,%6,%7},{%8,%9},{%0,%1,%2,%3};"
        : "+f"(c[0]), "+f"(c[1]), "+f"(c[2]), "+f"(c[3])
        : "r"(a[0]), "r"(a[1]), "r"(a[2]), "r"(a[3]), "r"(b[0]), "r"(b[1]));
}

__global__ void zero_kernel(float4* p, int n4) {
    int i = blockIdx.x * blockDim.x + threadIdx.x;
    if (i < n4) p[i] = make_float4(0.f, 0.f, 0.f, 0.f);
}

// h[:, 0:5] = x, rest 0
__global__ void pad_kernel(const float* __restrict__ x, float* __restrict__ h) {
    int i = blockIdx.x * blockDim.x + threadIdx.x;
    if (i >= N_NODES * 32) return;
    int n = i >> 5, c4 = i & 31;
    float4 v = make_float4(0.f, 0.f, 0.f, 0.f);
    if (c4 == 0) {
        const float* xr = x + n * IN_F;
        v.x = xr[0]; v.y = xr[1]; v.z = xr[2]; v.w = xr[3];
    } else if (c4 == 1) {
        v.x = x[n * IN_F + 4];
    }
    reinterpret_cast<float4*>(h)[i] = v;
}

// wT[l][n][k] = gconv_w[l][k][n]
__global__ void prep_gconv(const float* __restrict__ w, float* __restrict__ wT) {
    int idx = blockIdx.x * blockDim.x + threadIdx.x;
    if (idx >= 2 * HDIM * HDIM) return;
    int l = idx >> 14, rem = idx & 16383, n = rem >> 7, k = rem & 127;
    wT[l * 16384 + n * 128 + k] = w[l * 16384 + k * 128 + n];
}

// ---------------- CSR build ----------------
__global__ void count_kernel(const int* __restrict__ ei, int* __restrict__ deg) {
    int e = blockIdx.x * blockDim.x + threadIdx.x;
    if (e < N_EDGES) atomicAdd(&deg[ei[N_EDGES + e]], 1);
}

__global__ void scan_kernel(const int* __restrict__ deg, int* __restrict__ off,
                            int* __restrict__ cur) {
    __shared__ int ssum[1024];
    int t = threadIdx.x;
    int base = t * 64;
    int s = 0;
    #pragma unroll 8
    for (int i = 0; i < 64; i++) s += deg[base + i];
    int my = s;
    ssum[t] = s;
    __syncthreads();
    for (int o = 1; o < 1024; o <<= 1) {
        int v = (t >= o) ? ssum[t - o] : 0;
        __syncthreads();
        ssum[t] += v;
        __syncthreads();
    }
    int run = ssum[t] - my;
    for (int i = 0; i < 64; i++) {
        off[base + i] = run;
        cur[base + i] = run;
        run += deg[base + i];
    }
    if (t == 1023) off[N_NODES] = run;
}

__global__ void fill_kernel(const int* __restrict__ ei, const float* __restrict__ ea,
                            int* __restrict__ cur, int* __restrict__ csrc,
                            float* __restrict__ cw) {
    int e = blockIdx.x * blockDim.x + threadIdx.x;
    if (e >= N_EDGES) return;
    int d = ei[N_EDGES + e];
    int pos = atomicAdd(&cur[d], 1);
    csrc[pos] = ei[e];
    cw[pos]   = ea[e];
}

// ---------------- gather aggregation ----------------
__global__ void agg_kernel(const int* __restrict__ off, const int* __restrict__ csrc,
                           const float* __restrict__ cw, const float4* __restrict__ m4,
                           float4* __restrict__ agg4) {
    int gid  = blockIdx.x * blockDim.x + threadIdx.x;
    int node = gid >> 5;
    int lane = gid & 31;
    if (node >= N_NODES) return;
    int e0 = __ldg(off + node), e1 = __ldg(off + node + 1);
    float4 acc0 = make_float4(0.f, 0.f, 0.f, 0.f);
    float4 acc1 = make_float4(0.f, 0.f, 0.f, 0.f);
    int e = e0;
    for (; e + 1 < e1; e += 2) {
        int   sA = __ldg(csrc + e),     sB = __ldg(csrc + e + 1);
        float wA = __ldg(cw + e),       wB = __ldg(cw + e + 1);
        float4 vA = __ldg(m4 + (size_t)sA * 32 + lane);
        float4 vB = __ldg(m4 + (size_t)sB * 32 + lane);
        acc0.x += wA * vA.x; acc0.y += wA * vA.y; acc0.z += wA * vA.z; acc0.w += wA * vA.w;
        acc1.x += wB * vB.x; acc1.y += wB * vB.y; acc1.z += wB * vB.z; acc1.w += wB * vB.w;
    }
    if (e < e1) {
        int   sA = __ldg(csrc + e);
        float wA = __ldg(cw + e);
        float4 vA = __ldg(m4 + (size_t)sA * 32 + lane);
        acc0.x += wA * vA.x; acc0.y += wA * vA.y; acc0.z += wA * vA.z; acc0.w += wA * vA.w;
    }
    acc0.x += acc1.x; acc0.y += acc1.y; acc0.z += acc1.z; acc0.w += acc1.w;
    agg4[(size_t)node * 32 + lane] = acc0;
}

// ---------------- tf32 GEMM (m = h @ gconv_w, Nc=128) ----------------
#define AS_STR 132
#define BS_STR 136
#define GEMM_SMEM ((128 * AS_STR + 128 * BS_STR) * 4)

__global__ void gemm_tf32(const float* __restrict__ A, const float* __restrict__ Bsrc,
                          float* __restrict__ C, int Nc) {
    extern __shared__ unsigned int sm[];
    unsigned int* As = sm;
    unsigned int* Bs = sm + 128 * AS_STR;

    int t  = threadIdx.x;
    int rb = blockIdx.x * 128;
    int cb = blockIdx.y * 128;

    {
        const float4* A4 = reinterpret_cast<const float4*>(A) + (size_t)rb * 32;
        #pragma unroll
        for (int i = t; i < 128 * 32; i += 256) {
            int r = i >> 5, k4 = i & 31;
            float4 v = A4[r * 32 + k4];
            uint4 u = make_uint4(f2tf(v.x), f2tf(v.y), f2tf(v.z), f2tf(v.w));
            *reinterpret_cast<uint4*>(&As[r * AS_STR + k4 * 4]) = u;
        }
    }
    {
        const float4* B4 = reinterpret_cast<const float4*>(Bsrc) + (size_t)cb * 32;
        #pragma unroll
        for (int i = t; i < 128 * 32; i += 256) {
            int n = i >> 5, k4 = i & 31;
            float4 v = B4[n * 32 + k4];
            uint4 u = make_uint4(f2tf(v.x), f2tf(v.y), f2tf(v.z), f2tf(v.w));
            *reinterpret_cast<uint4*>(&Bs[n * BS_STR + k4 * 4]) = u;
        }
    }
    __syncthreads();

    int warp = t >> 5, lane = t & 31;
    int wm = (warp >> 2) * 64;
    int wn = (warp & 3) * 32;
    int lr = lane >> 2, lc = lane & 3;

    float acc[4][4][4];
    #pragma unroll
    for (int mt = 0; mt < 4; mt++)
        #pragma unroll
        for (int nt = 0; nt < 4; nt++)
            #pragma unroll
            for (int q = 0; q < 4; q++) acc[mt][nt][q] = 0.f;

    #pragma unroll
    for (int kk = 0; kk < 16; kk++) {
        int k0 = kk * 8 + lc;
        unsigned int a[4][4], b[4][2];
        #pragma unroll
        for (int mt = 0; mt < 4; mt++) {
            int r = wm + mt * 16 + lr;
            a[mt][0] = As[r * AS_STR + k0];
            a[mt][1] = As[(r + 8) * AS_STR + k0];
            a[mt][2] = As[r * AS_STR + k0 + 4];
            a[mt][3] = As[(r + 8) * AS_STR + k0 + 4];
        }
        #pragma unroll
        for (int nt = 0; nt < 4; nt++) {
            int n = wn + nt * 8 + lr;
            b[nt][0] = Bs[n * BS_STR + k0];
            b[nt][1] = Bs[n * BS_STR + k0 + 4];
        }
        #pragma unroll
        for (int mt = 0; mt < 4; mt++)
            #pragma unroll
            for (int nt = 0; nt < 4; nt++)
                mma_tf32(acc[mt][nt], a[mt], b[nt]);
    }

    #pragma unroll
    for (int nt = 0; nt < 4; nt++) {
        int c = cb + wn + nt * 8 + lc * 2;
        #pragma unroll
        for (int mt = 0; mt < 4; mt++) {
            int r = rb + wm + mt * 16 + lr;
            float2 v0 = make_float2(acc[mt][nt][0], acc[mt][nt][1]);
            float2 v1 = make_float2(acc[mt][nt][2], acc[mt][nt][3]);
            *reinterpret_cast<float2*>(&C[(size_t)r * Nc + c])       = v0;
            *reinterpret_cast<float2*>(&C[(size_t)(r + 8) * Nc + c]) = v1;
        }
    }
}

// ---------------- fused GRU: gi-GEMM + gh-GEMM + GRU update ----------------
// Block: 64 node rows, 512 threads (16 warps in 2x8 grid).
// Warp tile: 32 rows (2 m-tiles) x 16 cols of EACH of the 3 gates (2 n-tiles/gate).
// Phase 0: acc = agg @ w_ih^T, stashed to smem gi buffer (same thread owns same
// positions in both phases). Phase 1: acc = h @ w_hh^T, then GRU epilogue writes h.
#define FAS_STR 68
#define FBS_STR 68
#define GI_STR  388
#define FUSED_SMEM ((64 * FAS_STR + 384 * FBS_STR + 64 * GI_STR) * 4)

__global__ void __launch_bounds__(512, 1)
gru_fused(const float* __restrict__ agg, float* __restrict__ h,
          const float* __restrict__ w_ih, const float* __restrict__ w_hh,
          const float* __restrict__ b_ih, const float* __restrict__ b_hh) {
    extern __shared__ unsigned int sm[];
    unsigned int* As = sm;                         // [64][FAS_STR]  k-chunk of A
    unsigned int* Bs = sm + 64 * FAS_STR;          // [384][FBS_STR] k-chunk of W
    float* sgi = reinterpret_cast<float*>(sm + 64 * FAS_STR + 384 * FBS_STR); // [64][GI_STR]

    int t = threadIdx.x;
    int rb = blockIdx.x * 64;
    int warp = t >> 5, lane = t & 31;
    int wr = warp & 1;        // 2 warp-rows
    int wc = warp >> 1;       // 8 warp-cols
    int lr = lane >> 2, lc = lane & 3;

    float acc[2][3][2][4];    // [mt][gate][nt][frag]

    #pragma unroll
    for (int phase = 0; phase < 2; phase++) {
        const float* A = phase ? h    : agg;
        const float* W = phase ? w_hh : w_ih;

        #pragma unroll
        for (int mt = 0; mt < 2; mt++)
            #pragma unroll
            for (int g = 0; g < 3; g++)
                #pragma unroll
                for (int nt = 0; nt < 2; nt++)
                    #pragma unroll
                    for (int q = 0; q < 4; q++) acc[mt][g][nt][q] = 0.f;

        for (int kc = 0; kc < 2; kc++) {
            __syncthreads();
            // load A chunk: 64 rows x 64 k
            #pragma unroll
            for (int i = t; i < 64 * 16; i += 512) {
                int r = i >> 4, k4 = i & 15;
                float4 v = *reinterpret_cast<const float4*>(
                    &A[(size_t)(rb + r) * 128 + kc * 64 + k4 * 4]);
                uint4 u = make_uint4(f2tf(v.x), f2tf(v.y), f2tf(v.z), f2tf(v.w));
                *reinterpret_cast<uint4*>(&As[r * FAS_STR + k4 * 4]) = u;
            }
            // load W chunk: 384 rows x 64 k
            #pragma unroll
            for (int i = t; i < 384 * 16; i += 512) {
                int n = i >> 4, k4 = i & 15;
                float4 v = *reinterpret_cast<const float4*>(
                    &W[(size_t)n * 128 + kc * 64 + k4 * 4]);
                uint4 u = make_uint4(f2tf(v.x), f2tf(v.y), f2tf(v.z), f2tf(v.w));
                *reinterpret_cast<uint4*>(&Bs[n * FBS_STR + k4 * 4]) = u;
            }
            __syncthreads();

            #pragma unroll
            for (int ks = 0; ks < 8; ks++) {
                int k0 = ks * 8 + lc;
                unsigned int a[2][4], b[3][2][2];
                #pragma unroll
                for (int mt = 0; mt < 2; mt++) {
                    int r = wr * 32 + mt * 16 + lr;
                    a[mt][0] = As[r * FAS_STR + k0];
                    a[mt][1] = As[(r + 8) * FAS_STR + k0];
                    a[mt][2] = As[r * FAS_STR + k0 + 4];
                    a[mt][3] = As[(r + 8) * FAS_STR + k0 + 4];
                }
                #pragma unroll
                for (int g = 0; g < 3; g++)
                    #pragma unroll
                    for (int nt = 0; nt < 2; nt++) {
                        int n = g * 128 + wc * 16 + nt * 8 + lr;
                        b[g][nt][0] = Bs[n * FBS_STR + k0];
                        b[g][nt][1] = Bs[n * FBS_STR + k0 + 4];
                    }
                #pragma unroll
                for (int mt = 0; mt < 2; mt++)
                    #pragma unroll
                    for (int g = 0; g < 3; g++)
                        #pragma unroll
                        for (int nt = 0; nt < 2; nt++)
                            mma_tf32(acc[mt][g][nt], a[mt], b[g][nt]);
            }
        }

        if (phase == 0) {
            // stash gi fragments (thread-private positions; no barrier needed)
            #pragma unroll
            for (int mt = 0; mt < 2; mt++)
                #pragma unroll
                for (int g = 0; g < 3; g++)
                    #pragma unroll
                    for (int nt = 0; nt < 2; nt++) {
                        int row = wr * 32 + mt * 16 + lr;
                        int c = g * 128 + wc * 16 + nt * 8 + lc * 2;
                        *reinterpret_cast<float2*>(&sgi[row * GI_STR + c]) =
                            make_float2(acc[mt][g][nt][0], acc[mt][g][nt][1]);
                        *reinterpret_cast<float2*>(&sgi[(row + 8) * GI_STR + c]) =
                            make_float2(acc[mt][g][nt][2], acc[mt][g][nt][3]);
                    }
        }
    }

    // GRU epilogue: acc holds gh; sgi holds gi (same thread wrote same positions)
    #pragma unroll
    for (int nt = 0; nt < 2; nt++) {
        int c = wc * 16 + nt * 8 + lc * 2;   // col within gate, 0..127
        float bir0 = __ldg(b_ih + c),       bir1 = __ldg(b_ih + c + 1);
        float biz0 = __ldg(b_ih + 128 + c), biz1 = __ldg(b_ih + 128 + c + 1);
        float bin0 = __ldg(b_ih + 256 + c), bin1 = __ldg(b_ih + 256 + c + 1);
        float bhr0 = __ldg(b_hh + c),       bhr1 = __ldg(b_hh + c + 1);
        float bhz0 = __ldg(b_hh + 128 + c), bhz1 = __ldg(b_hh + 128 + c + 1);
        float bhn0 = __ldg(b_hh + 256 + c), bhn1 = __ldg(b_hh + 256 + c + 1);
        #pragma unroll
        for (int mt = 0; mt < 2; mt++) {
            #pragma unroll
            for (int half = 0; half < 2; half++) {
                int row = wr * 32 + mt * 16 + lr + half * 8;
                int q0 = half * 2;
                float2 gir = *reinterpret_cast<float2*>(&sgi[row * GI_STR + c]);
                float2 giz = *reinterpret_cast<float2*>(&sgi[row * GI_STR + 128 + c]);
                float2 gin = *reinterpret_cast<float2*>(&sgi[row * GI_STR + 256 + c]);
                float ghr0 = acc[mt][0][nt][q0], ghr1 = acc[mt][0][nt][q0 + 1];
                float ghz0 = acc[mt][1][nt][q0], ghz1 = acc[mt][1][nt][q0 + 1];
                float ghn0 = acc[mt][2][nt][q0], ghn1 = acc[mt][2][nt][q0 + 1];
                float2 hold = *reinterpret_cast<float2*>(&h[(size_t)(rb + row) * 128 + c]);
                float r0 = 1.f / (1.f + __expf(-(gir.x + ghr0 + bir0 + bhr0)));
                float z0 = 1.f / (1.f + __expf(-(giz.x + ghz0 + biz0 + bhz0)));
                float n0 = tanhf(gin.x + bin0 + r0 * (ghn0 + bhn0));
                float r1 = 1.f / (1.f + __expf(-(gir.y + ghr1 + bir1 + bhr1)));
                float z1 = 1.f / (1.f + __expf(-(giz.y + ghz1 + biz1 + bhz1)));
                float n1 = tanhf(gin.y + bin1 + r1 * (ghn1 + bhn1));
                float2 hnew = make_float2((1.f - z0) * n0 + z0 * hold.x,
                                          (1.f - z1) * n1 + z1 * hold.y);
                *reinterpret_cast<float2*>(&h[(size_t)(rb + row) * 128 + c]) = hnew;
            }
        }
    }
}

// ---------------- post ----------------
__global__ void post_kernel(const float* __restrict__ h,
                            const float* __restrict__ conv_w, const float* __restrict__ conv_b,
                            const float* __restrict__ lin1_w, const float* __restrict__ lin1_b,
                            const float* __restrict__ lin2_w, const float* __restrict__ lin2_b,
                            float* __restrict__ out) {
    int b = blockIdx.x;
    int t = threadIdx.x;
    __shared__ float cw[48];
    __shared__ float v[ELEC * LCONV];
    __shared__ float u[HDIM];

    if (t < 48) cw[t] = conv_w[t];
    __syncthreads();
    float cb0 = conv_b[0];

    for (int idx = t; idx < ELEC * LCONV; idx += 256) {
        int e = idx / LCONV, l = idx % LCONV;
        float s = cb0;
        #pragma unroll
        for (int g = 0; g < N_GRAPH; g++) {
            const float* hr = h + ((size_t)((b * N_GRAPH + g) * ELEC + e)) * HDIM + 2 * l;
            s += cw[g * 3 + 0] * fmaxf(hr[0], 0.f)
               + cw[g * 3 + 1] * fmaxf(hr[1], 0.f)
               + cw[g * 3 + 2] * fmaxf(hr[2], 0.f);
        }
        v[idx] = fmaxf(s, 0.f);
    }
    __syncthreads();

    int w = t >> 5, lane = t & 31;
    for (int j = w; j < HDIM; j += 8) {
        float s = 0.f;
        for (int f = lane * 4; f < ELEC * LCONV; f += 128) {
            float4 wv = *reinterpret_cast<const float4*>(&lin1_w[(size_t)j * 2016 + f]);
            float4 vv = *reinterpret_cast<const float4*>(&v[f]);
            s += wv.x * vv.x + wv.y * vv.y + wv.z * vv.z + wv.w * vv.w;
        }
        #pragma unroll
        for (int o = 16; o; o >>= 1) s += __shfl_xor_sync(0xffffffffu, s, o);
        if (lane == 0) u[j] = fmaxf(s + lin1_b[j], 0.f);
    }
    __syncthreads();

    if (t < 32) {
        float s3[3];
        #pragma unroll
        for (int j = 0; j < 3; j++) {
            float acc = 0.f;
            for (int f = t; f < HDIM; f += 32) acc += lin2_w[j * HDIM + f] * u[f];
            #pragma unroll
            for (int o = 16; o; o >>= 1) acc += __shfl_xor_sync(0xffffffffu, acc, o);
            s3[j] = acc + lin2_b[j];
        }
        if (t == 0) {
            float mx = fmaxf(s3[0], fmaxf(s3[1], s3[2]));
            float e0 = expf(s3[0] - mx), e1 = expf(s3[1] - mx), e2 = expf(s3[2] - mx);
            float inv = 1.f / (e0 + e1 + e2);
            out[b * 3 + 0] = e0 * inv;
            out[b * 3 + 1] = e1 * inv;
            out[b * 3 + 2] = e2 * inv;
        }
    }
}

// ---------------- launch ----------------
extern "C" void kernel_launch(void* const* d_in, const int* in_sizes, int n_in,
                              void* d_out, int out_size) {
    const float* x       = (const float*)d_in[0];
    const int*   ei      = (const int*)  d_in[1];
    const float* ea      = (const float*)d_in[2];
    const float* gconv_w = (const float*)d_in[4];
    const float* w_ih    = (const float*)d_in[5];
    const float* w_hh    = (const float*)d_in[6];
    const float* b_ih    = (const float*)d_in[7];
    const float* b_hh    = (const float*)d_in[8];
    const float* conv_w  = (const float*)d_in[9];
    const float* conv_b  = (const float*)d_in[10];
    const float* lin1_w  = (const float*)d_in[11];
    const float* lin1_b  = (const float*)d_in[12];
    const float* lin2_w  = (const float*)d_in[13];
    const float* lin2_b  = (const float*)d_in[14];
    float* out = (float*)d_out;

    float *ph, *pm, *pagg, *pwT, *pcw;
    int *pdeg, *poff, *pcur, *pcsrc;
    cudaGetSymbolAddress((void**)&ph,    g_h);
    cudaGetSymbolAddress((void**)&pm,    g_m);
    cudaGetSymbolAddress((void**)&pagg,  g_agg);
    cudaGetSymbolAddress((void**)&pwT,   g_wT);
    cudaGetSymbolAddress((void**)&pdeg,  g_deg);
    cudaGetSymbolAddress((void**)&poff,  g_off);
    cudaGetSymbolAddress((void**)&pcur,  g_cur);
    cudaGetSymbolAddress((void**)&pcsrc, g_csrc);
    cudaGetSymbolAddress((void**)&pcw,   g_cw);

    cudaFuncSetAttribute(gemm_tf32, cudaFuncAttributeMaxDynamicSharedMemorySize, GEMM_SMEM);
    cudaFuncSetAttribute(gru_fused, cudaFuncAttributeMaxDynamicSharedMemorySize, FUSED_SMEM);

    // preprocessing
    prep_gconv<<<(2 * HDIM * HDIM + 255) / 256, 256>>>(gconv_w, pwT);
    pad_kernel<<<(N_NODES * 32 + 255) / 256, 256>>>(x, ph);
    // CSR build
    zero_kernel<<<(N_NODES / 4 + 255) / 256, 256>>>((float4*)pdeg, N_NODES / 4);
    count_kernel<<<N_EDGES / 256, 256>>>(ei, pdeg);
    scan_kernel<<<1, 1024>>>(pdeg, poff, pcur);
    fill_kernel<<<N_EDGES / 256, 256>>>(ei, ea, pcur, pcsrc, pcw);

    for (int layer = 0; layer < 2; layer++) {
        // m = h @ gconv_w[layer]
        gemm_tf32<<<dim3(N_NODES / 128, 1), 256, GEMM_SMEM>>>(
            ph, pwT + (size_t)layer * HDIM * HDIM, pm, HDIM);
        // agg[n] = sum_{e->n} w_e * m[src_e]
        agg_kernel<<<N_NODES * 32 / 256, 256>>>(poff, pcsrc, pcw,
                                                (const float4*)pm, (float4*)pagg);
        // fused: gi-GEMM + gh-GEMM + GRU -> h (in place)
        gru_fused<<<N_NODES / 64, 512, FUSED_SMEM>>>(pagg, ph, w_ih, w_hh, b_ih, b_hh);
    }

    post_kernel<<<BSZ, 256>>>(ph, conv_w, conv_b, lin1_w, lin1_b, lin2_w, lin2_b, out);
}

// round 6
// speedup vs baseline: 1.4474x; 1.1800x over previous
#include <cuda_runtime.h>
#include <cuda_bf16.h>
#include <cstdint>

#define N_NODES 65536
#define N_EDGES 1048576
#define HDIM    128
#define IN_F    5
#define N_GRAPH 16
#define ELEC    32
#define BSZ     128
#define LCONV   63   // (128-3)/2+1

// ---------------- device scratch (no allocations allowed) ----------------
__device__ float g_h  [N_NODES * HDIM];     // 32 MB
__device__ float g_agg[N_NODES * HDIM];     // 32 MB
__device__ float g_qt [2 * 384 * HDIM];     // combined Wg@W_ih^T per layer, [384][128] K-major
// CSR scratch
__device__ int   g_deg [N_NODES];
__device__ int   g_off [N_NODES + 1];
__device__ int   g_cur [N_NODES];
__device__ int   g_csrc[N_EDGES];
__device__ float g_cw  [N_EDGES];

// ---------------- helpers ----------------
__device__ __forceinline__ unsigned int f2tf(float f) {
    unsigned int u; asm("cvt.rna.tf32.f32 %0, %1;" : "=r"(u) : "f"(f)); return u;
}

__device__ __forceinline__ void mma_tf32(float* c, const unsigned int* a, const unsigned int* b) {
    asm("mma.sync.aligned.m16n8k8.row.col.f32.tf32.tf32.f32 "
        "{%0,%1,%2,%3},{%4,%5,%6,%7},{%8,%9},{%0,%1,%2,%3};"
        : "+f"(c[0]), "+f"(c[1]), "+f"(c[2]), "+f"(c[3])
        : "r"(a[0]), "r"(a[1]), "r"(a[2]), "r"(a[3]), "r"(b[0]), "r"(b[1]));
}

__global__ void zero_kernel(float4* p, int n4) {
    int i = blockIdx.x * blockDim.x + threadIdx.x;
    if (i < n4) p[i] = make_float4(0.f, 0.f, 0.f, 0.f);
}

// h[:, 0:5] = x, rest 0
__global__ void pad_kernel(const float* __restrict__ x, float* __restrict__ h) {
    int i = blockIdx.x * blockDim.x + threadIdx.x;
    if (i >= N_NODES * 32) return;
    int n = i >> 5, c4 = i & 31;
    float4 v = make_float4(0.f, 0.f, 0.f, 0.f);
    if (c4 == 0) {
        const float* xr = x + n * IN_F;
        v.x = xr[0]; v.y = xr[1]; v.z = xr[2]; v.w = xr[3];
    } else if (c4 == 1) {
        v.x = x[n * IN_F + 4];
    }
    reinterpret_cast<float4*>(h)[i] = v;
}

// ---------------- CSR build ----------------
__global__ void count_kernel(const int* __restrict__ ei, int* __restrict__ deg) {
    int e = blockIdx.x * blockDim.x + threadIdx.x;
    if (e < N_EDGES) atomicAdd(&deg[ei[N_EDGES + e]], 1);
}

__global__ void scan_kernel(const int* __restrict__ deg, int* __restrict__ off,
                            int* __restrict__ cur) {
    __shared__ int ssum[1024];
    int t = threadIdx.x;
    int base = t * 64;
    int s = 0;
    #pragma unroll 8
    for (int i = 0; i < 64; i++) s += deg[base + i];
    int my = s;
    ssum[t] = s;
    __syncthreads();
    for (int o = 1; o < 1024; o <<= 1) {
        int v = (t >= o) ? ssum[t - o] : 0;
        __syncthreads();
        ssum[t] += v;
        __syncthreads();
    }
    int run = ssum[t] - my;
    for (int i = 0; i < 64; i++) {
        off[base + i] = run;
        cur[base + i] = run;
        run += deg[base + i];
    }
    if (t == 1023) off[N_NODES] = run;
}

__global__ void fill_kernel(const int* __restrict__ ei, const float* __restrict__ ea,
                            int* __restrict__ cur, int* __restrict__ csrc,
                            float* __restrict__ cw) {
    int e = blockIdx.x * blockDim.x + threadIdx.x;
    if (e >= N_EDGES) return;
    int d = ei[N_EDGES + e];
    int pos = atomicAdd(&cur[d], 1);
    csrc[pos] = ei[e];
    cw[pos]   = ea[e];
}

// ---------------- gather aggregation (full 128 cols, layer 2) ----------------
__global__ void agg_kernel(const int* __restrict__ off, const int* __restrict__ csrc,
                           const float* __restrict__ cw, const float4* __restrict__ src4,
                           float4* __restrict__ dst4) {
    int gid  = blockIdx.x * blockDim.x + threadIdx.x;
    int node = gid >> 5;
    int lane = gid & 31;
    if (node >= N_NODES) return;
    int e0 = __ldg(off + node), e1 = __ldg(off + node + 1);
    float4 acc0 = make_float4(0.f, 0.f, 0.f, 0.f);
    float4 acc1 = make_float4(0.f, 0.f, 0.f, 0.f);
    int e = e0;
    for (; e + 1 < e1; e += 2) {
        int   sA = __ldg(csrc + e),     sB = __ldg(csrc + e + 1);
        float wA = __ldg(cw + e),       wB = __ldg(cw + e + 1);
        float4 vA = __ldg(src4 + (size_t)sA * 32 + lane);
        float4 vB = __ldg(src4 + (size_t)sB * 32 + lane);
        acc0.x += wA * vA.x; acc0.y += wA * vA.y; acc0.z += wA * vA.z; acc0.w += wA * vA.w;
        acc1.x += wB * vB.x; acc1.y += wB * vB.y; acc1.z += wB * vB.z; acc1.w += wB * vB.w;
    }
    if (e < e1) {
        int   sA = __ldg(csrc + e);
        float wA = __ldg(cw + e);
        float4 vA = __ldg(src4 + (size_t)sA * 32 + lane);
        acc0.x += wA * vA.x; acc0.y += wA * vA.y; acc0.z += wA * vA.z; acc0.w += wA * vA.w;
    }
    acc0.x += acc1.x; acc0.y += acc1.y; acc0.z += acc1.z; acc0.w += acc1.w;
    dst4[(size_t)node * 32 + lane] = acc0;
}

// ---------------- layer-1 aggregation: h has only cols 0..4 nonzero ----------------
// Edge-parallel across lanes; gathers 2 float4s (cols 0..7) per edge, warp-reduce.
// Writes cols 0..63 (16 float4s, zeros beyond col 7) so gru phase0 can use kc0=1.
__global__ void agg1_kernel(const int* __restrict__ off, const int* __restrict__ csrc,
                            const float* __restrict__ cw, const float4* __restrict__ h4,
                            float4* __restrict__ dst4) {
    int gid  = blockIdx.x * blockDim.x + threadIdx.x;
    int node = gid >> 5;
    int lane = gid & 31;
    if (node >= N_NODES) return;
    int e0 = __ldg(off + node), e1 = __ldg(off + node + 1);
    float4 a0 = make_float4(0.f, 0.f, 0.f, 0.f);
    float  a4 = 0.f;   // col 4 (cols 5..7 are zero)
    for (int e = e0 + lane; e < e1; e += 32) {
        int   s = __ldg(csrc + e);
        float w = __ldg(cw + e);
        float4 v0 = __ldg(h4 + (size_t)s * 32);
        float  v4 = __ldg(reinterpret_cast<const float*>(h4 + (size_t)s * 32 + 1));
        a0.x += w * v0.x; a0.y += w * v0.y; a0.z += w * v0.z; a0.w += w * v0.w;
        a4   += w * v4;
    }
    #pragma unroll
    for (int o = 16; o; o >>= 1) {
        a0.x += __shfl_xor_sync(0xffffffffu, a0.x, o);
        a0.y += __shfl_xor_sync(0xffffffffu, a0.y, o);
        a0.z += __shfl_xor_sync(0xffffffffu, a0.z, o);
        a0.w += __shfl_xor_sync(0xffffffffu, a0.w, o);
        a4   += __shfl_xor_sync(0xffffffffu, a4, o);
    }
    float4* drow = dst4 + (size_t)node * 32;
    if (lane == 0) {
        drow[0] = a0;
        drow[1] = make_float4(a4, 0.f, 0.f, 0.f);
    } else if (lane >= 2 && lane < 16) {
        drow[lane] = make_float4(0.f, 0.f, 0.f, 0.f);
    }
}

// ---------------- tf32 GEMM (used only for tiny Qt = W_ih @ Wg^T precompute) ----------------
#define AS_STR 132
#define BS_STR 136
#define GEMM_SMEM ((128 * AS_STR + 128 * BS_STR) * 4)

__global__ void gemm_tf32(const float* __restrict__ A, const float* __restrict__ Bsrc,
                          float* __restrict__ C, int Nc) {
    extern __shared__ unsigned int sm[];
    unsigned int* As = sm;
    unsigned int* Bs = sm + 128 * AS_STR;

    int t  = threadIdx.x;
    int rb = blockIdx.x * 128;
    int cb = blockIdx.y * 128;

    {
        const float4* A4 = reinterpret_cast<const float4*>(A) + (size_t)rb * 32;
        #pragma unroll
        for (int i = t; i < 128 * 32; i += 256) {
            int r = i >> 5, k4 = i & 31;
            float4 v = A4[r * 32 + k4];
            uint4 u = make_uint4(f2tf(v.x), f2tf(v.y), f2tf(v.z), f2tf(v.w));
            *reinterpret_cast<uint4*>(&As[r * AS_STR + k4 * 4]) = u;
        }
    }
    {
        const float4* B4 = reinterpret_cast<const float4*>(Bsrc) + (size_t)cb * 32;
        #pragma unroll
        for (int i = t; i < 128 * 32; i += 256) {
            int n = i >> 5, k4 = i & 31;
            float4 v = B4[n * 32 + k4];
            uint4 u = make_uint4(f2tf(v.x), f2tf(v.y), f2tf(v.z), f2tf(v.w));
            *reinterpret_cast<uint4*>(&Bs[n * BS_STR + k4 * 4]) = u;
        }
    }
    __syncthreads();

    int warp = t >> 5, lane = t & 31;
    int wm = (warp >> 2) * 64;
    int wn = (warp & 3) * 32;
    int lr = lane >> 2, lc = lane & 3;

    float acc[4][4][4];
    #pragma unroll
    for (int mt = 0; mt < 4; mt++)
        #pragma unroll
        for (int nt = 0; nt < 4; nt++)
            #pragma unroll
            for (int q = 0; q < 4; q++) acc[mt][nt][q] = 0.f;

    #pragma unroll
    for (int kk = 0; kk < 16; kk++) {
        int k0 = kk * 8 + lc;
        unsigned int a[4][4], b[4][2];
        #pragma unroll
        for (int mt = 0; mt < 4; mt++) {
            int r = wm + mt * 16 + lr;
            a[mt][0] = As[r * AS_STR + k0];
            a[mt][1] = As[(r + 8) * AS_STR + k0];
            a[mt][2] = As[r * AS_STR + k0 + 4];
            a[mt][3] = As[(r + 8) * AS_STR + k0 + 4];
        }
        #pragma unroll
        for (int nt = 0; nt < 4; nt++) {
            int n = wn + nt * 8 + lr;
            b[nt][0] = Bs[n * BS_STR + k0];
            b[nt][1] = Bs[n * BS_STR + k0 + 4];
        }
        #pragma unroll
        for (int mt = 0; mt < 4; mt++)
            #pragma unroll
            for (int nt = 0; nt < 4; nt++)
                mma_tf32(acc[mt][nt], a[mt], b[nt]);
    }

    #pragma unroll
    for (int nt = 0; nt < 4; nt++) {
        int c = cb + wn + nt * 8 + lc * 2;
        #pragma unroll
        for (int mt = 0; mt < 4; mt++) {
            int r = rb + wm + mt * 16 + lr;
            float2 v0 = make_float2(acc[mt][nt][0], acc[mt][nt][1]);
            float2 v1 = make_float2(acc[mt][nt][2], acc[mt][nt][3]);
            *reinterpret_cast<float2*>(&C[(size_t)r * Nc + c])       = v0;
            *reinterpret_cast<float2*>(&C[(size_t)(r + 8) * Nc + c]) = v1;
        }
    }
}

// ---------------- fused GRU: gi-GEMM + gh-GEMM + GRU update ----------------
// Phase 0: acc = A0 @ W0^T (W0 = Qt, combined weights), stash to smem.
// Phase 1: acc = h @ w_hh^T; epilogue does full GRU, writes h in place.
// kc0 = number of 64-wide K chunks for phase 0 (1 for layer 1, 2 for layer 2).
#define FAS_STR 68
#define FBS_STR 68
#define GI_STR  388
#define FUSED_SMEM ((64 * FAS_STR + 384 * FBS_STR + 64 * GI_STR) * 4)

__global__ void __launch_bounds__(512, 1)
gru_fused(const float* __restrict__ agg, float* __restrict__ h,
          const float* __restrict__ w0, const float* __restrict__ w_hh,
          const float* __restrict__ b_ih, const float* __restrict__ b_hh,
          int kc0) {
    extern __shared__ unsigned int sm[];
    unsigned int* As = sm;                         // [64][FAS_STR]
    unsigned int* Bs = sm + 64 * FAS_STR;          // [384][FBS_STR]
    float* sgi = reinterpret_cast<float*>(sm + 64 * FAS_STR + 384 * FBS_STR); // [64][GI_STR]

    int t = threadIdx.x;
    int rb = blockIdx.x * 64;
    int warp = t >> 5, lane = t & 31;
    int wr = warp & 1;
    int wc = warp >> 1;
    int lr = lane >> 2, lc = lane & 3;

    float acc[2][3][2][4];

    #pragma unroll
    for (int phase = 0; phase < 2; phase++) {
        const float* A = phase ? h    : agg;
        const float* W = phase ? w_hh : w0;
        int nkc = phase ? 2 : kc0;

        #pragma unroll
        for (int mt = 0; mt < 2; mt++)
            #pragma unroll
            for (int g = 0; g < 3; g++)
                #pragma unroll
                for (int nt = 0; nt < 2; nt++)
                    #pragma unroll
                    for (int q = 0; q < 4; q++) acc[mt][g][nt][q] = 0.f;

        for (int kc = 0; kc < nkc; kc++) {
            __syncthreads();
            #pragma unroll
            for (int i = t; i < 64 * 16; i += 512) {
                int r = i >> 4, k4 = i & 15;
                float4 v = *reinterpret_cast<const float4*>(
                    &A[(size_t)(rb + r) * 128 + kc * 64 + k4 * 4]);
                uint4 u = make_uint4(f2tf(v.x), f2tf(v.y), f2tf(v.z), f2tf(v.w));
                *reinterpret_cast<uint4*>(&As[r * FAS_STR + k4 * 4]) = u;
            }
            #pragma unroll
            for (int i = t; i < 384 * 16; i += 512) {
                int n = i >> 4, k4 = i & 15;
                float4 v = *reinterpret_cast<const float4*>(
                    &W[(size_t)n * 128 + kc * 64 + k4 * 4]);
                uint4 u = make_uint4(f2tf(v.x), f2tf(v.y), f2tf(v.z), f2tf(v.w));
                *reinterpret_cast<uint4*>(&Bs[n * FBS_STR + k4 * 4]) = u;
            }
            __syncthreads();

            #pragma unroll
            for (int ks = 0; ks < 8; ks++) {
                int k0 = ks * 8 + lc;
                unsigned int a[2][4], b[3][2][2];
                #pragma unroll
                for (int mt = 0; mt < 2; mt++) {
                    int r = wr * 32 + mt * 16 + lr;
                    a[mt][0] = As[r * FAS_STR + k0];
                    a[mt][1] = As[(r + 8) * FAS_STR + k0];
                    a[mt][2] = As[r * FAS_STR + k0 + 4];
                    a[mt][3] = As[(r + 8) * FAS_STR + k0 + 4];
                }
                #pragma unroll
                for (int g = 0; g < 3; g++)
                    #pragma unroll
                    for (int nt = 0; nt < 2; nt++) {
                        int n = g * 128 + wc * 16 + nt * 8 + lr;
                        b[g][nt][0] = Bs[n * FBS_STR + k0];
                        b[g][nt][1] = Bs[n * FBS_STR + k0 + 4];
                    }
                #pragma unroll
                for (int mt = 0; mt < 2; mt++)
                    #pragma unroll
                    for (int g = 0; g < 3; g++)
                        #pragma unroll
                        for (int nt = 0; nt < 2; nt++)
                            mma_tf32(acc[mt][g][nt], a[mt], b[g][nt]);
            }
        }

        if (phase == 0) {
            #pragma unroll
            for (int mt = 0; mt < 2; mt++)
                #pragma unroll
                for (int g = 0; g < 3; g++)
                    #pragma unroll
                    for (int nt = 0; nt < 2; nt++) {
                        int row = wr * 32 + mt * 16 + lr;
                        int c = g * 128 + wc * 16 + nt * 8 + lc * 2;
                        *reinterpret_cast<float2*>(&sgi[row * GI_STR + c]) =
                            make_float2(acc[mt][g][nt][0], acc[mt][g][nt][1]);
                        *reinterpret_cast<float2*>(&sgi[(row + 8) * GI_STR + c]) =
                            make_float2(acc[mt][g][nt][2], acc[mt][g][nt][3]);
                    }
        }
    }

    // GRU epilogue
    #pragma unroll
    for (int nt = 0; nt < 2; nt++) {
        int c = wc * 16 + nt * 8 + lc * 2;
        float bir0 = __ldg(b_ih + c),       bir1 = __ldg(b_ih + c + 1);
        float biz0 = __ldg(b_ih + 128 + c), biz1 = __ldg(b_ih + 128 + c + 1);
        float bin0 = __ldg(b_ih + 256 + c), bin1 = __ldg(b_ih + 256 + c + 1);
        float bhr0 = __ldg(b_hh + c),       bhr1 = __ldg(b_hh + c + 1);
        float bhz0 = __ldg(b_hh + 128 + c), bhz1 = __ldg(b_hh + 128 + c + 1);
        float bhn0 = __ldg(b_hh + 256 + c), bhn1 = __ldg(b_hh + 256 + c + 1);
        #pragma unroll
        for (int mt = 0; mt < 2; mt++) {
            #pragma unroll
            for (int half = 0; half < 2; half++) {
                int row = wr * 32 + mt * 16 + lr + half * 8;
                int q0 = half * 2;
                float2 gir = *reinterpret_cast<float2*>(&sgi[row * GI_STR + c]);
                float2 giz = *reinterpret_cast<float2*>(&sgi[row * GI_STR + 128 + c]);
                float2 gin = *reinterpret_cast<float2*>(&sgi[row * GI_STR + 256 + c]);
                float ghr0 = acc[mt][0][nt][q0], ghr1 = acc[mt][0][nt][q0 + 1];
                float ghz0 = acc[mt][1][nt][q0], ghz1 = acc[mt][1][nt][q0 + 1];
                float ghn0 = acc[mt][2][nt][q0], ghn1 = acc[mt][2][nt][q0 + 1];
                float2 hold = *reinterpret_cast<float2*>(&h[(size_t)(rb + row) * 128 + c]);
                float r0 = 1.f / (1.f + __expf(-(gir.x + ghr0 + bir0 + bhr0)));
                float z0 = 1.f / (1.f + __expf(-(giz.x + ghz0 + biz0 + bhz0)));
                float n0 = tanhf(gin.x + bin0 + r0 * (ghn0 + bhn0));
                float r1 = 1.f / (1.f + __expf(-(gir.y + ghr1 + bir1 + bhr1)));
                float z1 = 1.f / (1.f + __expf(-(giz.y + ghz1 + biz1 + bhz1)));
                float n1 = tanhf(gin.y + bin1 + r1 * (ghn1 + bhn1));
                float2 hnew = make_float2((1.f - z0) * n0 + z0 * hold.x,
                                          (1.f - z1) * n1 + z1 * hold.y);
                *reinterpret_cast<float2*>(&h[(size_t)(rb + row) * 128 + c]) = hnew;
            }
        }
    }
}

// ---------------- post ----------------
__global__ void post_kernel(const float* __restrict__ h,
                            const float* __restrict__ conv_w, const float* __restrict__ conv_b,
                            const float* __restrict__ lin1_w, const float* __restrict__ lin1_b,
                            const float* __restrict__ lin2_w, const float* __restrict__ lin2_b,
                            float* __restrict__ out) {
    int b = blockIdx.x;
    int t = threadIdx.x;
    __shared__ float cw[48];
    __shared__ float v[ELEC * LCONV];
    __shared__ float u[HDIM];

    if (t < 48) cw[t] = conv_w[t];
    __syncthreads();
    float cb0 = conv_b[0];

    for (int idx = t; idx < ELEC * LCONV; idx += 256) {
        int e = idx / LCONV, l = idx % LCONV;
        float s = cb0;
        #pragma unroll
        for (int g = 0; g < N_GRAPH; g++) {
            const float* hr = h + ((size_t)((b * N_GRAPH + g) * ELEC + e)) * HDIM + 2 * l;
            s += cw[g * 3 + 0] * fmaxf(hr[0], 0.f)
               + cw[g * 3 + 1] * fmaxf(hr[1], 0.f)
               + cw[g * 3 + 2] * fmaxf(hr[2], 0.f);
        }
        v[idx] = fmaxf(s, 0.f);
    }
    __syncthreads();

    int w = t >> 5, lane = t & 31;
    for (int j = w; j < HDIM; j += 8) {
        float s = 0.f;
        for (int f = lane * 4; f < ELEC * LCONV; f += 128) {
            float4 wv = *reinterpret_cast<const float4*>(&lin1_w[(size_t)j * 2016 + f]);
            float4 vv = *reinterpret_cast<const float4*>(&v[f]);
            s += wv.x * vv.x + wv.y * vv.y + wv.z * vv.z + wv.w * vv.w;
        }
        #pragma unroll
        for (int o = 16; o; o >>= 1) s += __shfl_xor_sync(0xffffffffu, s, o);
        if (lane == 0) u[j] = fmaxf(s + lin1_b[j], 0.f);
    }
    __syncthreads();

    if (t < 32) {
        float s3[3];
        #pragma unroll
        for (int j = 0; j < 3; j++) {
            float acc = 0.f;
            for (int f = t; f < HDIM; f += 32) acc += lin2_w[j * HDIM + f] * u[f];
            #pragma unroll
            for (int o = 16; o; o >>= 1) acc += __shfl_xor_sync(0xffffffffu, acc, o);
            s3[j] = acc + lin2_b[j];
        }
        if (t == 0) {
            float mx = fmaxf(s3[0], fmaxf(s3[1], s3[2]));
            float e0 = expf(s3[0] - mx), e1 = expf(s3[1] - mx), e2 = expf(s3[2] - mx);
            float inv = 1.f / (e0 + e1 + e2);
            out[b * 3 + 0] = e0 * inv;
            out[b * 3 + 1] = e1 * inv;
            out[b * 3 + 2] = e2 * inv;
        }
    }
}

// ---------------- launch ----------------
extern "C" void kernel_launch(void* const* d_in, const int* in_sizes, int n_in,
                              void* d_out, int out_size) {
    const float* x       = (const float*)d_in[0];
    const int*   ei      = (const int*)  d_in[1];
    const float* ea      = (const float*)d_in[2];
    const float* gconv_w = (const float*)d_in[4];
    const float* w_ih    = (const float*)d_in[5];
    const float* w_hh    = (const float*)d_in[6];
    const float* b_ih    = (const float*)d_in[7];
    const float* b_hh    = (const float*)d_in[8];
    const float* conv_w  = (const float*)d_in[9];
    const float* conv_b  = (const float*)d_in[10];
    const float* lin1_w  = (const float*)d_in[11];
    const float* lin1_b  = (const float*)d_in[12];
    const float* lin2_w  = (const float*)d_in[13];
    const float* lin2_b  = (const float*)d_in[14];
    float* out = (float*)d_out;

    float *ph, *pagg, *pqt, *pcw;
    int *pdeg, *poff, *pcur, *pcsrc;
    cudaGetSymbolAddress((void**)&ph,    g_h);
    cudaGetSymbolAddress((void**)&pagg,  g_agg);
    cudaGetSymbolAddress((void**)&pqt,   g_qt);
    cudaGetSymbolAddress((void**)&pdeg,  g_deg);
    cudaGetSymbolAddress((void**)&poff,  g_off);
    cudaGetSymbolAddress((void**)&pcur,  g_cur);
    cudaGetSymbolAddress((void**)&pcsrc, g_csrc);
    cudaGetSymbolAddress((void**)&pcw,   g_cw);

    cudaFuncSetAttribute(gemm_tf32, cudaFuncAttributeMaxDynamicSharedMemorySize, GEMM_SMEM);
    cudaFuncSetAttribute(gru_fused, cudaFuncAttributeMaxDynamicSharedMemorySize, FUSED_SMEM);

    // Qt[l] = W_ih @ Wg_l^T  ([384][128] K-major) — combined gconv+gi weights
    gemm_tf32<<<dim3(3, 1), 256, GEMM_SMEM>>>(w_ih, gconv_w,         pqt,          HDIM);
    gemm_tf32<<<dim3(3, 1), 256, GEMM_SMEM>>>(w_ih, gconv_w + 16384, pqt + 49152,  HDIM);

    pad_kernel<<<(N_NODES * 32 + 255) / 256, 256>>>(x, ph);
    // CSR build
    zero_kernel<<<(N_NODES / 4 + 255) / 256, 256>>>((float4*)pdeg, N_NODES / 4);
    count_kernel<<<N_EDGES / 256, 256>>>(ei, pdeg);
    scan_kernel<<<1, 1024>>>(pdeg, poff, pcur);
    fill_kernel<<<N_EDGES / 256, 256>>>(ei, ea, pcur, pcsrc, pcw);

    // ---- layer 1: h cols 5..127 are zero -> narrow gather + kc0=1 ----
    agg1_kernel<<<N_NODES * 32 / 256, 256>>>(poff, pcsrc, pcw,
                                             (const float4*)ph, (float4*)pagg);
    gru_fused<<<N_NODES / 64, 512, FUSED_SMEM>>>(pagg, ph, pqt, w_hh, b_ih, b_hh, 1);

    // ---- layer 2: full gather ----
    agg_kernel<<<N_NODES * 32 / 256, 256>>>(poff, pcsrc, pcw,
                                            (const float4*)ph, (float4*)pagg);
    gru_fused<<<N_NODES / 64, 512, FUSED_SMEM>>>(pagg, ph, pqt + 49152, w_hh, b_ih, b_hh, 2);

    post_kernel<<<BSZ, 256>>>(ph, conv_w, conv_b, lin1_w, lin1_b, lin2_w, lin2_b, out);
}

// round 7
// speedup vs baseline: 1.4675x; 1.0139x over previous
#include <cuda_runtime.h>
#include <cuda_bf16.h>
#include <cuda_fp16.h>
#include <cstdint>

#define N_NODES 65536
#define N_EDGES 1048576
#define HDIM    128
#define IN_F    5
#define N_GRAPH 16
#define ELEC    32
#define BSZ     128
#define LCONV   63   // (128-3)/2+1

// ---------------- device scratch (no allocations allowed) ----------------
__device__ float g_h  [N_NODES * HDIM];     // 32 MB
__device__ float g_agg[N_NODES * HDIM];     // 32 MB
__device__ float g_qt [2 * 384 * HDIM];     // combined W_ih@Wg^T per layer, [384][128] K-major
// CSR scratch
__device__ int   g_deg [N_NODES];
__device__ int   g_off [N_NODES + 1];
__device__ int   g_cur [N_NODES];
__device__ int   g_csrc[N_EDGES];
__device__ float g_cw  [N_EDGES];

// ---------------- helpers ----------------
__device__ __forceinline__ unsigned int f2tf(float f) {
    unsigned int u; asm("cvt.rna.tf32.f32 %0, %1;" : "=r"(u) : "f"(f)); return u;
}

__device__ __forceinline__ void mma_tf32(float* c, const unsigned int* a, const unsigned int* b) {
    asm("mma.sync.aligned.m16n8k8.row.col.f32.tf32.tf32.f32 "
        "{%0,%1,%2,%3},{%4,%5,%6,%7},{%8,%9},{%0,%1,%2,%3};"
        : "+f"(c[0]), "+f"(c[1]), "+f"(c[2]), "+f"(c[3])
        : "r"(a[0]), "r"(a[1]), "r"(a[2]), "r"(a[3]), "r"(b[0]), "r"(b[1]));
}

__device__ __forceinline__ void cp16(unsigned saddr, const void* gptr) {
    asm volatile("cp.async.cg.shared.global [%0], [%1], 16;" :: "r"(saddr), "l"(gptr));
}

__global__ void zero_kernel(float4* p, int n4) {
    int i = blockIdx.x * blockDim.x + threadIdx.x;
    if (i < n4) p[i] = make_float4(0.f, 0.f, 0.f, 0.f);
}

// h[:, 0:5] = x, rest 0
__global__ void pad_kernel(const float* __restrict__ x, float* __restrict__ h) {
    int i = blockIdx.x * blockDim.x + threadIdx.x;
    if (i >= N_NODES * 32) return;
    int n = i >> 5, c4 = i & 31;
    float4 v = make_float4(0.f, 0.f, 0.f, 0.f);
    if (c4 == 0) {
        const float* xr = x + n * IN_F;
        v.x = xr[0]; v.y = xr[1]; v.z = xr[2]; v.w = xr[3];
    } else if (c4 == 1) {
        v.x = x[n * IN_F + 4];
    }
    reinterpret_cast<float4*>(h)[i] = v;
}

// ---------------- CSR build ----------------
__global__ void count_kernel(const int* __restrict__ ei, int* __restrict__ deg) {
    int e = blockIdx.x * blockDim.x + threadIdx.x;
    if (e < N_EDGES) atomicAdd(&deg[ei[N_EDGES + e]], 1);
}

__global__ void scan_kernel(const int* __restrict__ deg, int* __restrict__ off,
                            int* __restrict__ cur) {
    __shared__ int ssum[1024];
    int t = threadIdx.x;
    int base = t * 64;
    int s = 0;
    #pragma unroll 8
    for (int i = 0; i < 64; i++) s += deg[base + i];
    int my = s;
    ssum[t] = s;
    __syncthreads();
    for (int o = 1; o < 1024; o <<= 1) {
        int v = (t >= o) ? ssum[t - o] : 0;
        __syncthreads();
        ssum[t] += v;
        __syncthreads();
    }
    int run = ssum[t] - my;
    for (int i = 0; i < 64; i++) {
        off[base + i] = run;
        cur[base + i] = run;
        run += deg[base + i];
    }
    if (t == 1023) off[N_NODES] = run;
}

__global__ void fill_kernel(const int* __restrict__ ei, const float* __restrict__ ea,
                            int* __restrict__ cur, int* __restrict__ csrc,
                            float* __restrict__ cw) {
    int e = blockIdx.x * blockDim.x + threadIdx.x;
    if (e >= N_EDGES) return;
    int d = ei[N_EDGES + e];
    int pos = atomicAdd(&cur[d], 1);
    csrc[pos] = ei[e];
    cw[pos]   = ea[e];
}

// ---------------- gather aggregation (full 128 cols, layer 2) ----------------
__global__ void agg_kernel(const int* __restrict__ off, const int* __restrict__ csrc,
                           const float* __restrict__ cw, const float4* __restrict__ src4,
                           float4* __restrict__ dst4) {
    int gid  = blockIdx.x * blockDim.x + threadIdx.x;
    int node = gid >> 5;
    int lane = gid & 31;
    if (node >= N_NODES) return;
    int e0 = __ldg(off + node), e1 = __ldg(off + node + 1);
    float4 acc0 = make_float4(0.f, 0.f, 0.f, 0.f);
    float4 acc1 = make_float4(0.f, 0.f, 0.f, 0.f);
    int e = e0;
    for (; e + 1 < e1; e += 2) {
        int   sA = __ldg(csrc + e),     sB = __ldg(csrc + e + 1);
        float wA = __ldg(cw + e),       wB = __ldg(cw + e + 1);
        float4 vA = __ldg(src4 + (size_t)sA * 32 + lane);
        float4 vB = __ldg(src4 + (size_t)sB * 32 + lane);
        acc0.x += wA * vA.x; acc0.y += wA * vA.y; acc0.z += wA * vA.z; acc0.w += wA * vA.w;
        acc1.x += wB * vB.x; acc1.y += wB * vB.y; acc1.z += wB * vB.z; acc1.w += wB * vB.w;
    }
    if (e < e1) {
        int   sA = __ldg(csrc + e);
        float wA = __ldg(cw + e);
        float4 vA = __ldg(src4 + (size_t)sA * 32 + lane);
        acc0.x += wA * vA.x; acc0.y += wA * vA.y; acc0.z += wA * vA.z; acc0.w += wA * vA.w;
    }
    acc0.x += acc1.x; acc0.y += acc1.y; acc0.z += acc1.z; acc0.w += acc1.w;
    dst4[(size_t)node * 32 + lane] = acc0;
}

// ---------------- layer-1 aggregation: h has only cols 0..4 nonzero ----------------
__global__ void agg1_kernel(const int* __restrict__ off, const int* __restrict__ csrc,
                            const float* __restrict__ cw, const float4* __restrict__ h4,
                            float4* __restrict__ dst4) {
    int gid  = blockIdx.x * blockDim.x + threadIdx.x;
    int node = gid >> 5;
    int lane = gid & 31;
    if (node >= N_NODES) return;
    int e0 = __ldg(off + node), e1 = __ldg(off + node + 1);
    float4 a0 = make_float4(0.f, 0.f, 0.f, 0.f);
    float  a4 = 0.f;
    for (int e = e0 + lane; e < e1; e += 32) {
        int   s = __ldg(csrc + e);
        float w = __ldg(cw + e);
        float4 v0 = __ldg(h4 + (size_t)s * 32);
        float  v4 = __ldg(reinterpret_cast<const float*>(h4 + (size_t)s * 32 + 1));
        a0.x += w * v0.x; a0.y += w * v0.y; a0.z += w * v0.z; a0.w += w * v0.w;
        a4   += w * v4;
    }
    #pragma unroll
    for (int o = 16; o; o >>= 1) {
        a0.x += __shfl_xor_sync(0xffffffffu, a0.x, o);
        a0.y += __shfl_xor_sync(0xffffffffu, a0.y, o);
        a0.z += __shfl_xor_sync(0xffffffffu, a0.z, o);
        a0.w += __shfl_xor_sync(0xffffffffu, a0.w, o);
        a4   += __shfl_xor_sync(0xffffffffu, a4, o);
    }
    float4* drow = dst4 + (size_t)node * 32;
    if (lane == 0) {
        drow[0] = a0;
        drow[1] = make_float4(a4, 0.f, 0.f, 0.f);
    } else if (lane >= 2 && lane < 16) {
        drow[lane] = make_float4(0.f, 0.f, 0.f, 0.f);
    }
}

// ---------------- tf32 GEMM (only for tiny Qt = W_ih @ Wg^T precompute) ----------------
#define AS_STR 132
#define BS_STR 136
#define GEMM_SMEM ((128 * AS_STR + 128 * BS_STR) * 4)

__global__ void gemm_tf32(const float* __restrict__ A, const float* __restrict__ Bsrc,
                          float* __restrict__ C, int Nc) {
    extern __shared__ unsigned int sm[];
    unsigned int* As = sm;
    unsigned int* Bs = sm + 128 * AS_STR;

    int t  = threadIdx.x;
    int rb = blockIdx.x * 128;
    int cb = blockIdx.y * 128;

    {
        const float4* A4 = reinterpret_cast<const float4*>(A) + (size_t)rb * 32;
        #pragma unroll
        for (int i = t; i < 128 * 32; i += 256) {
            int r = i >> 5, k4 = i & 31;
            float4 v = A4[r * 32 + k4];
            uint4 u = make_uint4(f2tf(v.x), f2tf(v.y), f2tf(v.z), f2tf(v.w));
            *reinterpret_cast<uint4*>(&As[r * AS_STR + k4 * 4]) = u;
        }
    }
    {
        const float4* B4 = reinterpret_cast<const float4*>(Bsrc) + (size_t)cb * 32;
        #pragma unroll
        for (int i = t; i < 128 * 32; i += 256) {
            int n = i >> 5, k4 = i & 31;
            float4 v = B4[n * 32 + k4];
            uint4 u = make_uint4(f2tf(v.x), f2tf(v.y), f2tf(v.z), f2tf(v.w));
            *reinterpret_cast<uint4*>(&Bs[n * BS_STR + k4 * 4]) = u;
        }
    }
    __syncthreads();

    int warp = t >> 5, lane = t & 31;
    int wm = (warp >> 2) * 64;
    int wn = (warp & 3) * 32;
    int lr = lane >> 2, lc = lane & 3;

    float acc[4][4][4];
    #pragma unroll
    for (int mt = 0; mt < 4; mt++)
        #pragma unroll
        for (int nt = 0; nt < 4; nt++)
            #pragma unroll
            for (int q = 0; q < 4; q++) acc[mt][nt][q] = 0.f;

    #pragma unroll
    for (int kk = 0; kk < 16; kk++) {
        int k0 = kk * 8 + lc;
        unsigned int a[4][4], b[4][2];
        #pragma unroll
        for (int mt = 0; mt < 4; mt++) {
            int r = wm + mt * 16 + lr;
            a[mt][0] = As[r * AS_STR + k0];
            a[mt][1] = As[(r + 8) * AS_STR + k0];
            a[mt][2] = As[r * AS_STR + k0 + 4];
            a[mt][3] = As[(r + 8) * AS_STR + k0 + 4];
        }
        #pragma unroll
        for (int nt = 0; nt < 4; nt++) {
            int n = wn + nt * 8 + lr;
            b[nt][0] = Bs[n * BS_STR + k0];
            b[nt][1] = Bs[n * BS_STR + k0 + 4];
        }
        #pragma unroll
        for (int mt = 0; mt < 4; mt++)
            #pragma unroll
            for (int nt = 0; nt < 4; nt++)
                mma_tf32(acc[mt][nt], a[mt], b[nt]);
    }

    #pragma unroll
    for (int nt = 0; nt < 4; nt++) {
        int c = cb + wn + nt * 8 + lc * 2;
        #pragma unroll
        for (int mt = 0; mt < 4; mt++) {
            int r = rb + wm + mt * 16 + lr;
            float2 v0 = make_float2(acc[mt][nt][0], acc[mt][nt][1]);
            float2 v1 = make_float2(acc[mt][nt][2], acc[mt][nt][3]);
            *reinterpret_cast<float2*>(&C[(size_t)r * Nc + c])       = v0;
            *reinterpret_cast<float2*>(&C[(size_t)(r + 8) * Nc + c]) = v1;
        }
    }
}

// ---------------- fused GRU: pipelined gi-GEMM + gh-GEMM + GRU update ----------------
// 64 rows/block, 512 threads (16 warps: 2 row x 8 col), warp tile 32 x 48 (3 gates x 16).
// Unified chunk sequence over both phases, K-chunk = 32, cp.async double-buffered.
// Raw fp32 fed as tf32 operands (HW ignores low mantissa bits). gi stash in fp16.
// smem: As[2][64][36] f32 (18432 B) | Bs[2][384][36] f32 (110592 B) | sgi[64][392] half (50176 B)
#define FA_STR 36
#define FB_STR 36
#define SGI_STR 392
#define OFF_BS  18432
#define OFF_SGI 129024
#define FUSED_SMEM (OFF_SGI + 64 * SGI_STR * 2)

__global__ void __launch_bounds__(512, 1)
gru_fused(const float* __restrict__ agg, float* __restrict__ h,
          const float* __restrict__ w0, const float* __restrict__ w_hh,
          const float* __restrict__ b_ih, const float* __restrict__ b_hh,
          int kc0) {
    extern __shared__ char smem[];
    unsigned sb = (unsigned)__cvta_generic_to_shared(smem);
    const unsigned* As = reinterpret_cast<const unsigned*>(smem);            // [2][64][36]
    const unsigned* Bs = reinterpret_cast<const unsigned*>(smem + OFF_BS);   // [2][384][36]
    __half* sgi = reinterpret_cast<__half*>(smem + OFF_SGI);                 // [64][392]

    int t = threadIdx.x;
    int rb = blockIdx.x * 64;
    int warp = t >> 5, lane = t & 31;
    int wr = warp & 1;
    int wc = warp >> 1;
    int lr = lane >> 2, lc = lane & 3;

    int nch0  = kc0 * 2;      // chunks in phase 0
    int total = nch0 + 4;

    // thread-constant load indices
    int la_r = t >> 3, la_k = (t & 7) * 4;        // A: 1 float4/thread

    auto load_chunk = [&](int j, int buf) {
        const float* A; const float* W; int kcol;
        if (j < nch0) { A = agg; W = w0;   kcol = j * 32; }
        else          { A = h;   W = w_hh; kcol = (j - nch0) * 32; }
        cp16(sb + (unsigned)(buf * (64 * FA_STR) + la_r * FA_STR + la_k) * 4,
             &A[(size_t)(rb + la_r) * 128 + kcol + la_k]);
        #pragma unroll
        for (int i = 0; i < 6; i++) {
            int idx = t + i * 512;
            int n = idx >> 3, k4 = (idx & 7) * 4;
            cp16(sb + OFF_BS + (unsigned)(buf * (384 * FB_STR) + n * FB_STR + k4) * 4,
                 &W[(size_t)n * 128 + kcol + k4]);
        }
        asm volatile("cp.async.commit_group;");
    };

    load_chunk(0, 0);
    load_chunk(1, 1);

    float acc[2][3][2][4];

    for (int j = 0; j < total; j++) {
        int buf = j & 1;
        if (j == 0 || j == nch0) {
            #pragma unroll
            for (int mt = 0; mt < 2; mt++)
                #pragma unroll
                for (int g = 0; g < 3; g++)
                    #pragma unroll
                    for (int nt = 0; nt < 2; nt++)
                        #pragma unroll
                        for (int q = 0; q < 4; q++) acc[mt][g][nt][q] = 0.f;
        }
        if (j + 1 < total) asm volatile("cp.async.wait_group 1;");
        else               asm volatile("cp.async.wait_group 0;");
        __syncthreads();

        const unsigned* Ab = As + buf * (64 * FA_STR);
        const unsigned* Bb = Bs + buf * (384 * FB_STR);
        #pragma unroll
        for (int ks = 0; ks < 4; ks++) {
            int k0 = ks * 8 + lc;
            unsigned a[2][4], b[3][2][2];
            #pragma unroll
            for (int mt = 0; mt < 2; mt++) {
                int r = wr * 32 + mt * 16 + lr;
                a[mt][0] = Ab[r * FA_STR + k0];
                a[mt][1] = Ab[(r + 8) * FA_STR + k0];
                a[mt][2] = Ab[r * FA_STR + k0 + 4];
                a[mt][3] = Ab[(r + 8) * FA_STR + k0 + 4];
            }
            #pragma unroll
            for (int g = 0; g < 3; g++)
                #pragma unroll
                for (int nt = 0; nt < 2; nt++) {
                    int n = g * 128 + wc * 16 + nt * 8 + lr;
                    b[g][nt][0] = Bb[n * FB_STR + k0];
                    b[g][nt][1] = Bb[n * FB_STR + k0 + 4];
                }
            #pragma unroll
            for (int mt = 0; mt < 2; mt++)
                #pragma unroll
                for (int g = 0; g < 3; g++)
                    #pragma unroll
                    for (int nt = 0; nt < 2; nt++)
                        mma_tf32(acc[mt][g][nt], a[mt], b[g][nt]);
        }
        __syncthreads();
        if (j + 2 < total) load_chunk(j + 2, buf);

        if (j == nch0 - 1) {
            // stash gi fragments as fp16 (thread-private positions, no barrier needed)
            #pragma unroll
            for (int mt = 0; mt < 2; mt++)
                #pragma unroll
                for (int g = 0; g < 3; g++)
                    #pragma unroll
                    for (int nt = 0; nt < 2; nt++) {
                        int row = wr * 32 + mt * 16 + lr;
                        int c = g * 128 + wc * 16 + nt * 8 + lc * 2;
                        *reinterpret_cast<__half2*>(&sgi[row * SGI_STR + c]) =
                            __floats2half2_rn(acc[mt][g][nt][0], acc[mt][g][nt][1]);
                        *reinterpret_cast<__half2*>(&sgi[(row + 8) * SGI_STR + c]) =
                            __floats2half2_rn(acc[mt][g][nt][2], acc[mt][g][nt][3]);
                    }
        }
    }

    // GRU epilogue: acc holds gh; sgi holds gi
    #pragma unroll
    for (int nt = 0; nt < 2; nt++) {
        int c = wc * 16 + nt * 8 + lc * 2;
        float bir0 = __ldg(b_ih + c),       bir1 = __ldg(b_ih + c + 1);
        float biz0 = __ldg(b_ih + 128 + c), biz1 = __ldg(b_ih + 128 + c + 1);
        float bin0 = __ldg(b_ih + 256 + c), bin1 = __ldg(b_ih + 256 + c + 1);
        float bhr0 = __ldg(b_hh + c),       bhr1 = __ldg(b_hh + c + 1);
        float bhz0 = __ldg(b_hh + 128 + c), bhz1 = __ldg(b_hh + 128 + c + 1);
        float bhn0 = __ldg(b_hh + 256 + c), bhn1 = __ldg(b_hh + 256 + c + 1);
        #pragma unroll
        for (int mt = 0; mt < 2; mt++) {
            #pragma unroll
            for (int half = 0; half < 2; half++) {
                int row = wr * 32 + mt * 16 + lr + half * 8;
                int q0 = half * 2;
                float2 gir = __half22float2(*reinterpret_cast<__half2*>(&sgi[row * SGI_STR + c]));
                float2 giz = __half22float2(*reinterpret_cast<__half2*>(&sgi[row * SGI_STR + 128 + c]));
                float2 gin = __half22float2(*reinterpret_cast<__half2*>(&sgi[row * SGI_STR + 256 + c]));
                float ghr0 = acc[mt][0][nt][q0], ghr1 = acc[mt][0][nt][q0 + 1];
                float ghz0 = acc[mt][1][nt][q0], ghz1 = acc[mt][1][nt][q0 + 1];
                float ghn0 = acc[mt][2][nt][q0], ghn1 = acc[mt][2][nt][q0 + 1];
                float2 hold = *reinterpret_cast<float2*>(&h[(size_t)(rb + row) * 128 + c]);
                float r0 = 1.f / (1.f + __expf(-(gir.x + ghr0 + bir0 + bhr0)));
                float z0 = 1.f / (1.f + __expf(-(giz.x + ghz0 + biz0 + bhz0)));
                float n0 = tanhf(gin.x + bin0 + r0 * (ghn0 + bhn0));
                float r1 = 1.f / (1.f + __expf(-(gir.y + ghr1 + bir1 + bhr1)));
                float z1 = 1.f / (1.f + __expf(-(giz.y + ghz1 + biz1 + bhz1)));
                float n1 = tanhf(gin.y + bin1 + r1 * (ghn1 + bhn1));
                float2 hnew = make_float2((1.f - z0) * n0 + z0 * hold.x,
                                          (1.f - z1) * n1 + z1 * hold.y);
                *reinterpret_cast<float2*>(&h[(size_t)(rb + row) * 128 + c]) = hnew;
            }
        }
    }
}

// ---------------- post ----------------
__global__ void post_kernel(const float* __restrict__ h,
                            const float* __restrict__ conv_w, const float* __restrict__ conv_b,
                            const float* __restrict__ lin1_w, const float* __restrict__ lin1_b,
                            const float* __restrict__ lin2_w, const float* __restrict__ lin2_b,
                            float* __restrict__ out) {
    int b = blockIdx.x;
    int t = threadIdx.x;
    __shared__ float cw[48];
    __shared__ float v[ELEC * LCONV];
    __shared__ float u[HDIM];

    if (t < 48) cw[t] = conv_w[t];
    __syncthreads();
    float cb0 = conv_b[0];

    for (int idx = t; idx < ELEC * LCONV; idx += 256) {
        int e = idx / LCONV, l = idx % LCONV;
        float s = cb0;
        #pragma unroll
        for (int g = 0; g < N_GRAPH; g++) {
            const float* hr = h + ((size_t)((b * N_GRAPH + g) * ELEC + e)) * HDIM + 2 * l;
            s += cw[g * 3 + 0] * fmaxf(hr[0], 0.f)
               + cw[g * 3 + 1] * fmaxf(hr[1], 0.f)
               + cw[g * 3 + 2] * fmaxf(hr[2], 0.f);
        }
        v[idx] = fmaxf(s, 0.f);
    }
    __syncthreads();

    int w = t >> 5, lane = t & 31;
    for (int j = w; j < HDIM; j += 8) {
        float s = 0.f;
        for (int f = lane * 4; f < ELEC * LCONV; f += 128) {
            float4 wv = *reinterpret_cast<const float4*>(&lin1_w[(size_t)j * 2016 + f]);
            float4 vv = *reinterpret_cast<const float4*>(&v[f]);
            s += wv.x * vv.x + wv.y * vv.y + wv.z * vv.z + wv.w * vv.w;
        }
        #pragma unroll
        for (int o = 16; o; o >>= 1) s += __shfl_xor_sync(0xffffffffu, s, o);
        if (lane == 0) u[j] = fmaxf(s + lin1_b[j], 0.f);
    }
    __syncthreads();

    if (t < 32) {
        float s3[3];
        #pragma unroll
        for (int j = 0; j < 3; j++) {
            float acc = 0.f;
            for (int f = t; f < HDIM; f += 32) acc += lin2_w[j * HDIM + f] * u[f];
            #pragma unroll
            for (int o = 16; o; o >>= 1) acc += __shfl_xor_sync(0xffffffffu, acc, o);
            s3[j] = acc + lin2_b[j];
        }
        if (t == 0) {
            float mx = fmaxf(s3[0], fmaxf(s3[1], s3[2]));
            float e0 = expf(s3[0] - mx), e1 = expf(s3[1] - mx), e2 = expf(s3[2] - mx);
            float inv = 1.f / (e0 + e1 + e2);
            out[b * 3 + 0] = e0 * inv;
            out[b * 3 + 1] = e1 * inv;
            out[b * 3 + 2] = e2 * inv;
        }
    }
}

// ---------------- launch ----------------
extern "C" void kernel_launch(void* const* d_in, const int* in_sizes, int n_in,
                              void* d_out, int out_size) {
    const float* x       = (const float*)d_in[0];
    const int*   ei      = (const int*)  d_in[1];
    const float* ea      = (const float*)d_in[2];
    const float* gconv_w = (const float*)d_in[4];
    const float* w_ih    = (const float*)d_in[5];
    const float* w_hh    = (const float*)d_in[6];
    const float* b_ih    = (const float*)d_in[7];
    const float* b_hh    = (const float*)d_in[8];
    const float* conv_w  = (const float*)d_in[9];
    const float* conv_b  = (const float*)d_in[10];
    const float* lin1_w  = (const float*)d_in[11];
    const float* lin1_b  = (const float*)d_in[12];
    const float* lin2_w  = (const float*)d_in[13];
    const float* lin2_b  = (const float*)d_in[14];
    float* out = (float*)d_out;

    float *ph, *pagg, *pqt, *pcw;
    int *pdeg, *poff, *pcur, *pcsrc;
    cudaGetSymbolAddress((void**)&ph,    g_h);
    cudaGetSymbolAddress((void**)&pagg,  g_agg);
    cudaGetSymbolAddress((void**)&pqt,   g_qt);
    cudaGetSymbolAddress((void**)&pdeg,  g_deg);
    cudaGetSymbolAddress((void**)&poff,  g_off);
    cudaGetSymbolAddress((void**)&pcur,  g_cur);
    cudaGetSymbolAddress((void**)&pcsrc, g_csrc);
    cudaGetSymbolAddress((void**)&pcw,   g_cw);

    cudaFuncSetAttribute(gemm_tf32, cudaFuncAttributeMaxDynamicSharedMemorySize, GEMM_SMEM);
    cudaFuncSetAttribute(gru_fused, cudaFuncAttributeMaxDynamicSharedMemorySize, FUSED_SMEM);

    // Qt[l] = W_ih @ Wg_l^T ([384][128] K-major)
    gemm_tf32<<<dim3(3, 1), 256, GEMM_SMEM>>>(w_ih, gconv_w,         pqt,         HDIM);
    gemm_tf32<<<dim3(3, 1), 256, GEMM_SMEM>>>(w_ih, gconv_w + 16384, pqt + 49152, HDIM);

    pad_kernel<<<(N_NODES * 32 + 255) / 256, 256>>>(x, ph);
    // CSR build
    zero_kernel<<<(N_NODES / 4 + 255) / 256, 256>>>((float4*)pdeg, N_NODES / 4);
    count_kernel<<<N_EDGES / 256, 256>>>(ei, pdeg);
    scan_kernel<<<1, 1024>>>(pdeg, poff, pcur);
    fill_kernel<<<N_EDGES / 256, 256>>>(ei, ea, pcur, pcsrc, pcw);

    // ---- layer 1 ----
    agg1_kernel<<<N_NODES * 32 / 256, 256>>>(poff, pcsrc, pcw,
                                             (const float4*)ph, (float4*)pagg);
    gru_fused<<<N_NODES / 64, 512, FUSED_SMEM>>>(pagg, ph, pqt, w_hh, b_ih, b_hh, 1);

    // ---- layer 2 ----
    agg_kernel<<<N_NODES * 32 / 256, 256>>>(poff, pcsrc, pcw,
                                            (const float4*)ph, (float4*)pagg);
    gru_fused<<<N_NODES / 64, 512, FUSED_SMEM>>>(pagg, ph, pqt + 49152, w_hh, b_ih, b_hh, 2);

    post_kernel<<<BSZ, 256>>>(ph, conv_w, conv_b, lin1_w, lin1_b, lin2_w, lin2_b, out);
}

// round 8
// speedup vs baseline: 1.7227x; 1.1739x over previous
#include <cuda_runtime.h>
#include <cuda_bf16.h>
#include <cuda_fp16.h>
#include <cstdint>

#define N_NODES 65536
#define N_EDGES 1048576
#define HDIM    128
#define IN_F    5
#define N_GRAPH 16
#define ELEC    32
#define BSZ     128
#define LCONV   63   // (128-3)/2+1

// ---------------- device scratch (no allocations allowed) ----------------
__device__ float           g_h   [N_NODES * HDIM];   // 32 MB fp32 h (hold path + post)
__device__ __nv_bfloat16   g_hb  [N_NODES * HDIM];   // 16 MB bf16 mirror of h
__device__ __nv_bfloat16   g_aggb[N_NODES * HDIM];   // 16 MB bf16 agg
__device__ float           g_qt  [2 * 384 * HDIM];   // fp32 Qt = W_ih @ Wg^T
__device__ __nv_bfloat16   g_qtb [2 * 384 * HDIM];   // bf16 Qt
__device__ __nv_bfloat16   g_whb [384 * HDIM];       // bf16 w_hh
// CSR scratch
__device__ int   g_deg [N_NODES];
__device__ int   g_off [N_NODES + 1];
__device__ int   g_cur [N_NODES];
__device__ int   g_csrc[N_EDGES];
__device__ float g_cw  [N_EDGES];

// ---------------- helpers ----------------
__device__ __forceinline__ unsigned int f2tf(float f) {
    unsigned int u; asm("cvt.rna.tf32.f32 %0, %1;" : "=r"(u) : "f"(f)); return u;
}

__device__ __forceinline__ void mma_tf32(float* c, const unsigned int* a, const unsigned int* b) {
    asm("mma.sync.aligned.m16n8k8.row.col.f32.tf32.tf32.f32 "
        "{%0,%1,%2,%3},{%4,%5,%6,%7},{%8,%9},{%0,%1,%2,%3};"
        : "+f"(c[0]), "+f"(c[1]), "+f"(c[2]), "+f"(c[3])
        : "r"(a[0]), "r"(a[1]), "r"(a[2]), "r"(a[3]), "r"(b[0]), "r"(b[1]));
}

__device__ __forceinline__ void mma_bf16(float* c, const unsigned int* a, const unsigned int* b) {
    asm("mma.sync.aligned.m16n8k16.row.col.f32.bf16.bf16.f32 "
        "{%0,%1,%2,%3},{%4,%5,%6,%7},{%8,%9},{%0,%1,%2,%3};"
        : "+f"(c[0]), "+f"(c[1]), "+f"(c[2]), "+f"(c[3])
        : "r"(a[0]), "r"(a[1]), "r"(a[2]), "r"(a[3]), "r"(b[0]), "r"(b[1]));
}

__device__ __forceinline__ void cp16(unsigned saddr, const void* gptr) {
    asm volatile("cp.async.cg.shared.global [%0], [%1], 16;" :: "r"(saddr), "l"(gptr));
}

__global__ void zero_kernel(float4* p, int n4) {
    int i = blockIdx.x * blockDim.x + threadIdx.x;
    if (i < n4) p[i] = make_float4(0.f, 0.f, 0.f, 0.f);
}

__global__ void cvt_bf16_kernel(const float* __restrict__ src, __nv_bfloat16* __restrict__ dst,
                                int n) {
    int i = blockIdx.x * blockDim.x + threadIdx.x;
    if (i < n) dst[i] = __float2bfloat16_rn(src[i]);
}

// h[:, 0:5] = x, rest 0; also bf16 mirror
__global__ void pad_kernel(const float* __restrict__ x, float* __restrict__ h,
                           __nv_bfloat16* __restrict__ hb) {
    int i = blockIdx.x * blockDim.x + threadIdx.x;
    if (i >= N_NODES * 32) return;
    int n = i >> 5, c4 = i & 31;
    float4 v = make_float4(0.f, 0.f, 0.f, 0.f);
    if (c4 == 0) {
        const float* xr = x + n * IN_F;
        v.x = xr[0]; v.y = xr[1]; v.z = xr[2]; v.w = xr[3];
    } else if (c4 == 1) {
        v.x = x[n * IN_F + 4];
    }
    reinterpret_cast<float4*>(h)[i] = v;
    __nv_bfloat162 p0 = __floats2bfloat162_rn(v.x, v.y);
    __nv_bfloat162 p1 = __floats2bfloat162_rn(v.z, v.w);
    uint2 u;
    u.x = *reinterpret_cast<unsigned*>(&p0);
    u.y = *reinterpret_cast<unsigned*>(&p1);
    reinterpret_cast<uint2*>(hb)[i] = u;
}

// ---------------- CSR build ----------------
__global__ void count_kernel(const int* __restrict__ ei, int* __restrict__ deg) {
    int e = blockIdx.x * blockDim.x + threadIdx.x;
    if (e < N_EDGES) atomicAdd(&deg[ei[N_EDGES + e]], 1);
}

__global__ void scan_kernel(const int* __restrict__ deg, int* __restrict__ off,
                            int* __restrict__ cur) {
    __shared__ int ssum[1024];
    int t = threadIdx.x;
    int base = t * 64;
    int s = 0;
    #pragma unroll 8
    for (int i = 0; i < 64; i++) s += deg[base + i];
    int my = s;
    ssum[t] = s;
    __syncthreads();
    for (int o = 1; o < 1024; o <<= 1) {
        int v = (t >= o) ? ssum[t - o] : 0;
        __syncthreads();
        ssum[t] += v;
        __syncthreads();
    }
    int run = ssum[t] - my;
    for (int i = 0; i < 64; i++) {
        off[base + i] = run;
        cur[base + i] = run;
        run += deg[base + i];
    }
    if (t == 1023) off[N_NODES] = run;
}

__global__ void fill_kernel(const int* __restrict__ ei, const float* __restrict__ ea,
                            int* __restrict__ cur, int* __restrict__ csrc,
                            float* __restrict__ cw) {
    int e = blockIdx.x * blockDim.x + threadIdx.x;
    if (e >= N_EDGES) return;
    int d = ei[N_EDGES + e];
    int pos = atomicAdd(&cur[d], 1);
    csrc[pos] = ei[e];
    cw[pos]   = ea[e];
}

// ---------------- layer-2 gather: bf16 in, bf16 out, fp32 accumulate ----------------
// warp per node; lane covers 4 cols (uint2 = 4 bf16). Row = 32 uint2.
__global__ void aggb_kernel(const int* __restrict__ off, const int* __restrict__ csrc,
                            const float* __restrict__ cw, const uint2* __restrict__ src,
                            uint2* __restrict__ dst) {
    int gid  = blockIdx.x * blockDim.x + threadIdx.x;
    int node = gid >> 5;
    int lane = gid & 31;
    if (node >= N_NODES) return;
    int e0 = __ldg(off + node), e1 = __ldg(off + node + 1);
    float4 acc = make_float4(0.f, 0.f, 0.f, 0.f);
    int e = e0;
    for (; e + 1 < e1; e += 2) {
        int   sA = __ldg(csrc + e),     sB = __ldg(csrc + e + 1);
        float wA = __ldg(cw + e),       wB = __ldg(cw + e + 1);
        uint2 vA = __ldg(src + (size_t)sA * 32 + lane);
        uint2 vB = __ldg(src + (size_t)sB * 32 + lane);
        float2 a0 = __bfloat1622float2(*reinterpret_cast<__nv_bfloat162*>(&vA.x));
        float2 a1 = __bfloat1622float2(*reinterpret_cast<__nv_bfloat162*>(&vA.y));
        float2 b0 = __bfloat1622float2(*reinterpret_cast<__nv_bfloat162*>(&vB.x));
        float2 b1 = __bfloat1622float2(*reinterpret_cast<__nv_bfloat162*>(&vB.y));
        acc.x += wA * a0.x + wB * b0.x;
        acc.y += wA * a0.y + wB * b0.y;
        acc.z += wA * a1.x + wB * b1.x;
        acc.w += wA * a1.y + wB * b1.y;
    }
    if (e < e1) {
        int   sA = __ldg(csrc + e);
        float wA = __ldg(cw + e);
        uint2 vA = __ldg(src + (size_t)sA * 32 + lane);
        float2 a0 = __bfloat1622float2(*reinterpret_cast<__nv_bfloat162*>(&vA.x));
        float2 a1 = __bfloat1622float2(*reinterpret_cast<__nv_bfloat162*>(&vA.y));
        acc.x += wA * a0.x; acc.y += wA * a0.y;
        acc.z += wA * a1.x; acc.w += wA * a1.y;
    }
    __nv_bfloat162 p0 = __floats2bfloat162_rn(acc.x, acc.y);
    __nv_bfloat162 p1 = __floats2bfloat162_rn(acc.z, acc.w);
    uint2 o;
    o.x = *reinterpret_cast<unsigned*>(&p0);
    o.y = *reinterpret_cast<unsigned*>(&p1);
    dst[(size_t)node * 32 + lane] = o;
}

// ---------------- layer-1 gather: fp32 h cols 0..4 -> bf16 agg cols 0..31 ----------------
__global__ void agg1b_kernel(const int* __restrict__ off, const int* __restrict__ csrc,
                             const float* __restrict__ cw, const float4* __restrict__ h4,
                             uint2* __restrict__ dst) {
    int gid  = blockIdx.x * blockDim.x + threadIdx.x;
    int node = gid >> 5;
    int lane = gid & 31;
    if (node >= N_NODES) return;
    int e0 = __ldg(off + node), e1 = __ldg(off + node + 1);
    float4 a0 = make_float4(0.f, 0.f, 0.f, 0.f);
    float  a4 = 0.f;
    for (int e = e0 + lane; e < e1; e += 32) {
        int   s = __ldg(csrc + e);
        float w = __ldg(cw + e);
        float4 v0 = __ldg(h4 + (size_t)s * 32);
        float  v4 = __ldg(reinterpret_cast<const float*>(h4 + (size_t)s * 32 + 1));
        a0.x += w * v0.x; a0.y += w * v0.y; a0.z += w * v0.z; a0.w += w * v0.w;
        a4   += w * v4;
    }
    #pragma unroll
    for (int o = 16; o; o >>= 1) {
        a0.x += __shfl_xor_sync(0xffffffffu, a0.x, o);
        a0.y += __shfl_xor_sync(0xffffffffu, a0.y, o);
        a0.z += __shfl_xor_sync(0xffffffffu, a0.z, o);
        a0.w += __shfl_xor_sync(0xffffffffu, a0.w, o);
        a4   += __shfl_xor_sync(0xffffffffu, a4, o);
    }
    // all lanes hold the full sums; lanes 0..7 write cols 0..31 (bf16)
    if (lane < 8) {
        uint2 o = make_uint2(0u, 0u);
        if (lane == 0) {
            __nv_bfloat162 p0 = __floats2bfloat162_rn(a0.x, a0.y);
            __nv_bfloat162 p1 = __floats2bfloat162_rn(a0.z, a0.w);
            o.x = *reinterpret_cast<unsigned*>(&p0);
            o.y = *reinterpret_cast<unsigned*>(&p1);
        } else if (lane == 1) {
            __nv_bfloat162 p0 = __floats2bfloat162_rn(a4, 0.f);
            o.x = *reinterpret_cast<unsigned*>(&p0);
        }
        dst[(size_t)node * 32 + lane] = o;
    }
}

// ---------------- tf32 GEMM (only for tiny Qt = W_ih @ Wg^T precompute) ----------------
#define AS_STR 132
#define BS_STR 136
#define GEMM_SMEM ((128 * AS_STR + 128 * BS_STR) * 4)

__global__ void gemm_tf32(const float* __restrict__ A, const float* __restrict__ Bsrc,
                          float* __restrict__ C, int Nc) {
    extern __shared__ unsigned int sm[];
    unsigned int* As = sm;
    unsigned int* Bs = sm + 128 * AS_STR;

    int t  = threadIdx.x;
    int rb = blockIdx.x * 128;
    int cb = blockIdx.y * 128;

    {
        const float4* A4 = reinterpret_cast<const float4*>(A) + (size_t)rb * 32;
        #pragma unroll
        for (int i = t; i < 128 * 32; i += 256) {
            int r = i >> 5, k4 = i & 31;
            float4 v = A4[r * 32 + k4];
            uint4 u = make_uint4(f2tf(v.x), f2tf(v.y), f2tf(v.z), f2tf(v.w));
            *reinterpret_cast<uint4*>(&As[r * AS_STR + k4 * 4]) = u;
        }
    }
    {
        const float4* B4 = reinterpret_cast<const float4*>(Bsrc) + (size_t)cb * 32;
        #pragma unroll
        for (int i = t; i < 128 * 32; i += 256) {
            int n = i >> 5, k4 = i & 31;
            float4 v = B4[n * 32 + k4];
            uint4 u = make_uint4(f2tf(v.x), f2tf(v.y), f2tf(v.z), f2tf(v.w));
            *reinterpret_cast<uint4*>(&Bs[n * BS_STR + k4 * 4]) = u;
        }
    }
    __syncthreads();

    int warp = t >> 5, lane = t & 31;
    int wm = (warp >> 2) * 64;
    int wn = (warp & 3) * 32;
    int lr = lane >> 2, lc = lane & 3;

    float acc[4][4][4];
    #pragma unroll
    for (int mt = 0; mt < 4; mt++)
        #pragma unroll
        for (int nt = 0; nt < 4; nt++)
            #pragma unroll
            for (int q = 0; q < 4; q++) acc[mt][nt][q] = 0.f;

    #pragma unroll
    for (int kk = 0; kk < 16; kk++) {
        int k0 = kk * 8 + lc;
        unsigned int a[4][4], b[4][2];
        #pragma unroll
        for (int mt = 0; mt < 4; mt++) {
            int r = wm + mt * 16 + lr;
            a[mt][0] = As[r * AS_STR + k0];
            a[mt][1] = As[(r + 8) * AS_STR + k0];
            a[mt][2] = As[r * AS_STR + k0 + 4];
            a[mt][3] = As[(r + 8) * AS_STR + k0 + 4];
        }
        #pragma unroll
        for (int nt = 0; nt < 4; nt++) {
            int n = wn + nt * 8 + lr;
            b[nt][0] = Bs[n * BS_STR + k0];
            b[nt][1] = Bs[n * BS_STR + k0 + 4];
        }
        #pragma unroll
        for (int mt = 0; mt < 4; mt++)
            #pragma unroll
            for (int nt = 0; nt < 4; nt++)
                mma_tf32(acc[mt][nt], a[mt], b[nt]);
    }

    #pragma unroll
    for (int nt = 0; nt < 4; nt++) {
        int c = cb + wn + nt * 8 + lc * 2;
        #pragma unroll
        for (int mt = 0; mt < 4; mt++) {
            int r = rb + wm + mt * 16 + lr;
            float2 v0 = make_float2(acc[mt][nt][0], acc[mt][nt][1]);
            float2 v1 = make_float2(acc[mt][nt][2], acc[mt][nt][3]);
            *reinterpret_cast<float2*>(&C[(size_t)r * Nc + c])       = v0;
            *reinterpret_cast<float2*>(&C[(size_t)(r + 8) * Nc + c]) = v1;
        }
    }
}

// ---------------- fused GRU (bf16 MMA): gi-GEMM + gh-GEMM + GRU update ----------------
// 64 rows/block, 512 threads (16 warps: 2 row x 8 col), warp tile 32 x 48.
// K-chunk = 32 (16 bf16x2 words/row), m16n8k16, cp.async double-buffered.
// gi stash lives in 24 half2 REGISTERS per thread (same thread owns same positions).
// smem words: A[2][64][20] | B[2][384][20]  -> 17920 words = 71,680 B
#define RA_STR 20
#define RB_STR 20
#define OFF_BW (2 * 64 * RA_STR)            // word offset of B region
#define FUSED_SMEM ((OFF_BW + 2 * 384 * RB_STR) * 4)

__global__ void __launch_bounds__(512, 1)
gru_fused(const __nv_bfloat16* __restrict__ aggb, float* __restrict__ h,
          __nv_bfloat16* __restrict__ hb,
          const __nv_bfloat16* __restrict__ w0b, const __nv_bfloat16* __restrict__ whb,
          const float* __restrict__ b_ih, const float* __restrict__ b_hh,
          int nch0) {
    extern __shared__ char smem[];
    unsigned sb = (unsigned)__cvta_generic_to_shared(smem);
    const unsigned* As = reinterpret_cast<const unsigned*>(smem);
    const unsigned* Bs = reinterpret_cast<const unsigned*>(smem) + OFF_BW;

    int t = threadIdx.x;
    int rb = blockIdx.x * 64;
    int warp = t >> 5, lane = t & 31;
    int wr = warp & 1;
    int wc = warp >> 1;
    int lr = lane >> 2, lc = lane & 3;

    int total = nch0 + 4;

    // loader indices: A 256 cp16s (t<256), B 1536 cp16s (3/thread)
    int la_r = t >> 2, la_k = t & 3;

    auto load_chunk = [&](int j, int buf) {
        const __nv_bfloat16* A; const __nv_bfloat16* W; int kcol;
        if (j < nch0) { A = aggb; W = w0b; kcol = j * 32; }
        else          { A = hb;   W = whb; kcol = (j - nch0) * 32; }
        if (t < 256)
            cp16(sb + (unsigned)(buf * (64 * RA_STR) + la_r * RA_STR + la_k * 4) * 4,
                 A + (size_t)(rb + la_r) * 128 + kcol + la_k * 8);
        #pragma unroll
        for (int i = 0; i < 3; i++) {
            int idx = t + i * 512;
            int n = idx >> 2, k16 = idx & 3;
            cp16(sb + (unsigned)(OFF_BW + buf * (384 * RB_STR) + n * RB_STR + k16 * 4) * 4,
                 W + (size_t)n * 128 + kcol + k16 * 8);
        }
        asm volatile("cp.async.commit_group;");
    };

    load_chunk(0, 0);
    load_chunk(1, 1);

    float acc[2][3][2][4];
    __half2 gi_st[2][3][2][2];

    for (int j = 0; j < total; j++) {
        int buf = j & 1;
        if (j == 0 || j == nch0) {
            #pragma unroll
            for (int mt = 0; mt < 2; mt++)
                #pragma unroll
                for (int g = 0; g < 3; g++)
                    #pragma unroll
                    for (int nt = 0; nt < 2; nt++)
                        #pragma unroll
                        for (int q = 0; q < 4; q++) acc[mt][g][nt][q] = 0.f;
        }
        if (j + 1 < total) asm volatile("cp.async.wait_group 1;");
        else               asm volatile("cp.async.wait_group 0;");
        __syncthreads();

        const unsigned* Ab = As + buf * (64 * RA_STR);
        const unsigned* Bb = Bs + buf * (384 * RB_STR);
        #pragma unroll
        for (int ks = 0; ks < 2; ks++) {       // 2 x K=16 per 32-chunk
            int k0 = ks * 8 + lc;
            unsigned a[2][4], b[3][2][2];
            #pragma unroll
            for (int mt = 0; mt < 2; mt++) {
                int r = wr * 32 + mt * 16 + lr;
                a[mt][0] = Ab[r * RA_STR + k0];
                a[mt][1] = Ab[(r + 8) * RA_STR + k0];
                a[mt][2] = Ab[r * RA_STR + k0 + 4];
                a[mt][3] = Ab[(r + 8) * RA_STR + k0 + 4];
            }
            #pragma unroll
            for (int g = 0; g < 3; g++)
                #pragma unroll
                for (int nt = 0; nt < 2; nt++) {
                    int n = g * 128 + wc * 16 + nt * 8 + lr;
                    b[g][nt][0] = Bb[n * RB_STR + k0];
                    b[g][nt][1] = Bb[n * RB_STR + k0 + 4];
                }
            #pragma unroll
            for (int mt = 0; mt < 2; mt++)
                #pragma unroll
                for (int g = 0; g < 3; g++)
                    #pragma unroll
                    for (int nt = 0; nt < 2; nt++)
                        mma_bf16(acc[mt][g][nt], a[mt], b[g][nt]);
        }
        __syncthreads();
        if (j + 2 < total) load_chunk(j + 2, buf);

        if (j == nch0 - 1) {
            // stash gi in fp16 registers
            #pragma unroll
            for (int mt = 0; mt < 2; mt++)
                #pragma unroll
                for (int g = 0; g < 3; g++)
                    #pragma unroll
                    for (int nt = 0; nt < 2; nt++) {
                        gi_st[mt][g][nt][0] = __floats2half2_rn(acc[mt][g][nt][0], acc[mt][g][nt][1]);
                        gi_st[mt][g][nt][1] = __floats2half2_rn(acc[mt][g][nt][2], acc[mt][g][nt][3]);
                    }
        }
    }

    // GRU epilogue: acc holds gh; gi_st holds gi
    #pragma unroll
    for (int nt = 0; nt < 2; nt++) {
        int c = wc * 16 + nt * 8 + lc * 2;
        float bir0 = __ldg(b_ih + c),       bir1 = __ldg(b_ih + c + 1);
        float biz0 = __ldg(b_ih + 128 + c), biz1 = __ldg(b_ih + 128 + c + 1);
        float bin0 = __ldg(b_ih + 256 + c), bin1 = __ldg(b_ih + 256 + c + 1);
        float bhr0 = __ldg(b_hh + c),       bhr1 = __ldg(b_hh + c + 1);
        float bhz0 = __ldg(b_hh + 128 + c), bhz1 = __ldg(b_hh + 128 + c + 1);
        float bhn0 = __ldg(b_hh + 256 + c), bhn1 = __ldg(b_hh + 256 + c + 1);
        #pragma unroll
        for (int mt = 0; mt < 2; mt++) {
            #pragma unroll
            for (int half = 0; half < 2; half++) {
                int row = wr * 32 + mt * 16 + lr + half * 8;
                int q0 = half * 2;
                float2 gir = __half22float2(gi_st[mt][0][nt][half]);
                float2 giz = __half22float2(gi_st[mt][1][nt][half]);
                float2 gin = __half22float2(gi_st[mt][2][nt][half]);
                float ghr0 = acc[mt][0][nt][q0], ghr1 = acc[mt][0][nt][q0 + 1];
                float ghz0 = acc[mt][1][nt][q0], ghz1 = acc[mt][1][nt][q0 + 1];
                float ghn0 = acc[mt][2][nt][q0], ghn1 = acc[mt][2][nt][q0 + 1];
                float2 hold = *reinterpret_cast<float2*>(&h[(size_t)(rb + row) * 128 + c]);
                float r0 = 1.f / (1.f + __expf(-(gir.x + ghr0 + bir0 + bhr0)));
                float z0 = 1.f / (1.f + __expf(-(giz.x + ghz0 + biz0 + bhz0)));
                float n0 = tanhf(gin.x + bin0 + r0 * (ghn0 + bhn0));
                float r1 = 1.f / (1.f + __expf(-(gir.y + ghr1 + bir1 + bhr1)));
                float z1 = 1.f / (1.f + __expf(-(giz.y + ghz1 + biz1 + bhz1)));
                float n1 = tanhf(gin.y + bin1 + r1 * (ghn1 + bhn1));
                float hx = (1.f - z0) * n0 + z0 * hold.x;
                float hy = (1.f - z1) * n1 + z1 * hold.y;
                *reinterpret_cast<float2*>(&h[(size_t)(rb + row) * 128 + c]) = make_float2(hx, hy);
                __nv_bfloat162 hp = __floats2bfloat162_rn(hx, hy);
                *reinterpret_cast<unsigned*>(&hb[(size_t)(rb + row) * 128 + c]) =
                    *reinterpret_cast<unsigned*>(&hp);
            }
        }
    }
}

// ---------------- post ----------------
__global__ void post_kernel(const float* __restrict__ h,
                            const float* __restrict__ conv_w, const float* __restrict__ conv_b,
                            const float* __restrict__ lin1_w, const float* __restrict__ lin1_b,
                            const float* __restrict__ lin2_w, const float* __restrict__ lin2_b,
                            float* __restrict__ out) {
    int b = blockIdx.x;
    int t = threadIdx.x;
    __shared__ float cw[48];
    __shared__ float v[ELEC * LCONV];
    __shared__ float u[HDIM];

    if (t < 48) cw[t] = conv_w[t];
    __syncthreads();
    float cb0 = conv_b[0];

    for (int idx = t; idx < ELEC * LCONV; idx += 256) {
        int e = idx / LCONV, l = idx % LCONV;
        float s = cb0;
        #pragma unroll
        for (int g = 0; g < N_GRAPH; g++) {
            const float* hr = h + ((size_t)((b * N_GRAPH + g) * ELEC + e)) * HDIM + 2 * l;
            s += cw[g * 3 + 0] * fmaxf(hr[0], 0.f)
               + cw[g * 3 + 1] * fmaxf(hr[1], 0.f)
               + cw[g * 3 + 2] * fmaxf(hr[2], 0.f);
        }
        v[idx] = fmaxf(s, 0.f);
    }
    __syncthreads();

    int w = t >> 5, lane = t & 31;
    for (int j = w; j < HDIM; j += 8) {
        float s = 0.f;
        for (int f = lane * 4; f < ELEC * LCONV; f += 128) {
            float4 wv = *reinterpret_cast<const float4*>(&lin1_w[(size_t)j * 2016 + f]);
            float4 vv = *reinterpret_cast<const float4*>(&v[f]);
            s += wv.x * vv.x + wv.y * vv.y + wv.z * vv.z + wv.w * vv.w;
        }
        #pragma unroll
        for (int o = 16; o; o >>= 1) s += __shfl_xor_sync(0xffffffffu, s, o);
        if (lane == 0) u[j] = fmaxf(s + lin1_b[j], 0.f);
    }
    __syncthreads();

    if (t < 32) {
        float s3[3];
        #pragma unroll
        for (int j = 0; j < 3; j++) {
            float acc = 0.f;
            for (int f = t; f < HDIM; f += 32) acc += lin2_w[j * HDIM + f] * u[f];
            #pragma unroll
            for (int o = 16; o; o >>= 1) acc += __shfl_xor_sync(0xffffffffu, acc, o);
            s3[j] = acc + lin2_b[j];
        }
        if (t == 0) {
            float mx = fmaxf(s3[0], fmaxf(s3[1], s3[2]));
            float e0 = expf(s3[0] - mx), e1 = expf(s3[1] - mx), e2 = expf(s3[2] - mx);
            float inv = 1.f / (e0 + e1 + e2);
            out[b * 3 + 0] = e0 * inv;
            out[b * 3 + 1] = e1 * inv;
            out[b * 3 + 2] = e2 * inv;
        }
    }
}

// ---------------- launch ----------------
extern "C" void kernel_launch(void* const* d_in, const int* in_sizes, int n_in,
                              void* d_out, int out_size) {
    const float* x       = (const float*)d_in[0];
    const int*   ei      = (const int*)  d_in[1];
    const float* ea      = (const float*)d_in[2];
    const float* gconv_w = (const float*)d_in[4];
    const float* w_ih    = (const float*)d_in[5];
    const float* w_hh    = (const float*)d_in[6];
    const float* b_ih    = (const float*)d_in[7];
    const float* b_hh    = (const float*)d_in[8];
    const float* conv_w  = (const float*)d_in[9];
    const float* conv_b  = (const float*)d_in[10];
    const float* lin1_w  = (const float*)d_in[11];
    const float* lin1_b  = (const float*)d_in[12];
    const float* lin2_w  = (const float*)d_in[13];
    const float* lin2_b  = (const float*)d_in[14];
    float* out = (float*)d_out;

    float *ph, *pqt, *pcw;
    __nv_bfloat16 *phb, *paggb, *pqtb, *pwhb;
    int *pdeg, *poff, *pcur, *pcsrc;
    cudaGetSymbolAddress((void**)&ph,    g_h);
    cudaGetSymbolAddress((void**)&phb,   g_hb);
    cudaGetSymbolAddress((void**)&paggb, g_aggb);
    cudaGetSymbolAddress((void**)&pqt,   g_qt);
    cudaGetSymbolAddress((void**)&pqtb,  g_qtb);
    cudaGetSymbolAddress((void**)&pwhb,  g_whb);
    cudaGetSymbolAddress((void**)&pdeg,  g_deg);
    cudaGetSymbolAddress((void**)&poff,  g_off);
    cudaGetSymbolAddress((void**)&pcur,  g_cur);
    cudaGetSymbolAddress((void**)&pcsrc, g_csrc);
    cudaGetSymbolAddress((void**)&pcw,   g_cw);

    cudaFuncSetAttribute(gemm_tf32, cudaFuncAttributeMaxDynamicSharedMemorySize, GEMM_SMEM);
    cudaFuncSetAttribute(gru_fused, cudaFuncAttributeMaxDynamicSharedMemorySize, FUSED_SMEM);

    // Qt[l] = W_ih @ Wg_l^T ([384][128] K-major), then convert weights to bf16
    gemm_tf32<<<dim3(3, 1), 256, GEMM_SMEM>>>(w_ih, gconv_w,         pqt,         HDIM);
    gemm_tf32<<<dim3(3, 1), 256, GEMM_SMEM>>>(w_ih, gconv_w + 16384, pqt + 49152, HDIM);
    cvt_bf16_kernel<<<(2 * 384 * HDIM + 255) / 256, 256>>>(pqt, pqtb, 2 * 384 * HDIM);
    cvt_bf16_kernel<<<(384 * HDIM + 255) / 256, 256>>>(w_hh, pwhb, 384 * HDIM);

    pad_kernel<<<(N_NODES * 32 + 255) / 256, 256>>>(x, ph, phb);
    // CSR build
    zero_kernel<<<(N_NODES / 4 + 255) / 256, 256>>>((float4*)pdeg, N_NODES / 4);
    count_kernel<<<N_EDGES / 256, 256>>>(ei, pdeg);
    scan_kernel<<<1, 1024>>>(pdeg, poff, pcur);
    fill_kernel<<<N_EDGES / 256, 256>>>(ei, ea, pcur, pcsrc, pcw);

    // ---- layer 1: sparse input -> bf16 agg cols 0..31, 1 phase-0 chunk ----
    agg1b_kernel<<<N_NODES * 32 / 256, 256>>>(poff, pcsrc, pcw,
                                              (const float4*)ph, (uint2*)paggb);
    gru_fused<<<N_NODES / 64, 512, FUSED_SMEM>>>(paggb, ph, phb, pqtb, pwhb,
                                                 b_ih, b_hh, 1);

    // ---- layer 2: full bf16 gather, 4 phase-0 chunks ----
    aggb_kernel<<<N_NODES * 32 / 256, 256>>>(poff, pcsrc, pcw,
                                             (const uint2*)phb, (uint2*)paggb);
    gru_fused<<<N_NODES / 64, 512, FUSED_SMEM>>>(paggb, ph, phb, pqtb + 49152, pwhb,
                                                 b_ih, b_hh, 4);

    post_kernel<<<BSZ, 256>>>(ph, conv_w, conv_b, lin1_w, lin1_b, lin2_w, lin2_b, out);
}

// round 9
// speedup vs baseline: 1.7479x; 1.0147x over previous
#include <cuda_runtime.h>
#include <cuda_bf16.h>
#include <cuda_fp16.h>
#include <cstdint>

#define N_NODES 65536
#define N_EDGES 1048576
#define HDIM    128
#define IN_F    5
#define N_GRAPH 16
#define ELEC    32
#define BSZ     128
#define LCONV   63   // (128-3)/2+1

// ---------------- device scratch (no allocations allowed) ----------------
__device__ float           g_h   [N_NODES * HDIM];   // 32 MB fp32 h
__device__ __nv_bfloat16   g_hb  [N_NODES * HDIM];   // 16 MB bf16 mirror of h
__device__ __nv_bfloat16   g_aggb[N_NODES * HDIM];   // 16 MB bf16 agg
__device__ float           g_qt  [2 * 384 * HDIM];   // fp32 Qt = W_ih @ Wg^T
__device__ __nv_bfloat16   g_qtb [2 * 384 * HDIM];   // bf16 Qt
__device__ __nv_bfloat16   g_whb [384 * HDIM];       // bf16 w_hh
// CSR scratch
__device__ int   g_deg [N_NODES];
__device__ int   g_off [N_NODES + 1];
__device__ int   g_cur [N_NODES];
__device__ int   g_csrc[N_EDGES];
__device__ float g_cw  [N_EDGES];

// ---------------- helpers ----------------
__device__ __forceinline__ unsigned int f2tf(float f) {
    unsigned int u; asm("cvt.rna.tf32.f32 %0, %1;" : "=r"(u) : "f"(f)); return u;
}

__device__ __forceinline__ void mma_tf32(float* c, const unsigned int* a, const unsigned int* b) {
    asm("mma.sync.aligned.m16n8k8.row.col.f32.tf32.tf32.f32 "
        "{%0,%1,%2,%3},{%4,%5,%6,%7},{%8,%9},{%0,%1,%2,%3};"
        : "+f"(c[0]), "+f"(c[1]), "+f"(c[2]), "+f"(c[3])
        : "r"(a[0]), "r"(a[1]), "r"(a[2]), "r"(a[3]), "r"(b[0]), "r"(b[1]));
}

__device__ __forceinline__ void mma_bf16(float* c, const unsigned int* a, const unsigned int* b) {
    asm("mma.sync.aligned.m16n8k16.row.col.f32.bf16.bf16.f32 "
        "{%0,%1,%2,%3},{%4,%5,%6,%7},{%8,%9},{%0,%1,%2,%3};"
        : "+f"(c[0]), "+f"(c[1]), "+f"(c[2]), "+f"(c[3])
        : "r"(a[0]), "r"(a[1]), "r"(a[2]), "r"(a[3]), "r"(b[0]), "r"(b[1]));
}

__device__ __forceinline__ void ldsm4(unsigned* r, unsigned addr) {
    asm volatile("ldmatrix.sync.aligned.m8n8.x4.shared.b16 {%0,%1,%2,%3}, [%4];"
        : "=r"(r[0]), "=r"(r[1]), "=r"(r[2]), "=r"(r[3]) : "r"(addr));
}

__device__ __forceinline__ void cp16(unsigned saddr, const void* gptr) {
    asm volatile("cp.async.cg.shared.global [%0], [%1], 16;" :: "r"(saddr), "l"(gptr));
}

__global__ void zero_kernel(float4* p, int n4) {
    int i = blockIdx.x * blockDim.x + threadIdx.x;
    if (i < n4) p[i] = make_float4(0.f, 0.f, 0.f, 0.f);
}

// convert qt (2*384*128) and w_hh (384*128) to bf16 in one launch
__global__ void cvt_weights_kernel(const float* __restrict__ qt, const float* __restrict__ whh,
                                   __nv_bfloat16* __restrict__ qtb,
                                   __nv_bfloat16* __restrict__ whb) {
    int i = blockIdx.x * blockDim.x + threadIdx.x;
    if (i < 2 * 384 * HDIM) qtb[i] = __float2bfloat16_rn(qt[i]);
    else {
        int j = i - 2 * 384 * HDIM;
        if (j < 384 * HDIM) whb[j] = __float2bfloat16_rn(whh[j]);
    }
}

// h[:, 0:5] = x, rest 0; also bf16 mirror
__global__ void pad_kernel(const float* __restrict__ x, float* __restrict__ h,
                           __nv_bfloat16* __restrict__ hb) {
    int i = blockIdx.x * blockDim.x + threadIdx.x;
    if (i >= N_NODES * 32) return;
    int n = i >> 5, c4 = i & 31;
    float4 v = make_float4(0.f, 0.f, 0.f, 0.f);
    if (c4 == 0) {
        const float* xr = x + n * IN_F;
        v.x = xr[0]; v.y = xr[1]; v.z = xr[2]; v.w = xr[3];
    } else if (c4 == 1) {
        v.x = x[n * IN_F + 4];
    }
    reinterpret_cast<float4*>(h)[i] = v;
    __nv_bfloat162 p0 = __floats2bfloat162_rn(v.x, v.y);
    __nv_bfloat162 p1 = __floats2bfloat162_rn(v.z, v.w);
    uint2 u;
    u.x = *reinterpret_cast<unsigned*>(&p0);
    u.y = *reinterpret_cast<unsigned*>(&p1);
    reinterpret_cast<uint2*>(hb)[i] = u;
}

// ---------------- CSR build ----------------
__global__ void count_kernel(const int* __restrict__ ei, int* __restrict__ deg) {
    int e = blockIdx.x * blockDim.x + threadIdx.x;
    if (e < N_EDGES) atomicAdd(&deg[ei[N_EDGES + e]], 1);
}

__global__ void scan_kernel(const int* __restrict__ deg, int* __restrict__ off,
                            int* __restrict__ cur) {
    __shared__ int ssum[1024];
    int t = threadIdx.x;
    int base = t * 64;
    int s = 0;
    #pragma unroll 8
    for (int i = 0; i < 64; i++) s += deg[base + i];
    int my = s;
    ssum[t] = s;
    __syncthreads();
    for (int o = 1; o < 1024; o <<= 1) {
        int v = (t >= o) ? ssum[t - o] : 0;
        __syncthreads();
        ssum[t] += v;
        __syncthreads();
    }
    int run = ssum[t] - my;
    for (int i = 0; i < 64; i++) {
        off[base + i] = run;
        cur[base + i] = run;
        run += deg[base + i];
    }
    if (t == 1023) off[N_NODES] = run;
}

__global__ void fill_kernel(const int* __restrict__ ei, const float* __restrict__ ea,
                            int* __restrict__ cur, int* __restrict__ csrc,
                            float* __restrict__ cw) {
    int e = blockIdx.x * blockDim.x + threadIdx.x;
    if (e >= N_EDGES) return;
    int d = ei[N_EDGES + e];
    int pos = atomicAdd(&cur[d], 1);
    csrc[pos] = ei[e];
    cw[pos]   = ea[e];
}

// ---------------- layer-2 gather: bf16 in/out, fp32 accumulate ----------------
__global__ void aggb_kernel(const int* __restrict__ off, const int* __restrict__ csrc,
                            const float* __restrict__ cw, const uint2* __restrict__ src,
                            uint2* __restrict__ dst) {
    int gid  = blockIdx.x * blockDim.x + threadIdx.x;
    int node = gid >> 5;
    int lane = gid & 31;
    if (node >= N_NODES) return;
    int e0 = __ldg(off + node), e1 = __ldg(off + node + 1);
    float4 acc = make_float4(0.f, 0.f, 0.f, 0.f);
    int e = e0;
    for (; e + 1 < e1; e += 2) {
        int   sA = __ldg(csrc + e),     sB = __ldg(csrc + e + 1);
        float wA = __ldg(cw + e),       wB = __ldg(cw + e + 1);
        uint2 vA = __ldg(src + (size_t)sA * 32 + lane);
        uint2 vB = __ldg(src + (size_t)sB * 32 + lane);
        float2 a0 = __bfloat1622float2(*reinterpret_cast<__nv_bfloat162*>(&vA.x));
        float2 a1 = __bfloat1622float2(*reinterpret_cast<__nv_bfloat162*>(&vA.y));
        float2 b0 = __bfloat1622float2(*reinterpret_cast<__nv_bfloat162*>(&vB.x));
        float2 b1 = __bfloat1622float2(*reinterpret_cast<__nv_bfloat162*>(&vB.y));
        acc.x += wA * a0.x + wB * b0.x;
        acc.y += wA * a0.y + wB * b0.y;
        acc.z += wA * a1.x + wB * b1.x;
        acc.w += wA * a1.y + wB * b1.y;
    }
    if (e < e1) {
        int   sA = __ldg(csrc + e);
        float wA = __ldg(cw + e);
        uint2 vA = __ldg(src + (size_t)sA * 32 + lane);
        float2 a0 = __bfloat1622float2(*reinterpret_cast<__nv_bfloat162*>(&vA.x));
        float2 a1 = __bfloat1622float2(*reinterpret_cast<__nv_bfloat162*>(&vA.y));
        acc.x += wA * a0.x; acc.y += wA * a0.y;
        acc.z += wA * a1.x; acc.w += wA * a1.y;
    }
    __nv_bfloat162 p0 = __floats2bfloat162_rn(acc.x, acc.y);
    __nv_bfloat162 p1 = __floats2bfloat162_rn(acc.z, acc.w);
    uint2 o;
    o.x = *reinterpret_cast<unsigned*>(&p0);
    o.y = *reinterpret_cast<unsigned*>(&p1);
    dst[(size_t)node * 32 + lane] = o;
}

// ---------------- layer-1 gather: fp32 h cols 0..4 -> bf16 agg cols 0..63 ----------------
__global__ void agg1b_kernel(const int* __restrict__ off, const int* __restrict__ csrc,
                             const float* __restrict__ cw, const float4* __restrict__ h4,
                             uint2* __restrict__ dst) {
    int gid  = blockIdx.x * blockDim.x + threadIdx.x;
    int node = gid >> 5;
    int lane = gid & 31;
    if (node >= N_NODES) return;
    int e0 = __ldg(off + node), e1 = __ldg(off + node + 1);
    float4 a0 = make_float4(0.f, 0.f, 0.f, 0.f);
    float  a4 = 0.f;
    for (int e = e0 + lane; e < e1; e += 32) {
        int   s = __ldg(csrc + e);
        float w = __ldg(cw + e);
        float4 v0 = __ldg(h4 + (size_t)s * 32);
        float  v4 = __ldg(reinterpret_cast<const float*>(h4 + (size_t)s * 32 + 1));
        a0.x += w * v0.x; a0.y += w * v0.y; a0.z += w * v0.z; a0.w += w * v0.w;
        a4   += w * v4;
    }
    #pragma unroll
    for (int o = 16; o; o >>= 1) {
        a0.x += __shfl_xor_sync(0xffffffffu, a0.x, o);
        a0.y += __shfl_xor_sync(0xffffffffu, a0.y, o);
        a0.z += __shfl_xor_sync(0xffffffffu, a0.z, o);
        a0.w += __shfl_xor_sync(0xffffffffu, a0.w, o);
        a4   += __shfl_xor_sync(0xffffffffu, a4, o);
    }
    // lanes 0..15 write cols 0..63 (zeros beyond col 4)
    if (lane < 16) {
        uint2 o = make_uint2(0u, 0u);
        if (lane == 0) {
            __nv_bfloat162 p0 = __floats2bfloat162_rn(a0.x, a0.y);
            __nv_bfloat162 p1 = __floats2bfloat162_rn(a0.z, a0.w);
            o.x = *reinterpret_cast<unsigned*>(&p0);
            o.y = *reinterpret_cast<unsigned*>(&p1);
        } else if (lane == 1) {
            __nv_bfloat162 p0 = __floats2bfloat162_rn(a4, 0.f);
            o.x = *reinterpret_cast<unsigned*>(&p0);
        }
        dst[(size_t)node * 32 + lane] = o;
    }
}

// ---------------- tf32 GEMM (only for tiny Qt = W_ih @ Wg^T precompute) ----------------
#define AS_STR 132
#define BS_STR 136
#define GEMM_SMEM ((128 * AS_STR + 128 * BS_STR) * 4)

__global__ void gemm_tf32(const float* __restrict__ A, const float* __restrict__ Bsrc,
                          float* __restrict__ C, int Nc) {
    extern __shared__ unsigned int sm[];
    unsigned int* As = sm;
    unsigned int* Bs = sm + 128 * AS_STR;

    int t  = threadIdx.x;
    int rb = blockIdx.x * 128;
    int cb = blockIdx.y * 128;

    {
        const float4* A4 = reinterpret_cast<const float4*>(A) + (size_t)rb * 32;
        #pragma unroll
        for (int i = t; i < 128 * 32; i += 256) {
            int r = i >> 5, k4 = i & 31;
            float4 v = A4[r * 32 + k4];
            uint4 u = make_uint4(f2tf(v.x), f2tf(v.y), f2tf(v.z), f2tf(v.w));
            *reinterpret_cast<uint4*>(&As[r * AS_STR + k4 * 4]) = u;
        }
    }
    {
        const float4* B4 = reinterpret_cast<const float4*>(Bsrc) + (size_t)cb * 32;
        #pragma unroll
        for (int i = t; i < 128 * 32; i += 256) {
            int n = i >> 5, k4 = i & 31;
            float4 v = B4[n * 32 + k4];
            uint4 u = make_uint4(f2tf(v.x), f2tf(v.y), f2tf(v.z), f2tf(v.w));
            *reinterpret_cast<uint4*>(&Bs[n * BS_STR + k4 * 4]) = u;
        }
    }
    __syncthreads();

    int warp = t >> 5, lane = t & 31;
    int wm = (warp >> 2) * 64;
    int wn = (warp & 3) * 32;
    int lr = lane >> 2, lc = lane & 3;

    float acc[4][4][4];
    #pragma unroll
    for (int mt = 0; mt < 4; mt++)
        #pragma unroll
        for (int nt = 0; nt < 4; nt++)
            #pragma unroll
            for (int q = 0; q < 4; q++) acc[mt][nt][q] = 0.f;

    #pragma unroll
    for (int kk = 0; kk < 16; kk++) {
        int k0 = kk * 8 + lc;
        unsigned int a[4][4], b[4][2];
        #pragma unroll
        for (int mt = 0; mt < 4; mt++) {
            int r = wm + mt * 16 + lr;
            a[mt][0] = As[r * AS_STR + k0];
            a[mt][1] = As[(r + 8) * AS_STR + k0];
            a[mt][2] = As[r * AS_STR + k0 + 4];
            a[mt][3] = As[(r + 8) * AS_STR + k0 + 4];
        }
        #pragma unroll
        for (int nt = 0; nt < 4; nt++) {
            int n = wn + nt * 8 + lr;
            b[nt][0] = Bs[n * BS_STR + k0];
            b[nt][1] = Bs[n * BS_STR + k0 + 4];
        }
        #pragma unroll
        for (int mt = 0; mt < 4; mt++)
            #pragma unroll
            for (int nt = 0; nt < 4; nt++)
                mma_tf32(acc[mt][nt], a[mt], b[nt]);
    }

    #pragma unroll
    for (int nt = 0; nt < 4; nt++) {
        int c = cb + wn + nt * 8 + lc * 2;
        #pragma unroll
        for (int mt = 0; mt < 4; mt++) {
            int r = rb + wm + mt * 16 + lr;
            float2 v0 = make_float2(acc[mt][nt][0], acc[mt][nt][1]);
            float2 v1 = make_float2(acc[mt][nt][2], acc[mt][nt][3]);
            *reinterpret_cast<float2*>(&C[(size_t)r * Nc + c])       = v0;
            *reinterpret_cast<float2*>(&C[(size_t)(r + 8) * Nc + c]) = v1;
        }
    }
}

// ---------------- fused GRU (bf16 MMA + ldmatrix): gi + gh + GRU update ----------------
// 64 rows/block, 512 threads (16 warps: 2 row x 8 col), warp tile 32 x 48.
// K-chunk = 64 bf16 (32 words + 4 pad), cp.async double-buffered, ldmatrix.x4 frags.
// smem words: A[2][64][36] | B[2][384][36] = 32256 words = 129,024 B
#define RA_STR 36
#define RB_STR 36
#define OFF_BW (2 * 64 * RA_STR)
#define FUSED_SMEM ((OFF_BW + 2 * 384 * RB_STR) * 4)

__global__ void __launch_bounds__(512, 1)
gru_fused(const __nv_bfloat16* __restrict__ aggb, float* __restrict__ h,
          __nv_bfloat16* __restrict__ hb,
          const __nv_bfloat16* __restrict__ w0b, const __nv_bfloat16* __restrict__ whb,
          const float* __restrict__ b_ih, const float* __restrict__ b_hh,
          int nch0, int write_hb) {
    extern __shared__ char smem[];
    unsigned sb = (unsigned)__cvta_generic_to_shared(smem);

    int t = threadIdx.x;
    int rb = blockIdx.x * 64;
    int warp = t >> 5, lane = t & 31;
    int wr = warp & 1;
    int wc = warp >> 1;
    int lr = lane >> 2, lc = lane & 3;

    int total = nch0 + 2;

    // cp.async loader indices: A 512 cp16 (1/thread), B 3072 cp16 (6/thread)
    int la_r = t >> 3, la_w = t & 7;

    auto load_chunk = [&](int j, int buf) {
        const __nv_bfloat16* A; const __nv_bfloat16* W; int kcol;
        if (j < nch0) { A = aggb; W = w0b; kcol = j * 64; }
        else          { A = hb;   W = whb; kcol = (j - nch0) * 64; }
        cp16(sb + (unsigned)(buf * (64 * RA_STR) + la_r * RA_STR + la_w * 4) * 4,
             A + (size_t)(rb + la_r) * 128 + kcol + la_w * 8);
        #pragma unroll
        for (int i = 0; i < 6; i++) {
            int idx = t + i * 512;
            int n = idx >> 3, w = idx & 7;
            cp16(sb + (unsigned)(OFF_BW + buf * (384 * RB_STR) + n * RB_STR + w * 4) * 4,
                 W + (size_t)n * 128 + kcol + w * 8);
        }
        asm volatile("cp.async.commit_group;");
    };

    load_chunk(0, 0);
    load_chunk(1, 1);

    // ldmatrix per-lane addressing constants
    int lm_m = lane >> 3, lm_r = lane & 7;
    int aRow = wr * 32 + (lm_m & 1) * 8 + lm_r;      // + mt*16
    int aWrd = (lm_m >> 1) * 4;                      // + ks*8
    int bRow = wc * 16 + (lm_m >> 1) * 8 + lm_r;     // + g*128
    int bWrd = (lm_m & 1) * 4;                       // + ks*8

    float acc[2][3][2][4];
    __half2 gi_st[2][3][2][2];

    for (int j = 0; j < total; j++) {
        int buf = j & 1;
        if (j == 0 || j == nch0) {
            #pragma unroll
            for (int mt = 0; mt < 2; mt++)
                #pragma unroll
                for (int g = 0; g < 3; g++)
                    #pragma unroll
                    for (int nt = 0; nt < 2; nt++)
                        #pragma unroll
                        for (int q = 0; q < 4; q++) acc[mt][g][nt][q] = 0.f;
        }
        if (j + 1 < total) asm volatile("cp.async.wait_group 1;");
        else               asm volatile("cp.async.wait_group 0;");
        __syncthreads();

        unsigned abase = sb + (unsigned)(buf * (64 * RA_STR)) * 4;
        unsigned bbase = sb + (unsigned)(OFF_BW + buf * (384 * RB_STR)) * 4;
        #pragma unroll
        for (int ks = 0; ks < 4; ks++) {       // 4 x K=16 per 64-chunk
            unsigned a[2][4], b[3][4];
            #pragma unroll
            for (int mt = 0; mt < 2; mt++)
                ldsm4(a[mt], abase + (unsigned)((aRow + mt * 16) * RA_STR + aWrd + ks * 8) * 4);
            #pragma unroll
            for (int g = 0; g < 3; g++)
                ldsm4(b[g], bbase + (unsigned)((bRow + g * 128) * RB_STR + bWrd + ks * 8) * 4);
            #pragma unroll
            for (int mt = 0; mt < 2; mt++)
                #pragma unroll
                for (int g = 0; g < 3; g++) {
                    mma_bf16(acc[mt][g][0], a[mt], &b[g][0]);
                    mma_bf16(acc[mt][g][1], a[mt], &b[g][2]);
                }
        }
        __syncthreads();
        if (j + 2 < total) load_chunk(j + 2, buf);

        if (j == nch0 - 1) {
            #pragma unroll
            for (int mt = 0; mt < 2; mt++)
                #pragma unroll
                for (int g = 0; g < 3; g++)
                    #pragma unroll
                    for (int nt = 0; nt < 2; nt++) {
                        gi_st[mt][g][nt][0] = __floats2half2_rn(acc[mt][g][nt][0], acc[mt][g][nt][1]);
                        gi_st[mt][g][nt][1] = __floats2half2_rn(acc[mt][g][nt][2], acc[mt][g][nt][3]);
                    }
        }
    }

    // GRU epilogue: acc holds gh; gi_st holds gi
    #pragma unroll
    for (int nt = 0; nt < 2; nt++) {
        int c = wc * 16 + nt * 8 + lc * 2;
        float bir0 = __ldg(b_ih + c),       bir1 = __ldg(b_ih + c + 1);
        float biz0 = __ldg(b_ih + 128 + c), biz1 = __ldg(b_ih + 128 + c + 1);
        float bin0 = __ldg(b_ih + 256 + c), bin1 = __ldg(b_ih + 256 + c + 1);
        float bhr0 = __ldg(b_hh + c),       bhr1 = __ldg(b_hh + c + 1);
        float bhz0 = __ldg(b_hh + 128 + c), bhz1 = __ldg(b_hh + 128 + c + 1);
        float bhn0 = __ldg(b_hh + 256 + c), bhn1 = __ldg(b_hh + 256 + c + 1);
        #pragma unroll
        for (int mt = 0; mt < 2; mt++) {
            #pragma unroll
            for (int half = 0; half < 2; half++) {
                int row = wr * 32 + mt * 16 + lr + half * 8;
                int q0 = half * 2;
                float2 gir = __half22float2(gi_st[mt][0][nt][half]);
                float2 giz = __half22float2(gi_st[mt][1][nt][half]);
                float2 gin = __half22float2(gi_st[mt][2][nt][half]);
                float ghr0 = acc[mt][0][nt][q0], ghr1 = acc[mt][0][nt][q0 + 1];
                float ghz0 = acc[mt][1][nt][q0], ghz1 = acc[mt][1][nt][q0 + 1];
                float ghn0 = acc[mt][2][nt][q0], ghn1 = acc[mt][2][nt][q0 + 1];
                float2 hold = *reinterpret_cast<float2*>(&h[(size_t)(rb + row) * 128 + c]);
                float r0 = 1.f / (1.f + __expf(-(gir.x + ghr0 + bir0 + bhr0)));
                float z0 = 1.f / (1.f + __expf(-(giz.x + ghz0 + biz0 + bhz0)));
                float n0 = tanhf(gin.x + bin0 + r0 * (ghn0 + bhn0));
                float r1 = 1.f / (1.f + __expf(-(gir.y + ghr1 + bir1 + bhr1)));
                float z1 = 1.f / (1.f + __expf(-(giz.y + ghz1 + biz1 + bhz1)));
                float n1 = tanhf(gin.y + bin1 + r1 * (ghn1 + bhn1));
                float hx = (1.f - z0) * n0 + z0 * hold.x;
                float hy = (1.f - z1) * n1 + z1 * hold.y;
                *reinterpret_cast<float2*>(&h[(size_t)(rb + row) * 128 + c]) = make_float2(hx, hy);
                if (write_hb) {
                    __nv_bfloat162 hp = __floats2bfloat162_rn(hx, hy);
                    *reinterpret_cast<unsigned*>(&hb[(size_t)(rb + row) * 128 + c]) =
                        *reinterpret_cast<unsigned*>(&hp);
                }
            }
        }
    }
}

// ---------------- post ----------------
__global__ void post_kernel(const float* __restrict__ h,
                            const float* __restrict__ conv_w, const float* __restrict__ conv_b,
                            const float* __restrict__ lin1_w, const float* __restrict__ lin1_b,
                            const float* __restrict__ lin2_w, const float* __restrict__ lin2_b,
                            float* __restrict__ out) {
    int b = blockIdx.x;
    int t = threadIdx.x;
    __shared__ float cw[48];
    __shared__ float v[ELEC * LCONV];
    __shared__ float u[HDIM];

    if (t < 48) cw[t] = conv_w[t];
    __syncthreads();
    float cb0 = conv_b[0];

    for (int idx = t; idx < ELEC * LCONV; idx += 256) {
        int e = idx / LCONV, l = idx % LCONV;
        float s = cb0;
        #pragma unroll
        for (int g = 0; g < N_GRAPH; g++) {
            const float* hr = h + ((size_t)((b * N_GRAPH + g) * ELEC + e)) * HDIM + 2 * l;
            s += cw[g * 3 + 0] * fmaxf(hr[0], 0.f)
               + cw[g * 3 + 1] * fmaxf(hr[1], 0.f)
               + cw[g * 3 + 2] * fmaxf(hr[2], 0.f);
        }
        v[idx] = fmaxf(s, 0.f);
    }
    __syncthreads();

    int w = t >> 5, lane = t & 31;
    for (int j = w; j < HDIM; j += 8) {
        float s = 0.f;
        for (int f = lane * 4; f < ELEC * LCONV; f += 128) {
            float4 wv = *reinterpret_cast<const float4*>(&lin1_w[(size_t)j * 2016 + f]);
            float4 vv = *reinterpret_cast<const float4*>(&v[f]);
            s += wv.x * vv.x + wv.y * vv.y + wv.z * vv.z + wv.w * vv.w;
        }
        #pragma unroll
        for (int o = 16; o; o >>= 1) s += __shfl_xor_sync(0xffffffffu, s, o);
        if (lane == 0) u[j] = fmaxf(s + lin1_b[j], 0.f);
    }
    __syncthreads();

    if (t < 32) {
        float s3[3];
        #pragma unroll
        for (int j = 0; j < 3; j++) {
            float acc = 0.f;
            for (int f = t; f < HDIM; f += 32) acc += lin2_w[j * HDIM + f] * u[f];
            #pragma unroll
            for (int o = 16; o; o >>= 1) acc += __shfl_xor_sync(0xffffffffu, acc, o);
            s3[j] = acc + lin2_b[j];
        }
        if (t == 0) {
            float mx = fmaxf(s3[0], fmaxf(s3[1], s3[2]));
            float e0 = expf(s3[0] - mx), e1 = expf(s3[1] - mx), e2 = expf(s3[2] - mx);
            float inv = 1.f / (e0 + e1 + e2);
            out[b * 3 + 0] = e0 * inv;
            out[b * 3 + 1] = e1 * inv;
            out[b * 3 + 2] = e2 * inv;
        }
    }
}

// ---------------- launch ----------------
extern "C" void kernel_launch(void* const* d_in, const int* in_sizes, int n_in,
                              void* d_out, int out_size) {
    const float* x       = (const float*)d_in[0];
    const int*   ei      = (const int*)  d_in[1];
    const float* ea      = (const float*)d_in[2];
    const float* gconv_w = (const float*)d_in[4];
    const float* w_ih    = (const float*)d_in[5];
    const float* w_hh    = (const float*)d_in[6];
    const float* b_ih    = (const float*)d_in[7];
    const float* b_hh    = (const float*)d_in[8];
    const float* conv_w  = (const float*)d_in[9];
    const float* conv_b  = (const float*)d_in[10];
    const float* lin1_w  = (const float*)d_in[11];
    const float* lin1_b  = (const float*)d_in[12];
    const float* lin2_w  = (const float*)d_in[13];
    const float* lin2_b  = (const float*)d_in[14];
    float* out = (float*)d_out;

    float *ph, *pqt, *pcw;
    __nv_bfloat16 *phb, *paggb, *pqtb, *pwhb;
    int *pdeg, *poff, *pcur, *pcsrc;
    cudaGetSymbolAddress((void**)&ph,    g_h);
    cudaGetSymbolAddress((void**)&phb,   g_hb);
    cudaGetSymbolAddress((void**)&paggb, g_aggb);
    cudaGetSymbolAddress((void**)&pqt,   g_qt);
    cudaGetSymbolAddress((void**)&pqtb,  g_qtb);
    cudaGetSymbolAddress((void**)&pwhb,  g_whb);
    cudaGetSymbolAddress((void**)&pdeg,  g_deg);
    cudaGetSymbolAddress((void**)&poff,  g_off);
    cudaGetSymbolAddress((void**)&pcur,  g_cur);
    cudaGetSymbolAddress((void**)&pcsrc, g_csrc);
    cudaGetSymbolAddress((void**)&pcw,   g_cw);

    cudaFuncSetAttribute(gemm_tf32, cudaFuncAttributeMaxDynamicSharedMemorySize, GEMM_SMEM);
    cudaFuncSetAttribute(gru_fused, cudaFuncAttributeMaxDynamicSharedMemorySize, FUSED_SMEM);

    // Qt[l] = W_ih @ Wg_l^T ([384][128] K-major), then weights -> bf16
    gemm_tf32<<<dim3(3, 1), 256, GEMM_SMEM>>>(w_ih, gconv_w,         pqt,         HDIM);
    gemm_tf32<<<dim3(3, 1), 256, GEMM_SMEM>>>(w_ih, gconv_w + 16384, pqt + 49152, HDIM);
    cvt_weights_kernel<<<(3 * 384 * HDIM + 255) / 256, 256>>>(pqt, w_hh, pqtb, pwhb);

    pad_kernel<<<(N_NODES * 32 + 255) / 256, 256>>>(x, ph, phb);
    // CSR build
    zero_kernel<<<(N_NODES / 4 + 255) / 256, 256>>>((float4*)pdeg, N_NODES / 4);
    count_kernel<<<N_EDGES / 256, 256>>>(ei, pdeg);
    scan_kernel<<<1, 1024>>>(pdeg, poff, pcur);
    fill_kernel<<<N_EDGES / 256, 256>>>(ei, ea, pcur, pcsrc, pcw);

    // ---- layer 1: sparse input -> bf16 agg cols 0..63, nch0=1 ----
    agg1b_kernel<<<N_NODES * 32 / 256, 256>>>(poff, pcsrc, pcw,
                                              (const float4*)ph, (uint2*)paggb);
    gru_fused<<<N_NODES / 64, 512, FUSED_SMEM>>>(paggb, ph, phb, pqtb, pwhb,
                                                 b_ih, b_hh, 1, 1);

    // ---- layer 2: full bf16 gather, nch0=2; skip hb write ----
    aggb_kernel<<<N_NODES * 32 / 256, 256>>>(poff, pcsrc, pcw,
                                             (const uint2*)phb, (uint2*)paggb);
    gru_fused<<<N_NODES / 64, 512, FUSED_SMEM>>>(paggb, ph, phb, pqtb + 49152, pwhb,
                                                 b_ih, b_hh, 2, 0);

    post_kernel<<<BSZ, 256>>>(ph, conv_w, conv_b, lin1_w, lin1_b, lin2_w, lin2_b, out);
}

// round 11
// speedup vs baseline: 1.8460x; 1.0561x over previous
#include <cuda_runtime.h>
#include <cuda_bf16.h>
#include <cuda_fp16.h>
#include <cstdint>

#define N_NODES 65536
#define N_EDGES 1048576
#define HDIM    128
#define IN_F    5
#define N_GRAPH 16
#define ELEC    32
#define BSZ     128
#define LCONV   63   // (128-3)/2+1

// ---------------- device scratch (no allocations allowed) ----------------
__device__ float           g_h   [N_NODES * HDIM];   // 32 MB fp32 h
__device__ __nv_bfloat16   g_hb  [N_NODES * HDIM];   // 16 MB bf16 mirror of h
__device__ __nv_bfloat16   g_aggb[N_NODES * HDIM];   // 16 MB bf16 agg
__device__ __nv_bfloat16   g_qtb [2 * 384 * HDIM];   // bf16 Qt = W_ih @ Wg^T
__device__ __nv_bfloat16   g_whb [384 * HDIM];       // bf16 w_hh
// CSR scratch
__device__ int   g_deg [N_NODES];
__device__ int   g_off [N_NODES + 1];
__device__ int   g_cur [N_NODES];
__device__ int   g_csrc[N_EDGES];
__device__ float g_cw  [N_EDGES];

// ---------------- helpers ----------------
__device__ __forceinline__ unsigned int f2tf(float f) {
    unsigned int u; asm("cvt.rna.tf32.f32 %0, %1;" : "=r"(u) : "f"(f)); return u;
}

__device__ __forceinline__ void mma_tf32(float* c, const unsigned int* a, const unsigned int* b) {
    asm("mma.sync.aligned.m16n8k8.row.col.f32.tf32.tf32.f32 "
        "{%0,%1,%2,%3},{%4,%5,%6,%7},{%8,%9},{%0,%1,%2,%3};"
        : "+f"(c[0]), "+f"(c[1]), "+f"(c[2]), "+f"(c[3])
        : "r"(a[0]), "r"(a[1]), "r"(a[2]), "r"(a[3]), "r"(b[0]), "r"(b[1]));
}

__device__ __forceinline__ void mma_bf16(float* c, const unsigned int* a, const unsigned int* b) {
    asm("mma.sync.aligned.m16n8k16.row.col.f32.bf16.bf16.f32 "
        "{%0,%1,%2,%3},{%4,%5,%6,%7},{%8,%9},{%0,%1,%2,%3};"
        : "+f"(c[0]), "+f"(c[1]), "+f"(c[2]), "+f"(c[3])
        : "r"(a[0]), "r"(a[1]), "r"(a[2]), "r"(a[3]), "r"(b[0]), "r"(b[1]));
}

__device__ __forceinline__ void ldsm4(unsigned* r, unsigned addr) {
    asm volatile("ldmatrix.sync.aligned.m8n8.x4.shared.b16 {%0,%1,%2,%3}, [%4];"
        : "=r"(r[0]), "=r"(r[1]), "=r"(r[2]), "=r"(r[3]) : "r"(addr));
}

__device__ __forceinline__ void cp16(unsigned saddr, const void* gptr) {
    asm volatile("cp.async.cg.shared.global [%0], [%1], 16;" :: "r"(saddr), "l"(gptr));
}

__global__ void zero_kernel(float4* p, int n4) {
    int i = blockIdx.x * blockDim.x + threadIdx.x;
    if (i < n4) p[i] = make_float4(0.f, 0.f, 0.f, 0.f);
}

// h[:, 0:5] = x, rest 0; also bf16 mirror
__global__ void pad_kernel(const float* __restrict__ x, float* __restrict__ h,
                           __nv_bfloat16* __restrict__ hb) {
    int i = blockIdx.x * blockDim.x + threadIdx.x;
    if (i >= N_NODES * 32) return;
    int n = i >> 5, c4 = i & 31;
    float4 v = make_float4(0.f, 0.f, 0.f, 0.f);
    if (c4 == 0) {
        const float* xr = x + n * IN_F;
        v.x = xr[0]; v.y = xr[1]; v.z = xr[2]; v.w = xr[3];
    } else if (c4 == 1) {
        v.x = x[n * IN_F + 4];
    }
    reinterpret_cast<float4*>(h)[i] = v;
    __nv_bfloat162 p0 = __floats2bfloat162_rn(v.x, v.y);
    __nv_bfloat162 p1 = __floats2bfloat162_rn(v.z, v.w);
    uint2 u;
    u.x = *reinterpret_cast<unsigned*>(&p0);
    u.y = *reinterpret_cast<unsigned*>(&p1);
    reinterpret_cast<uint2*>(hb)[i] = u;
}

// ---------------- CSR build ----------------
__global__ void count_kernel(const int* __restrict__ ei, int* __restrict__ deg) {
    int e = blockIdx.x * blockDim.x + threadIdx.x;
    if (e < N_EDGES) atomicAdd(&deg[ei[N_EDGES + e]], 1);
}

__global__ void scan_kernel(const int* __restrict__ deg, int* __restrict__ off,
                            int* __restrict__ cur) {
    __shared__ int ssum[1024];
    int t = threadIdx.x;
    int base = t * 64;
    int s = 0;
    #pragma unroll 8
    for (int i = 0; i < 64; i++) s += deg[base + i];
    int my = s;
    ssum[t] = s;
    __syncthreads();
    for (int o = 1; o < 1024; o <<= 1) {
        int v = (t >= o) ? ssum[t - o] : 0;
        __syncthreads();
        ssum[t] += v;
        __syncthreads();
    }
    int run = ssum[t] - my;
    for (int i = 0; i < 64; i++) {
        off[base + i] = run;
        cur[base + i] = run;
        run += deg[base + i];
    }
    if (t == 1023) off[N_NODES] = run;
}

// fill CSR payload; also converts w_hh -> bf16 (folded to save a launch)
__global__ void fill_kernel(const int* __restrict__ ei, const float* __restrict__ ea,
                            int* __restrict__ cur, int* __restrict__ csrc,
                            float* __restrict__ cw,
                            const float* __restrict__ whh, __nv_bfloat16* __restrict__ whb) {
    int e = blockIdx.x * blockDim.x + threadIdx.x;
    if (e >= N_EDGES) return;
    if (e < 384 * HDIM) whb[e] = __float2bfloat16_rn(whh[e]);
    int d = ei[N_EDGES + e];
    int pos = atomicAdd(&cur[d], 1);
    csrc[pos] = ei[e];
    cw[pos]   = ea[e];
}

// ---------------- layer-2 gather: bf16 in/out, fp32 accumulate ----------------
// 16 lanes per node, lane covers 8 bf16 (uint4 = 16B); 2 nodes per warp.
__global__ void aggb_kernel(const int* __restrict__ off, const int* __restrict__ csrc,
                            const float* __restrict__ cw, const uint4* __restrict__ src,
                            uint4* __restrict__ dst) {
    int gid  = blockIdx.x * blockDim.x + threadIdx.x;
    int node = gid >> 4;
    int lane = gid & 15;
    if (node >= N_NODES) return;
    int e0 = __ldg(off + node), e1 = __ldg(off + node + 1);
    float acc[8] = {0.f, 0.f, 0.f, 0.f, 0.f, 0.f, 0.f, 0.f};
    int e = e0;
    for (; e + 1 < e1; e += 2) {
        int   sA = __ldg(csrc + e),     sB = __ldg(csrc + e + 1);
        float wA = __ldg(cw + e),       wB = __ldg(cw + e + 1);
        uint4 vA = __ldg(src + (size_t)sA * 16 + lane);
        uint4 vB = __ldg(src + (size_t)sB * 16 + lane);
        const unsigned* pa = &vA.x;
        const unsigned* pb = &vB.x;
        #pragma unroll
        for (int q = 0; q < 4; q++) {
            float2 fa = __bfloat1622float2(*reinterpret_cast<const __nv_bfloat162*>(&pa[q]));
            float2 fb = __bfloat1622float2(*reinterpret_cast<const __nv_bfloat162*>(&pb[q]));
            acc[2*q]   += wA * fa.x + wB * fb.x;
            acc[2*q+1] += wA * fa.y + wB * fb.y;
        }
    }
    if (e < e1) {
        int   sA = __ldg(csrc + e);
        float wA = __ldg(cw + e);
        uint4 vA = __ldg(src + (size_t)sA * 16 + lane);
        const unsigned* pa = &vA.x;
        #pragma unroll
        for (int q = 0; q < 4; q++) {
            float2 fa = __bfloat1622float2(*reinterpret_cast<const __nv_bfloat162*>(&pa[q]));
            acc[2*q]   += wA * fa.x;
            acc[2*q+1] += wA * fa.y;
        }
    }
    uint4 o;
    unsigned* po = &o.x;
    #pragma unroll
    for (int q = 0; q < 4; q++) {
        __nv_bfloat162 p = __floats2bfloat162_rn(acc[2*q], acc[2*q+1]);
        po[q] = *reinterpret_cast<unsigned*>(&p);
    }
    dst[(size_t)node * 16 + lane] = o;
}

// ---------------- layer-1 gather: fp32 h cols 0..4 -> bf16 agg cols 0..63 ----------------
__global__ void agg1b_kernel(const int* __restrict__ off, const int* __restrict__ csrc,
                             const float* __restrict__ cw, const float4* __restrict__ h4,
                             uint2* __restrict__ dst) {
    int gid  = blockIdx.x * blockDim.x + threadIdx.x;
    int node = gid >> 5;
    int lane = gid & 31;
    if (node >= N_NODES) return;
    int e0 = __ldg(off + node), e1 = __ldg(off + node + 1);
    float4 a0 = make_float4(0.f, 0.f, 0.f, 0.f);
    float  a4 = 0.f;
    for (int e = e0 + lane; e < e1; e += 32) {
        int   s = __ldg(csrc + e);
        float w = __ldg(cw + e);
        float4 v0 = __ldg(h4 + (size_t)s * 32);
        float  v4 = __ldg(reinterpret_cast<const float*>(h4 + (size_t)s * 32 + 1));
        a0.x += w * v0.x; a0.y += w * v0.y; a0.z += w * v0.z; a0.w += w * v0.w;
        a4   += w * v4;
    }
    #pragma unroll
    for (int o = 16; o; o >>= 1) {
        a0.x += __shfl_xor_sync(0xffffffffu, a0.x, o);
        a0.y += __shfl_xor_sync(0xffffffffu, a0.y, o);
        a0.z += __shfl_xor_sync(0xffffffffu, a0.z, o);
        a0.w += __shfl_xor_sync(0xffffffffu, a0.w, o);
        a4   += __shfl_xor_sync(0xffffffffu, a4, o);
    }
    // lanes 0..15 write cols 0..63 (zeros beyond col 4)
    if (lane < 16) {
        uint2 o = make_uint2(0u, 0u);
        if (lane == 0) {
            __nv_bfloat162 p0 = __floats2bfloat162_rn(a0.x, a0.y);
            __nv_bfloat162 p1 = __floats2bfloat162_rn(a0.z, a0.w);
            o.x = *reinterpret_cast<unsigned*>(&p0);
            o.y = *reinterpret_cast<unsigned*>(&p1);
        } else if (lane == 1) {
            __nv_bfloat162 p0 = __floats2bfloat162_rn(a4, 0.f);
            o.x = *reinterpret_cast<unsigned*>(&p0);
        }
        dst[(size_t)node * 32 + lane] = o;
    }
}

// ---------------- Qt precompute: qtb[l] = bf16(W_ih @ Wg_l^T), [384][128] ----------------
#define AS_STR 132
#define BS_STR 136
#define GEMM_SMEM ((128 * AS_STR + 128 * BS_STR) * 4)

__global__ void gemm_qt(const float* __restrict__ w_ih, const float* __restrict__ gconv_w,
                        __nv_bfloat16* __restrict__ qtb) {
    extern __shared__ unsigned int sm[];
    unsigned int* As = sm;
    unsigned int* Bs = sm + 128 * AS_STR;

    const float* A = w_ih;                                    // [384][128]
    const float* Bsrc = gconv_w + (size_t)blockIdx.z * 16384; // [128][128]
    __nv_bfloat16* C = qtb + (size_t)blockIdx.z * 49152;

    int t  = threadIdx.x;
    int rb = blockIdx.x * 128;

    {
        const float4* A4 = reinterpret_cast<const float4*>(A) + (size_t)rb * 32;
        #pragma unroll
        for (int i = t; i < 128 * 32; i += 256) {
            int r = i >> 5, k4 = i & 31;
            float4 v = A4[r * 32 + k4];
            uint4 u = make_uint4(f2tf(v.x), f2tf(v.y), f2tf(v.z), f2tf(v.w));
            *reinterpret_cast<uint4*>(&As[r * AS_STR + k4 * 4]) = u;
        }
    }
    {
        const float4* B4 = reinterpret_cast<const float4*>(Bsrc);
        #pragma unroll
        for (int i = t; i < 128 * 32; i += 256) {
            int n = i >> 5, k4 = i & 31;
            float4 v = B4[n * 32 + k4];
            uint4 u = make_uint4(f2tf(v.x), f2tf(v.y), f2tf(v.z), f2tf(v.w));
            *reinterpret_cast<uint4*>(&Bs[n * BS_STR + k4 * 4]) = u;
        }
    }
    __syncthreads();

    int warp = t >> 5, lane = t & 31;
    int wm = (warp >> 2) * 64;
    int wn = (warp & 3) * 32;
    int lr = lane >> 2, lc = lane & 3;

    float acc[4][4][4];
    #pragma unroll
    for (int mt = 0; mt < 4; mt++)
        #pragma unroll
        for (int nt = 0; nt < 4; nt++)
            #pragma unroll
            for (int q = 0; q < 4; q++) acc[mt][nt][q] = 0.f;

    #pragma unroll
    for (int kk = 0; kk < 16; kk++) {
        int k0 = kk * 8 + lc;
        unsigned int a[4][4], b[4][2];
        #pragma unroll
        for (int mt = 0; mt < 4; mt++) {
            int r = wm + mt * 16 + lr;
            a[mt][0] = As[r * AS_STR + k0];
            a[mt][1] = As[(r + 8) * AS_STR + k0];
            a[mt][2] = As[r * AS_STR + k0 + 4];
            a[mt][3] = As[(r + 8) * AS_STR + k0 + 4];
        }
        #pragma unroll
        for (int nt = 0; nt < 4; nt++) {
            int n = wn + nt * 8 + lr;
            b[nt][0] = Bs[n * BS_STR + k0];
            b[nt][1] = Bs[n * BS_STR + k0 + 4];
        }
        #pragma unroll
        for (int mt = 0; mt < 4; mt++)
            #pragma unroll
            for (int nt = 0; nt < 4; nt++)
                mma_tf32(acc[mt][nt], a[mt], b[nt]);
    }

    #pragma unroll
    for (int nt = 0; nt < 4; nt++) {
        int c = wn + nt * 8 + lc * 2;
        #pragma unroll
        for (int mt = 0; mt < 4; mt++) {
            int r = rb + wm + mt * 16 + lr;
            __nv_bfloat162 p0 = __floats2bfloat162_rn(acc[mt][nt][0], acc[mt][nt][1]);
            __nv_bfloat162 p1 = __floats2bfloat162_rn(acc[mt][nt][2], acc[mt][nt][3]);
            *reinterpret_cast<unsigned*>(&C[(size_t)r * 128 + c]) =
                *reinterpret_cast<unsigned*>(&p0);
            *reinterpret_cast<unsigned*>(&C[(size_t)(r + 8) * 128 + c]) =
                *reinterpret_cast<unsigned*>(&p1);
        }
    }
}

// ---------------- fused GRU (bf16 MMA + ldmatrix): gi + gh + GRU update ----------------
// 64 rows/block, 512 threads (16 warps: 2 row x 8 col), warp tile 32 x 48.
// K-chunk = 64 bf16 (32 words + 4 pad), cp.async double-buffered, ldmatrix.x4 frags.
// nch0 = phase-0 K chunks (agg@Qt), nch1 = phase-1 K chunks (h@Whh; 1 for layer 1
// where h cols 64..127 are zero).
// smem words: A[2][64][36] | B[2][384][36] = 32256 words = 129,024 B
#define RA_STR 36
#define RB_STR 36
#define OFF_BW (2 * 64 * RA_STR)
#define FUSED_SMEM ((OFF_BW + 2 * 384 * RB_STR) * 4)

__global__ void __launch_bounds__(512, 1)
gru_fused(const __nv_bfloat16* __restrict__ aggb, float* __restrict__ h,
          __nv_bfloat16* __restrict__ hb,
          const __nv_bfloat16* __restrict__ w0b, const __nv_bfloat16* __restrict__ whb,
          const float* __restrict__ b_ih, const float* __restrict__ b_hh,
          int nch0, int nch1, int write_hb) {
    extern __shared__ char smem[];
    unsigned sb = (unsigned)__cvta_generic_to_shared(smem);

    int t = threadIdx.x;
    int rb = blockIdx.x * 64;
    int warp = t >> 5, lane = t & 31;
    int wr = warp & 1;
    int wc = warp >> 1;
    int lr = lane >> 2, lc = lane & 3;

    int total = nch0 + nch1;

    // cp.async loader indices: A 512 cp16 (1/thread), B 3072 cp16 (6/thread)
    int la_r = t >> 3, la_w = t & 7;

    auto load_chunk = [&](int j, int buf) {
        const __nv_bfloat16* A; const __nv_bfloat16* W; int kcol;
        if (j < nch0) { A = aggb; W = w0b; kcol = j * 64; }
        else          { A = hb;   W = whb; kcol = (j - nch0) * 64; }
        cp16(sb + (unsigned)(buf * (64 * RA_STR) + la_r * RA_STR + la_w * 4) * 4,
             A + (size_t)(rb + la_r) * 128 + kcol + la_w * 8);
        #pragma unroll
        for (int i = 0; i < 6; i++) {
            int idx = t + i * 512;
            int n = idx >> 3, w = idx & 7;
            cp16(sb + (unsigned)(OFF_BW + buf * (384 * RB_STR) + n * RB_STR + w * 4) * 4,
                 W + (size_t)n * 128 + kcol + w * 8);
        }
        asm volatile("cp.async.commit_group;");
    };

    load_chunk(0, 0);
    if (total > 1) load_chunk(1, 1);

    // ldmatrix per-lane addressing constants
    int lm_m = lane >> 3, lm_r = lane & 7;
    int aRow = wr * 32 + (lm_m & 1) * 8 + lm_r;      // + mt*16
    int aWrd = (lm_m >> 1) * 4;                      // + ks*8
    int bRow = wc * 16 + (lm_m >> 1) * 8 + lm_r;     // + g*128
    int bWrd = (lm_m & 1) * 4;                       // + ks*8

    float acc[2][3][2][4];
    __half2 gi_st[2][3][2][2];

    for (int j = 0; j < total; j++) {
        int buf = j & 1;
        if (j == 0 || j == nch0) {
            #pragma unroll
            for (int mt = 0; mt < 2; mt++)
                #pragma unroll
                for (int g = 0; g < 3; g++)
                    #pragma unroll
                    for (int nt = 0; nt < 2; nt++)
                        #pragma unroll
                        for (int q = 0; q < 4; q++) acc[mt][g][nt][q] = 0.f;
        }
        if (j + 1 < total) asm volatile("cp.async.wait_group 1;");
        else               asm volatile("cp.async.wait_group 0;");
        __syncthreads();

        unsigned abase = sb + (unsigned)(buf * (64 * RA_STR)) * 4;
        unsigned bbase = sb + (unsigned)(OFF_BW + buf * (384 * RB_STR)) * 4;
        #pragma unroll
        for (int ks = 0; ks < 4; ks++) {       // 4 x K=16 per 64-chunk
            unsigned a[2][4], b[3][4];
            #pragma unroll
            for (int mt = 0; mt < 2; mt++)
                ldsm4(a[mt], abase + (unsigned)((aRow + mt * 16) * RA_STR + aWrd + ks * 8) * 4);
            #pragma unroll
            for (int g = 0; g < 3; g++)
                ldsm4(b[g], bbase + (unsigned)((bRow + g * 128) * RB_STR + bWrd + ks * 8) * 4);
            #pragma unroll
            for (int mt = 0; mt < 2; mt++)
                #pragma unroll
                for (int g = 0; g < 3; g++) {
                    mma_bf16(acc[mt][g][0], a[mt], &b[g][0]);
                    mma_bf16(acc[mt][g][1], a[mt], &b[g][2]);
                }
        }
        __syncthreads();
        if (j + 2 < total) load_chunk(j + 2, buf);

        if (j == nch0 - 1) {
            #pragma unroll
            for (int mt = 0; mt < 2; mt++)
                #pragma unroll
                for (int g = 0; g < 3; g++)
                    #pragma unroll
                    for (int nt = 0; nt < 2; nt++) {
                        gi_st[mt][g][nt][0] = __floats2half2_rn(acc[mt][g][nt][0], acc[mt][g][nt][1]);
                        gi_st[mt][g][nt][1] = __floats2half2_rn(acc[mt][g][nt][2], acc[mt][g][nt][3]);
                    }
        }
    }

    // GRU epilogue: acc holds gh; gi_st holds gi
    #pragma unroll
    for (int nt = 0; nt < 2; nt++) {
        int c = wc * 16 + nt * 8 + lc * 2;
        float bir0 = __ldg(b_ih + c),       bir1 = __ldg(b_ih + c + 1);
        float biz0 = __ldg(b_ih + 128 + c), biz1 = __ldg(b_ih + 128 + c + 1);
        float bin0 = __ldg(b_ih + 256 + c), bin1 = __ldg(b_ih + 256 + c + 1);
        float bhr0 = __ldg(b_hh + c),       bhr1 = __ldg(b_hh + c + 1);
        float bhz0 = __ldg(b_hh + 128 + c), bhz1 = __ldg(b_hh + 128 + c + 1);
        float bhn0 = __ldg(b_hh + 256 + c), bhn1 = __ldg(b_hh + 256 + c + 1);
        #pragma unroll
        for (int mt = 0; mt < 2; mt++) {
            #pragma unroll
            for (int half = 0; half < 2; half++) {
                int row = wr * 32 + mt * 16 + lr + half * 8;
                int q0 = half * 2;
                float2 gir = __half22float2(gi_st[mt][0][nt][half]);
                float2 giz = __half22float2(gi_st[mt][1][nt][half]);
                float2 gin = __half22float2(gi_st[mt][2][nt][half]);
                float ghr0 = acc[mt][0][nt][q0], ghr1 = acc[mt][0][nt][q0 + 1];
                float ghz0 = acc[mt][1][nt][q0], ghz1 = acc[mt][1][nt][q0 + 1];
                float ghn0 = acc[mt][2][nt][q0], ghn1 = acc[mt][2][nt][q0 + 1];
                float2 hold = *reinterpret_cast<float2*>(&h[(size_t)(rb + row) * 128 + c]);
                float r0 = 1.f / (1.f + __expf(-(gir.x + ghr0 + bir0 + bhr0)));
                float z0 = 1.f / (1.f + __expf(-(giz.x + ghz0 + biz0 + bhz0)));
                float n0 = tanhf(gin.x + bin0 + r0 * (ghn0 + bhn0));
                float r1 = 1.f / (1.f + __expf(-(gir.y + ghr1 + bir1 + bhr1)));
                float z1 = 1.f / (1.f + __expf(-(giz.y + ghz1 + biz1 + bhz1)));
                float n1 = tanhf(gin.y + bin1 + r1 * (ghn1 + bhn1));
                float hx = (1.f - z0) * n0 + z0 * hold.x;
                float hy = (1.f - z1) * n1 + z1 * hold.y;
                *reinterpret_cast<float2*>(&h[(size_t)(rb + row) * 128 + c]) = make_float2(hx, hy);
                if (write_hb) {
                    __nv_bfloat162 hp = __floats2bfloat162_rn(hx, hy);
                    *reinterpret_cast<unsigned*>(&hb[(size_t)(rb + row) * 128 + c]) =
                        *reinterpret_cast<unsigned*>(&hp);
                }
            }
        }
    }
}

// ---------------- post ----------------
__global__ void post_kernel(const float* __restrict__ h,
                            const float* __restrict__ conv_w, const float* __restrict__ conv_b,
                            const float* __restrict__ lin1_w, const float* __restrict__ lin1_b,
                            const float* __restrict__ lin2_w, const float* __restrict__ lin2_b,
                            float* __restrict__ out) {
    int b = blockIdx.x;
    int t = threadIdx.x;
    __shared__ float cw[48];
    __shared__ float v[ELEC * LCONV];
    __shared__ float u[HDIM];

    if (t < 48) cw[t] = conv_w[t];
    __syncthreads();
    float cb0 = conv_b[0];

    for (int idx = t; idx < ELEC * LCONV; idx += 256) {
        int e = idx / LCONV, l = idx % LCONV;
        float s = cb0;
        #pragma unroll
        for (int g = 0; g < N_GRAPH; g++) {
            const float* hr = h + ((size_t)((b * N_GRAPH + g) * ELEC + e)) * HDIM + 2 * l;
            s += cw[g * 3 + 0] * fmaxf(hr[0], 0.f)
               + cw[g * 3 + 1] * fmaxf(hr[1], 0.f)
               + cw[g * 3 + 2] * fmaxf(hr[2], 0.f);
        }
        v[idx] = fmaxf(s, 0.f);
    }
    __syncthreads();

    int w = t >> 5, lane = t & 31;
    for (int j = w; j < HDIM; j += 8) {
        float s = 0.f;
        for (int f = lane * 4; f < ELEC * LCONV; f += 128) {
            float4 wv = *reinterpret_cast<const float4*>(&lin1_w[(size_t)j * 2016 + f]);
            float4 vv = *reinterpret_cast<const float4*>(&v[f]);
            s += wv.x * vv.x + wv.y * vv.y + wv.z * vv.z + wv.w * vv.w;
        }
        #pragma unroll
        for (int o = 16; o; o >>= 1) s += __shfl_xor_sync(0xffffffffu, s, o);
        if (lane == 0) u[j] = fmaxf(s + lin1_b[j], 0.f);
    }
    __syncthreads();

    if (t < 32) {
        float s3[3];
        #pragma unroll
        for (int j = 0; j < 3; j++) {
            float acc = 0.f;
            for (int f = t; f < HDIM; f += 32) acc += lin2_w[j * HDIM + f] * u[f];
            #pragma unroll
            for (int o = 16; o; o >>= 1) acc += __shfl_xor_sync(0xffffffffu, acc, o);
            s3[j] = acc + lin2_b[j];
        }
        if (t == 0) {
            float mx = fmaxf(s3[0], fmaxf(s3[1], s3[2]));
            float e0 = expf(s3[0] - mx), e1 = expf(s3[1] - mx), e2 = expf(s3[2] - mx);
            float inv = 1.f / (e0 + e1 + e2);
            out[b * 3 + 0] = e0 * inv;
            out[b * 3 + 1] = e1 * inv;
            out[b * 3 + 2] = e2 * inv;
        }
    }
}

// ---------------- launch ----------------
extern "C" void kernel_launch(void* const* d_in, const int* in_sizes, int n_in,
                              void* d_out, int out_size) {
    const float* x       = (const float*)d_in[0];
    const int*   ei      = (const int*)  d_in[1];
    const float* ea      = (const float*)d_in[2];
    const float* gconv_w = (const float*)d_in[4];
    const float* w_ih    = (const float*)d_in[5];
    const float* w_hh    = (const float*)d_in[6];
    const float* b_ih    = (const float*)d_in[7];
    const float* b_hh    = (const float*)d_in[8];
    const float* conv_w  = (const float*)d_in[9];
    const float* conv_b  = (const float*)d_in[10];
    const float* lin1_w  = (const float*)d_in[11];
    const float* lin1_b  = (const float*)d_in[12];
    const float* lin2_w  = (const float*)d_in[13];
    const float* lin2_b  = (const float*)d_in[14];
    float* out = (float*)d_out;

    float *ph, *pcw;
    __nv_bfloat16 *phb, *paggb, *pqtb, *pwhb;
    int *pdeg, *poff, *pcur, *pcsrc;
    cudaGetSymbolAddress((void**)&ph,    g_h);
    cudaGetSymbolAddress((void**)&phb,   g_hb);
    cudaGetSymbolAddress((void**)&paggb, g_aggb);
    cudaGetSymbolAddress((void**)&pqtb,  g_qtb);
    cudaGetSymbolAddress((void**)&pwhb,  g_whb);
    cudaGetSymbolAddress((void**)&pdeg,  g_deg);
    cudaGetSymbolAddress((void**)&poff,  g_off);
    cudaGetSymbolAddress((void**)&pcur,  g_cur);
    cudaGetSymbolAddress((void**)&pcsrc, g_csrc);
    cudaGetSymbolAddress((void**)&pcw,   g_cw);

    cudaFuncSetAttribute(gemm_qt,   cudaFuncAttributeMaxDynamicSharedMemorySize, GEMM_SMEM);
    cudaFuncSetAttribute(gru_fused, cudaFuncAttributeMaxDynamicSharedMemorySize, FUSED_SMEM);

    // Qt[l] = bf16(W_ih @ Wg_l^T)  — one launch, both layers, bf16 epilogue
    gemm_qt<<<dim3(3, 1, 2), 256, GEMM_SMEM>>>(w_ih, gconv_w, pqtb);

    pad_kernel<<<(N_NODES * 32 + 255) / 256, 256>>>(x, ph, phb);
    // CSR build (fill also converts w_hh -> bf16)
    zero_kernel<<<(N_NODES / 4 + 255) / 256, 256>>>((float4*)pdeg, N_NODES / 4);
    count_kernel<<<N_EDGES / 256, 256>>>(ei, pdeg);
    scan_kernel<<<1, 1024>>>(pdeg, poff, pcur);
    fill_kernel<<<N_EDGES / 256, 256>>>(ei, ea, pcur, pcsrc, pcw, w_hh, pwhb);

    // ---- layer 1: sparse input -> agg cols 0..63; phase-0 1 chunk, phase-1 1 chunk
    //      (h = [x|0] has zero cols 64..127) ----
    agg1b_kernel<<<N_NODES * 32 / 256, 256>>>(poff, pcsrc, pcw,
                                              (const float4*)ph, (uint2*)paggb);
    gru_fused<<<N_NODES / 64, 512, FUSED_SMEM>>>(paggb, ph, phb, pqtb, pwhb,
                                                 b_ih, b_hh, 1, 1, 1);

    // ---- layer 2: full bf16 gather; 2+2 chunks; skip hb write ----
    aggb_kernel<<<N_NODES * 16 / 256, 256>>>(poff, pcsrc, pcw,
                                             (const uint4*)phb, (uint4*)paggb);
    gru_fused<<<N_NODES / 64, 512, FUSED_SMEM>>>(paggb, ph, phb, pqtb + 49152, pwhb,
                                                 b_ih, b_hh, 2, 2, 0);

    post_kernel<<<BSZ, 256>>>(ph, conv_w, conv_b, lin1_w, lin1_b, lin2_w, lin2_b, out);
}

// round 12
// speedup vs baseline: 1.9507x; 1.0567x over previous
#include <cuda_runtime.h>
#include <cuda_bf16.h>
#include <cuda_fp16.h>
#include <cstdint>

#define N_NODES 65536
#define N_EDGES 1048576
#define HDIM    128
#define IN_F    5
#define N_GRAPH 16
#define ELEC    32
#define BSZ     128
#define LCONV   63   // (128-3)/2+1

// ---------------- device scratch (no allocations allowed) ----------------
__device__ float           g_h   [N_NODES * HDIM];   // 32 MB fp32 h
__device__ __nv_bfloat16   g_hb  [N_NODES * HDIM];   // 16 MB bf16 mirror of h
__device__ __nv_bfloat16   g_aggb[N_NODES * HDIM];   // 16 MB bf16 agg (layer 2)
__device__ __nv_bfloat16   g_aggc[N_NODES * 16];     // 2 MB compact agg (layer 1, 16 cols)
__device__ __nv_bfloat16   g_qtb [2 * 384 * HDIM];   // bf16 Qt = W_ih @ Wg^T
__device__ __nv_bfloat16   g_whb [384 * HDIM];       // bf16 w_hh
// CSR scratch
__device__ int   g_deg [N_NODES];
__device__ int   g_off [N_NODES + 1];
__device__ int   g_cur [N_NODES];
__device__ int   g_csrc[N_EDGES];
__device__ float g_cw  [N_EDGES];

// ---------------- helpers ----------------
__device__ __forceinline__ unsigned int f2tf(float f) {
    unsigned int u; asm("cvt.rna.tf32.f32 %0, %1;" : "=r"(u) : "f"(f)); return u;
}

__device__ __forceinline__ void mma_tf32(float* c, const unsigned int* a, const unsigned int* b) {
    asm("mma.sync.aligned.m16n8k8.row.col.f32.tf32.tf32.f32 "
        "{%0,%1,%2,%3},{%4,%5,%6,%7},{%8,%9},{%0,%1,%2,%3};"
        : "+f"(c[0]), "+f"(c[1]), "+f"(c[2]), "+f"(c[3])
        : "r"(a[0]), "r"(a[1]), "r"(a[2]), "r"(a[3]), "r"(b[0]), "r"(b[1]));
}

__device__ __forceinline__ void mma_bf16(float* c, const unsigned int* a, const unsigned int* b) {
    asm("mma.sync.aligned.m16n8k16.row.col.f32.bf16.bf16.f32 "
        "{%0,%1,%2,%3},{%4,%5,%6,%7},{%8,%9},{%0,%1,%2,%3};"
        : "+f"(c[0]), "+f"(c[1]), "+f"(c[2]), "+f"(c[3])
        : "r"(a[0]), "r"(a[1]), "r"(a[2]), "r"(a[3]), "r"(b[0]), "r"(b[1]));
}

__device__ __forceinline__ void ldsm4(unsigned* r, unsigned addr) {
    asm volatile("ldmatrix.sync.aligned.m8n8.x4.shared.b16 {%0,%1,%2,%3}, [%4];"
        : "=r"(r[0]), "=r"(r[1]), "=r"(r[2]), "=r"(r[3]) : "r"(addr));
}

__device__ __forceinline__ void cp16(unsigned saddr, const void* gptr) {
    asm volatile("cp.async.cg.shared.global [%0], [%1], 16;" :: "r"(saddr), "l"(gptr));
}

__global__ void zero_kernel(float4* p, int n4) {
    int i = blockIdx.x * blockDim.x + threadIdx.x;
    if (i < n4) p[i] = make_float4(0.f, 0.f, 0.f, 0.f);
}

// h[:, 0:5] = x, rest 0; also bf16 mirror
__global__ void pad_kernel(const float* __restrict__ x, float* __restrict__ h,
                           __nv_bfloat16* __restrict__ hb) {
    int i = blockIdx.x * blockDim.x + threadIdx.x;
    if (i >= N_NODES * 32) return;
    int n = i >> 5, c4 = i & 31;
    float4 v = make_float4(0.f, 0.f, 0.f, 0.f);
    if (c4 == 0) {
        const float* xr = x + n * IN_F;
        v.x = xr[0]; v.y = xr[1]; v.z = xr[2]; v.w = xr[3];
    } else if (c4 == 1) {
        v.x = x[n * IN_F + 4];
    }
    reinterpret_cast<float4*>(h)[i] = v;
    __nv_bfloat162 p0 = __floats2bfloat162_rn(v.x, v.y);
    __nv_bfloat162 p1 = __floats2bfloat162_rn(v.z, v.w);
    uint2 u;
    u.x = *reinterpret_cast<unsigned*>(&p0);
    u.y = *reinterpret_cast<unsigned*>(&p1);
    reinterpret_cast<uint2*>(hb)[i] = u;
}

// ---------------- CSR build ----------------
__global__ void count_kernel(const int* __restrict__ ei, int* __restrict__ deg) {
    int e = blockIdx.x * blockDim.x + threadIdx.x;
    if (e < N_EDGES) atomicAdd(&deg[ei[N_EDGES + e]], 1);
}

__global__ void scan_kernel(const int* __restrict__ deg, int* __restrict__ off,
                            int* __restrict__ cur) {
    __shared__ int ssum[1024];
    int t = threadIdx.x;
    int base = t * 64;
    int s = 0;
    #pragma unroll 8
    for (int i = 0; i < 64; i++) s += deg[base + i];
    int my = s;
    ssum[t] = s;
    __syncthreads();
    for (int o = 1; o < 1024; o <<= 1) {
        int v = (t >= o) ? ssum[t - o] : 0;
        __syncthreads();
        ssum[t] += v;
        __syncthreads();
    }
    int run = ssum[t] - my;
    for (int i = 0; i < 64; i++) {
        off[base + i] = run;
        cur[base + i] = run;
        run += deg[base + i];
    }
    if (t == 1023) off[N_NODES] = run;
}

// fill CSR payload; also converts w_hh -> bf16 (folded to save a launch)
__global__ void fill_kernel(const int* __restrict__ ei, const float* __restrict__ ea,
                            int* __restrict__ cur, int* __restrict__ csrc,
                            float* __restrict__ cw,
                            const float* __restrict__ whh, __nv_bfloat16* __restrict__ whb) {
    int e = blockIdx.x * blockDim.x + threadIdx.x;
    if (e >= N_EDGES) return;
    if (e < 384 * HDIM) whb[e] = __float2bfloat16_rn(whh[e]);
    int d = ei[N_EDGES + e];
    int pos = atomicAdd(&cur[d], 1);
    csrc[pos] = ei[e];
    cw[pos]   = ea[e];
}

// ---------------- layer-2 gather: bf16 in/out, fp32 accumulate ----------------
// 16 lanes per node, lane covers 8 bf16 (uint4 = 16B); 2 nodes per warp.
__global__ void aggb_kernel(const int* __restrict__ off, const int* __restrict__ csrc,
                            const float* __restrict__ cw, const uint4* __restrict__ src,
                            uint4* __restrict__ dst) {
    int gid  = blockIdx.x * blockDim.x + threadIdx.x;
    int node = gid >> 4;
    int lane = gid & 15;
    if (node >= N_NODES) return;
    int e0 = __ldg(off + node), e1 = __ldg(off + node + 1);
    float acc[8] = {0.f, 0.f, 0.f, 0.f, 0.f, 0.f, 0.f, 0.f};
    int e = e0;
    for (; e + 1 < e1; e += 2) {
        int   sA = __ldg(csrc + e),     sB = __ldg(csrc + e + 1);
        float wA = __ldg(cw + e),       wB = __ldg(cw + e + 1);
        uint4 vA = __ldg(src + (size_t)sA * 16 + lane);
        uint4 vB = __ldg(src + (size_t)sB * 16 + lane);
        const unsigned* pa = &vA.x;
        const unsigned* pb = &vB.x;
        #pragma unroll
        for (int q = 0; q < 4; q++) {
            float2 fa = __bfloat1622float2(*reinterpret_cast<const __nv_bfloat162*>(&pa[q]));
            float2 fb = __bfloat1622float2(*reinterpret_cast<const __nv_bfloat162*>(&pb[q]));
            acc[2*q]   += wA * fa.x + wB * fb.x;
            acc[2*q+1] += wA * fa.y + wB * fb.y;
        }
    }
    if (e < e1) {
        int   sA = __ldg(csrc + e);
        float wA = __ldg(cw + e);
        uint4 vA = __ldg(src + (size_t)sA * 16 + lane);
        const unsigned* pa = &vA.x;
        #pragma unroll
        for (int q = 0; q < 4; q++) {
            float2 fa = __bfloat1622float2(*reinterpret_cast<const __nv_bfloat162*>(&pa[q]));
            acc[2*q]   += wA * fa.x;
            acc[2*q+1] += wA * fa.y;
        }
    }
    uint4 o;
    unsigned* po = &o.x;
    #pragma unroll
    for (int q = 0; q < 4; q++) {
        __nv_bfloat162 p = __floats2bfloat162_rn(acc[2*q], acc[2*q+1]);
        po[q] = *reinterpret_cast<unsigned*>(&p);
    }
    dst[(size_t)node * 16 + lane] = o;
}

// ---------------- layer-1 gather: fp32 h cols 0..4 -> compact bf16 agg [N][16] ----------------
__global__ void agg1c_kernel(const int* __restrict__ off, const int* __restrict__ csrc,
                             const float* __restrict__ cw, const float4* __restrict__ h4,
                             uint2* __restrict__ dst) {
    int gid  = blockIdx.x * blockDim.x + threadIdx.x;
    int node = gid >> 5;
    int lane = gid & 31;
    if (node >= N_NODES) return;
    int e0 = __ldg(off + node), e1 = __ldg(off + node + 1);
    float4 a0 = make_float4(0.f, 0.f, 0.f, 0.f);
    float  a4 = 0.f;
    for (int e = e0 + lane; e < e1; e += 32) {
        int   s = __ldg(csrc + e);
        float w = __ldg(cw + e);
        float4 v0 = __ldg(h4 + (size_t)s * 32);
        float  v4 = __ldg(reinterpret_cast<const float*>(h4 + (size_t)s * 32 + 1));
        a0.x += w * v0.x; a0.y += w * v0.y; a0.z += w * v0.z; a0.w += w * v0.w;
        a4   += w * v4;
    }
    #pragma unroll
    for (int o = 16; o; o >>= 1) {
        a0.x += __shfl_xor_sync(0xffffffffu, a0.x, o);
        a0.y += __shfl_xor_sync(0xffffffffu, a0.y, o);
        a0.z += __shfl_xor_sync(0xffffffffu, a0.z, o);
        a0.w += __shfl_xor_sync(0xffffffffu, a0.w, o);
        a4   += __shfl_xor_sync(0xffffffffu, a4, o);
    }
    // compact row = 16 bf16 = 4 uint2; lanes 0..3 write
    if (lane < 4) {
        uint2 o = make_uint2(0u, 0u);
        if (lane == 0) {
            __nv_bfloat162 p0 = __floats2bfloat162_rn(a0.x, a0.y);
            __nv_bfloat162 p1 = __floats2bfloat162_rn(a0.z, a0.w);
            o.x = *reinterpret_cast<unsigned*>(&p0);
            o.y = *reinterpret_cast<unsigned*>(&p1);
        } else if (lane == 1) {
            __nv_bfloat162 p0 = __floats2bfloat162_rn(a4, 0.f);
            o.x = *reinterpret_cast<unsigned*>(&p0);
        }
        dst[(size_t)node * 4 + lane] = o;
    }
}

// ---------------- Qt precompute: qtb[l] = bf16(W_ih @ Wg_l^T), [384][128] ----------------
#define AS_STR 132
#define BS_STR 136
#define GEMM_SMEM ((128 * AS_STR + 128 * BS_STR) * 4)

__global__ void gemm_qt(const float* __restrict__ w_ih, const float* __restrict__ gconv_w,
                        __nv_bfloat16* __restrict__ qtb) {
    extern __shared__ unsigned int sm[];
    unsigned int* As = sm;
    unsigned int* Bs = sm + 128 * AS_STR;

    const float* A = w_ih;                                    // [384][128]
    const float* Bsrc = gconv_w + (size_t)blockIdx.z * 16384; // [128][128]
    __nv_bfloat16* C = qtb + (size_t)blockIdx.z * 49152;

    int t  = threadIdx.x;
    int rb = blockIdx.x * 128;

    {
        const float4* A4 = reinterpret_cast<const float4*>(A) + (size_t)rb * 32;
        #pragma unroll
        for (int i = t; i < 128 * 32; i += 256) {
            int r = i >> 5, k4 = i & 31;
            float4 v = A4[r * 32 + k4];
            uint4 u = make_uint4(f2tf(v.x), f2tf(v.y), f2tf(v.z), f2tf(v.w));
            *reinterpret_cast<uint4*>(&As[r * AS_STR + k4 * 4]) = u;
        }
    }
    {
        const float4* B4 = reinterpret_cast<const float4*>(Bsrc);
        #pragma unroll
        for (int i = t; i < 128 * 32; i += 256) {
            int n = i >> 5, k4 = i & 31;
            float4 v = B4[n * 32 + k4];
            uint4 u = make_uint4(f2tf(v.x), f2tf(v.y), f2tf(v.z), f2tf(v.w));
            *reinterpret_cast<uint4*>(&Bs[n * BS_STR + k4 * 4]) = u;
        }
    }
    __syncthreads();

    int warp = t >> 5, lane = t & 31;
    int wm = (warp >> 2) * 64;
    int wn = (warp & 3) * 32;
    int lr = lane >> 2, lc = lane & 3;

    float acc[4][4][4];
    #pragma unroll
    for (int mt = 0; mt < 4; mt++)
        #pragma unroll
        for (int nt = 0; nt < 4; nt++)
            #pragma unroll
            for (int q = 0; q < 4; q++) acc[mt][nt][q] = 0.f;

    #pragma unroll
    for (int kk = 0; kk < 16; kk++) {
        int k0 = kk * 8 + lc;
        unsigned int a[4][4], b[4][2];
        #pragma unroll
        for (int mt = 0; mt < 4; mt++) {
            int r = wm + mt * 16 + lr;
            a[mt][0] = As[r * AS_STR + k0];
            a[mt][1] = As[(r + 8) * AS_STR + k0];
            a[mt][2] = As[r * AS_STR + k0 + 4];
            a[mt][3] = As[(r + 8) * AS_STR + k0 + 4];
        }
        #pragma unroll
        for (int nt = 0; nt < 4; nt++) {
            int n = wn + nt * 8 + lr;
            b[nt][0] = Bs[n * BS_STR + k0];
            b[nt][1] = Bs[n * BS_STR + k0 + 4];
        }
        #pragma unroll
        for (int mt = 0; mt < 4; mt++)
            #pragma unroll
            for (int nt = 0; nt < 4; nt++)
                mma_tf32(acc[mt][nt], a[mt], b[nt]);
    }

    #pragma unroll
    for (int nt = 0; nt < 4; nt++) {
        int c = wn + nt * 8 + lc * 2;
        #pragma unroll
        for (int mt = 0; mt < 4; mt++) {
            int r = rb + wm + mt * 16 + lr;
            __nv_bfloat162 p0 = __floats2bfloat162_rn(acc[mt][nt][0], acc[mt][nt][1]);
            __nv_bfloat162 p1 = __floats2bfloat162_rn(acc[mt][nt][2], acc[mt][nt][3]);
            *reinterpret_cast<unsigned*>(&C[(size_t)r * 128 + c]) =
                *reinterpret_cast<unsigned*>(&p0);
            *reinterpret_cast<unsigned*>(&C[(size_t)(r + 8) * 128 + c]) =
                *reinterpret_cast<unsigned*>(&p1);
        }
    }
}

// ---------------- shared GRU epilogue ----------------
// acc holds gh fragments; gi_st holds gi fragments (fp16).
// layer1: hold-read only for cols < 5 (h0 zero elsewhere); also writes hb.
template <int LAYER1>
__device__ __forceinline__ void gru_epilogue(
    float acc[2][3][2][4], __half2 gi_st[2][3][2][2],
    float* h, __nv_bfloat16* hb, const float* b_ih, const float* b_hh,
    int rb, int wr, int wc, int lr, int lc) {
    #pragma unroll
    for (int nt = 0; nt < 2; nt++) {
        int c = wc * 16 + nt * 8 + lc * 2;
        float bir0 = __ldg(b_ih + c),       bir1 = __ldg(b_ih + c + 1);
        float biz0 = __ldg(b_ih + 128 + c), biz1 = __ldg(b_ih + 128 + c + 1);
        float bin0 = __ldg(b_ih + 256 + c), bin1 = __ldg(b_ih + 256 + c + 1);
        float bhr0 = __ldg(b_hh + c),       bhr1 = __ldg(b_hh + c + 1);
        float bhz0 = __ldg(b_hh + 128 + c), bhz1 = __ldg(b_hh + 128 + c + 1);
        float bhn0 = __ldg(b_hh + 256 + c), bhn1 = __ldg(b_hh + 256 + c + 1);
        #pragma unroll
        for (int mt = 0; mt < 2; mt++) {
            #pragma unroll
            for (int half = 0; half < 2; half++) {
                int row = wr * 32 + mt * 16 + lr + half * 8;
                int q0 = half * 2;
                float2 gir = __half22float2(gi_st[mt][0][nt][half]);
                float2 giz = __half22float2(gi_st[mt][1][nt][half]);
                float2 gin = __half22float2(gi_st[mt][2][nt][half]);
                float ghr0 = acc[mt][0][nt][q0], ghr1 = acc[mt][0][nt][q0 + 1];
                float ghz0 = acc[mt][1][nt][q0], ghz1 = acc[mt][1][nt][q0 + 1];
                float ghn0 = acc[mt][2][nt][q0], ghn1 = acc[mt][2][nt][q0 + 1];
                float2 hold;
                if (LAYER1) {
                    hold = make_float2(0.f, 0.f);
                    if (c < 5)
                        hold = *reinterpret_cast<float2*>(&h[(size_t)(rb + row) * 128 + c]);
                } else {
                    hold = *reinterpret_cast<float2*>(&h[(size_t)(rb + row) * 128 + c]);
                }
                float r0 = 1.f / (1.f + __expf(-(gir.x + ghr0 + bir0 + bhr0)));
                float z0 = 1.f / (1.f + __expf(-(giz.x + ghz0 + biz0 + bhz0)));
                float n0 = tanhf(gin.x + bin0 + r0 * (ghn0 + bhn0));
                float r1 = 1.f / (1.f + __expf(-(gir.y + ghr1 + bir1 + bhr1)));
                float z1 = 1.f / (1.f + __expf(-(giz.y + ghz1 + biz1 + bhz1)));
                float n1 = tanhf(gin.y + bin1 + r1 * (ghn1 + bhn1));
                float hx = (1.f - z0) * n0 + z0 * hold.x;
                float hy = (1.f - z1) * n1 + z1 * hold.y;
                *reinterpret_cast<float2*>(&h[(size_t)(rb + row) * 128 + c]) = make_float2(hx, hy);
                if (LAYER1) {
                    __nv_bfloat162 hp = __floats2bfloat162_rn(hx, hy);
                    *reinterpret_cast<unsigned*>(&hb[(size_t)(rb + row) * 128 + c]) =
                        *reinterpret_cast<unsigned*>(&hp);
                }
            }
        }
    }
}

// ---------------- layer-1 fused GRU: exact K=16 GEMMs ----------------
// agg1 and h0 have nonzero cols only 0..4 -> gi/gh GEMMs are exactly K=16
// (one bf16 MMA k-step, zero-padded). All 4 tiles loaded up front (43 KB smem).
// smem words: A0[64][12] | B0[384][12] | A1[64][12] | B1[384][12]
#define R1_STR 12
#define O_B0 (64 * R1_STR)
#define O_A1 (O_B0 + 384 * R1_STR)
#define O_B1 (O_A1 + 64 * R1_STR)
#define GRU1_SMEM ((O_B1 + 384 * R1_STR) * 4)

__global__ void __launch_bounds__(512, 1)
gru1_fused(const __nv_bfloat16* __restrict__ aggc, float* __restrict__ h,
           __nv_bfloat16* __restrict__ hb,
           const __nv_bfloat16* __restrict__ w0b, const __nv_bfloat16* __restrict__ whb,
           const float* __restrict__ b_ih, const float* __restrict__ b_hh) {
    extern __shared__ char smem[];
    unsigned sb = (unsigned)__cvta_generic_to_shared(smem);

    int t = threadIdx.x;
    int rb = blockIdx.x * 64;
    int warp = t >> 5, lane = t & 31;
    int wr = warp & 1;
    int wc = warp >> 1;
    int lr = lane >> 2, lc = lane & 3;

    // load all tiles: A0 (aggc 64x16), B0 (Qt[:,0:16]), A1 (hb rows cols 0..15), B1 (Whh[:,0:16])
    {
        // A0 + A1: 128 cp16 each; threads 0..255 do both
        if (t < 128) {
            int r = t >> 1, wq = (t & 1) * 4;
            cp16(sb + (unsigned)(r * R1_STR + wq) * 4, aggc + (size_t)(rb + r) * 16 + (t & 1) * 8);
        } else if (t < 256) {
            int tt = t - 128;
            int r = tt >> 1, wq = (tt & 1) * 4;
            cp16(sb + (unsigned)(O_A1 + r * R1_STR + wq) * 4,
                 hb + (size_t)(rb + r) * 128 + (tt & 1) * 8);
        }
        // B0: 768 cp16, B1: 768 cp16 -> 3 rounds of 512
        #pragma unroll
        for (int i = 0; i < 3; i++) {
            int idx = t + i * 512;   // 0..1535
            const __nv_bfloat16* W = (idx < 768) ? w0b : whb;
            int base = (idx < 768) ? O_B0 : O_B1;
            int j = (idx < 768) ? idx : idx - 768;
            int n = j >> 1, wq = (j & 1) * 4;
            cp16(sb + (unsigned)(base + n * R1_STR + wq) * 4,
                 W + (size_t)n * 128 + (j & 1) * 8);
        }
        asm volatile("cp.async.commit_group;");
    }
    asm volatile("cp.async.wait_group 0;");
    __syncthreads();

    // ldmatrix per-lane addressing
    int lm_m = lane >> 3, lm_r = lane & 7;
    int aRow = wr * 32 + (lm_m & 1) * 8 + lm_r;
    int aWrd = (lm_m >> 1) * 4;
    int bRow = wc * 16 + (lm_m >> 1) * 8 + lm_r;
    int bWrd = (lm_m & 1) * 4;

    float acc[2][3][2][4];
    __half2 gi_st[2][3][2][2];

    #pragma unroll
    for (int phase = 0; phase < 2; phase++) {
        unsigned abase = sb + (unsigned)((phase ? O_A1 : 0)) * 4;
        unsigned bbase = sb + (unsigned)((phase ? O_B1 : O_B0)) * 4;
        unsigned a[2][4], b[3][4];
        #pragma unroll
        for (int mt = 0; mt < 2; mt++)
            ldsm4(a[mt], abase + (unsigned)((aRow + mt * 16) * R1_STR + aWrd) * 4);
        #pragma unroll
        for (int g = 0; g < 3; g++)
            ldsm4(b[g], bbase + (unsigned)((bRow + g * 128) * R1_STR + bWrd) * 4);
        #pragma unroll
        for (int mt = 0; mt < 2; mt++)
            #pragma unroll
            for (int g = 0; g < 3; g++)
                #pragma unroll
                for (int nt = 0; nt < 2; nt++)
                    #pragma unroll
                    for (int q = 0; q < 4; q++) acc[mt][g][nt][q] = 0.f;
        #pragma unroll
        for (int mt = 0; mt < 2; mt++)
            #pragma unroll
            for (int g = 0; g < 3; g++) {
                mma_bf16(acc[mt][g][0], a[mt], &b[g][0]);
                mma_bf16(acc[mt][g][1], a[mt], &b[g][2]);
            }
        if (phase == 0) {
            #pragma unroll
            for (int mt = 0; mt < 2; mt++)
                #pragma unroll
                for (int g = 0; g < 3; g++)
                    #pragma unroll
                    for (int nt = 0; nt < 2; nt++) {
                        gi_st[mt][g][nt][0] = __floats2half2_rn(acc[mt][g][nt][0], acc[mt][g][nt][1]);
                        gi_st[mt][g][nt][1] = __floats2half2_rn(acc[mt][g][nt][2], acc[mt][g][nt][3]);
                    }
        }
    }

    gru_epilogue<1>(acc, gi_st, h, hb, b_ih, b_hh, rb, wr, wc, lr, lc);
}

// ---------------- layer-2 fused GRU (bf16 MMA + ldmatrix, K=64 chunks) ----------------
#define RA_STR 36
#define RB_STR 36
#define OFF_BW (2 * 64 * RA_STR)
#define FUSED_SMEM ((OFF_BW + 2 * 384 * RB_STR) * 4)

__global__ void __launch_bounds__(512, 1)
gru_fused(const __nv_bfloat16* __restrict__ aggb, float* __restrict__ h,
          __nv_bfloat16* __restrict__ hb,
          const __nv_bfloat16* __restrict__ w0b, const __nv_bfloat16* __restrict__ whb,
          const float* __restrict__ b_ih, const float* __restrict__ b_hh) {
    extern __shared__ char smem[];
    unsigned sb = (unsigned)__cvta_generic_to_shared(smem);

    int t = threadIdx.x;
    int rb = blockIdx.x * 64;
    int warp = t >> 5, lane = t & 31;
    int wr = warp & 1;
    int wc = warp >> 1;
    int lr = lane >> 2, lc = lane & 3;

    const int nch0 = 2, total = 4;

    int la_r = t >> 3, la_w = t & 7;

    auto load_chunk = [&](int j, int buf) {
        const __nv_bfloat16* A; const __nv_bfloat16* W; int kcol;
        if (j < nch0) { A = aggb; W = w0b; kcol = j * 64; }
        else          { A = hb;   W = whb; kcol = (j - nch0) * 64; }
        cp16(sb + (unsigned)(buf * (64 * RA_STR) + la_r * RA_STR + la_w * 4) * 4,
             A + (size_t)(rb + la_r) * 128 + kcol + la_w * 8);
        #pragma unroll
        for (int i = 0; i < 6; i++) {
            int idx = t + i * 512;
            int n = idx >> 3, w = idx & 7;
            cp16(sb + (unsigned)(OFF_BW + buf * (384 * RB_STR) + n * RB_STR + w * 4) * 4,
                 W + (size_t)n * 128 + kcol + w * 8);
        }
        asm volatile("cp.async.commit_group;");
    };

    load_chunk(0, 0);
    load_chunk(1, 1);

    int lm_m = lane >> 3, lm_r = lane & 7;
    int aRow = wr * 32 + (lm_m & 1) * 8 + lm_r;
    int aWrd = (lm_m >> 1) * 4;
    int bRow = wc * 16 + (lm_m >> 1) * 8 + lm_r;
    int bWrd = (lm_m & 1) * 4;

    float acc[2][3][2][4];
    __half2 gi_st[2][3][2][2];

    for (int j = 0; j < total; j++) {
        int buf = j & 1;
        if (j == 0 || j == nch0) {
            #pragma unroll
            for (int mt = 0; mt < 2; mt++)
                #pragma unroll
                for (int g = 0; g < 3; g++)
                    #pragma unroll
                    for (int nt = 0; nt < 2; nt++)
                        #pragma unroll
                        for (int q = 0; q < 4; q++) acc[mt][g][nt][q] = 0.f;
        }
        if (j + 1 < total) asm volatile("cp.async.wait_group 1;");
        else               asm volatile("cp.async.wait_group 0;");
        __syncthreads();

        unsigned abase = sb + (unsigned)(buf * (64 * RA_STR)) * 4;
        unsigned bbase = sb + (unsigned)(OFF_BW + buf * (384 * RB_STR)) * 4;
        #pragma unroll
        for (int ks = 0; ks < 4; ks++) {
            unsigned a[2][4], b[3][4];
            #pragma unroll
            for (int mt = 0; mt < 2; mt++)
                ldsm4(a[mt], abase + (unsigned)((aRow + mt * 16) * RA_STR + aWrd + ks * 8) * 4);
            #pragma unroll
            for (int g = 0; g < 3; g++)
                ldsm4(b[g], bbase + (unsigned)((bRow + g * 128) * RB_STR + bWrd + ks * 8) * 4);
            #pragma unroll
            for (int mt = 0; mt < 2; mt++)
                #pragma unroll
                for (int g = 0; g < 3; g++) {
                    mma_bf16(acc[mt][g][0], a[mt], &b[g][0]);
                    mma_bf16(acc[mt][g][1], a[mt], &b[g][2]);
                }
        }
        __syncthreads();
        if (j + 2 < total) load_chunk(j + 2, buf);

        if (j == nch0 - 1) {
            #pragma unroll
            for (int mt = 0; mt < 2; mt++)
                #pragma unroll
                for (int g = 0; g < 3; g++)
                    #pragma unroll
                    for (int nt = 0; nt < 2; nt++) {
                        gi_st[mt][g][nt][0] = __floats2half2_rn(acc[mt][g][nt][0], acc[mt][g][nt][1]);
                        gi_st[mt][g][nt][1] = __floats2half2_rn(acc[mt][g][nt][2], acc[mt][g][nt][3]);
                    }
        }
    }

    gru_epilogue<0>(acc, gi_st, h, hb, b_ih, b_hh, rb, wr, wc, lr, lc);
}

// ---------------- post ----------------
__global__ void post_kernel(const float* __restrict__ h,
                            const float* __restrict__ conv_w, const float* __restrict__ conv_b,
                            const float* __restrict__ lin1_w, const float* __restrict__ lin1_b,
                            const float* __restrict__ lin2_w, const float* __restrict__ lin2_b,
                            float* __restrict__ out) {
    int b = blockIdx.x;
    int t = threadIdx.x;
    __shared__ float cw[48];
    __shared__ float v[ELEC * LCONV];
    __shared__ float u[HDIM];

    if (t < 48) cw[t] = conv_w[t];
    __syncthreads();
    float cb0 = conv_b[0];

    for (int idx = t; idx < ELEC * LCONV; idx += 256) {
        int e = idx / LCONV, l = idx % LCONV;
        float s = cb0;
        #pragma unroll
        for (int g = 0; g < N_GRAPH; g++) {
            const float* hr = h + ((size_t)((b * N_GRAPH + g) * ELEC + e)) * HDIM + 2 * l;
            s += cw[g * 3 + 0] * fmaxf(hr[0], 0.f)
               + cw[g * 3 + 1] * fmaxf(hr[1], 0.f)
               + cw[g * 3 + 2] * fmaxf(hr[2], 0.f);
        }
        v[idx] = fmaxf(s, 0.f);
    }
    __syncthreads();

    int w = t >> 5, lane = t & 31;
    for (int j = w; j < HDIM; j += 8) {
        float s = 0.f;
        for (int f = lane * 4; f < ELEC * LCONV; f += 128) {
            float4 wv = *reinterpret_cast<const float4*>(&lin1_w[(size_t)j * 2016 + f]);
            float4 vv = *reinterpret_cast<const float4*>(&v[f]);
            s += wv.x * vv.x + wv.y * vv.y + wv.z * vv.z + wv.w * vv.w;
        }
        #pragma unroll
        for (int o = 16; o; o >>= 1) s += __shfl_xor_sync(0xffffffffu, s, o);
        if (lane == 0) u[j] = fmaxf(s + lin1_b[j], 0.f);
    }
    __syncthreads();

    if (t < 32) {
        float s3[3];
        #pragma unroll
        for (int j = 0; j < 3; j++) {
            float acc = 0.f;
            for (int f = t; f < HDIM; f += 32) acc += lin2_w[j * HDIM + f] * u[f];
            #pragma unroll
            for (int o = 16; o; o >>= 1) acc += __shfl_xor_sync(0xffffffffu, acc, o);
            s3[j] = acc + lin2_b[j];
        }
        if (t == 0) {
            float mx = fmaxf(s3[0], fmaxf(s3[1], s3[2]));
            float e0 = expf(s3[0] - mx), e1 = expf(s3[1] - mx), e2 = expf(s3[2] - mx);
            float inv = 1.f / (e0 + e1 + e2);
            out[b * 3 + 0] = e0 * inv;
            out[b * 3 + 1] = e1 * inv;
            out[b * 3 + 2] = e2 * inv;
        }
    }
}

// ---------------- launch ----------------
extern "C" void kernel_launch(void* const* d_in, const int* in_sizes, int n_in,
                              void* d_out, int out_size) {
    const float* x       = (const float*)d_in[0];
    const int*   ei      = (const int*)  d_in[1];
    const float* ea      = (const float*)d_in[2];
    const float* gconv_w = (const float*)d_in[4];
    const float* w_ih    = (const float*)d_in[5];
    const float* w_hh    = (const float*)d_in[6];
    const float* b_ih    = (const float*)d_in[7];
    const float* b_hh    = (const float*)d_in[8];
    const float* conv_w  = (const float*)d_in[9];
    const float* conv_b  = (const float*)d_in[10];
    const float* lin1_w  = (const float*)d_in[11];
    const float* lin1_b  = (const float*)d_in[12];
    const float* lin2_w  = (const float*)d_in[13];
    const float* lin2_b  = (const float*)d_in[14];
    float* out = (float*)d_out;

    float *ph, *pcw;
    __nv_bfloat16 *phb, *paggb, *paggc, *pqtb, *pwhb;
    int *pdeg, *poff, *pcur, *pcsrc;
    cudaGetSymbolAddress((void**)&ph,    g_h);
    cudaGetSymbolAddress((void**)&phb,   g_hb);
    cudaGetSymbolAddress((void**)&paggb, g_aggb);
    cudaGetSymbolAddress((void**)&paggc, g_aggc);
    cudaGetSymbolAddress((void**)&pqtb,  g_qtb);
    cudaGetSymbolAddress((void**)&pwhb,  g_whb);
    cudaGetSymbolAddress((void**)&pdeg,  g_deg);
    cudaGetSymbolAddress((void**)&poff,  g_off);
    cudaGetSymbolAddress((void**)&pcur,  g_cur);
    cudaGetSymbolAddress((void**)&pcsrc, g_csrc);
    cudaGetSymbolAddress((void**)&pcw,   g_cw);

    cudaFuncSetAttribute(gemm_qt,    cudaFuncAttributeMaxDynamicSharedMemorySize, GEMM_SMEM);
    cudaFuncSetAttribute(gru_fused,  cudaFuncAttributeMaxDynamicSharedMemorySize, FUSED_SMEM);
    cudaFuncSetAttribute(gru1_fused, cudaFuncAttributeMaxDynamicSharedMemorySize, GRU1_SMEM);

    // Qt[l] = bf16(W_ih @ Wg_l^T)  — one launch, both layers, bf16 epilogue
    gemm_qt<<<dim3(3, 1, 2), 256, GEMM_SMEM>>>(w_ih, gconv_w, pqtb);

    pad_kernel<<<(N_NODES * 32 + 255) / 256, 256>>>(x, ph, phb);
    // CSR build (fill also converts w_hh -> bf16)
    zero_kernel<<<(N_NODES / 4 + 255) / 256, 256>>>((float4*)pdeg, N_NODES / 4);
    count_kernel<<<N_EDGES / 256, 256>>>(ei, pdeg);
    scan_kernel<<<1, 1024>>>(pdeg, poff, pcur);
    fill_kernel<<<N_EDGES / 256, 256>>>(ei, ea, pcur, pcsrc, pcw, w_hh, pwhb);

    // ---- layer 1: rank-5 input -> compact agg [N][16]; exact K=16 GEMMs ----
    agg1c_kernel<<<N_NODES * 32 / 256, 256>>>(poff, pcsrc, pcw,
                                              (const float4*)ph, (uint2*)paggc);
    gru1_fused<<<N_NODES / 64, 512, GRU1_SMEM>>>(paggc, ph, phb, pqtb, pwhb, b_ih, b_hh);

    // ---- layer 2: full bf16 gather; 2+2 K=64 chunks ----
    aggb_kernel<<<N_NODES * 16 / 256, 256>>>(poff, pcsrc, pcw,
                                             (const uint4*)phb, (uint4*)paggb);
    gru_fused<<<N_NODES / 64, 512, FUSED_SMEM>>>(paggb, ph, phb, pqtb + 49152, pwhb,
                                                 b_ih, b_hh);

    post_kernel<<<BSZ, 256>>>(ph, conv_w, conv_b, lin1_w, lin1_b, lin2_w, lin2_b, out);
}